// round 1
// baseline (speedup 1.0000x reference)
#include <cuda_runtime.h>

// ---------------- problem constants ----------------
#define BATCH 32
#define SEQ   576
#define EMBD  768
#define NH    12
#define HD    64
#define NT    (BATCH * SEQ)        // 18432 tokens
#define OUT_ELEMS ((size_t)NT * EMBD)              // 14,155,776
#define ATTN_ELEMS ((size_t)BATCH * NH * SEQ * SEQ) // 127,401,984
#define ATT_SCALE 0.125f           // 64^-0.5

// ---------------- scratch (allocation-free rule: __device__ globals) ----------------
__device__ float g_q[NT * EMBD];    // [B,H,S,D]
__device__ float g_k[NT * EMBD];    // [B,H,S,D]
__device__ float g_v[NT * EMBD];    // [B,H,S,D]
__device__ float g_ctx[NT * EMBD];  // [N, EMB]

// =====================================================================
// GEMM: out[n, o] = sum_k X[n,k] * W[o,k] + bias[o]
// Tiles: BM=128, BN=64, BK=16, 256 threads, 8x4 per-thread register tile.
// QKV kernel: grid.z in {0,1,2} selects (W,b) and writes g_q/g_k/g_v in
// [B,H,S,D] layout. O kernel: reads g_ctx, writes plain [n,o] to outp.
// =====================================================================
__global__ __launch_bounds__(256) void qkv_gemm_kernel(
    const float* __restrict__ X,
    const float* __restrict__ qw, const float* __restrict__ qb,
    const float* __restrict__ kw, const float* __restrict__ kb,
    const float* __restrict__ vw, const float* __restrict__ vb)
{
    __shared__ float As[128][17];
    __shared__ float Bs[64][17];

    const int mode = blockIdx.z;
    const float* W    = (mode == 0) ? qw : (mode == 1) ? kw : vw;
    const float* bias = (mode == 0) ? qb : (mode == 1) ? kb : vb;
    float* dst        = (mode == 0) ? g_q : (mode == 1) ? g_k : g_v;

    const int t  = threadIdx.x;
    const int tx = t & 15;        // 16 col-groups of 4
    const int ty = t >> 4;        // 16 row-groups of 8
    const int row0 = blockIdx.y * 128;
    const int col0 = blockIdx.x * 64;

    float acc[8][4];
#pragma unroll
    for (int i = 0; i < 8; i++)
#pragma unroll
        for (int j = 0; j < 4; j++) acc[i][j] = 0.f;

    const int br  = t >> 2;           // 0..63 (B-tile row)
    const int bc4 = (t & 3) << 2;     // 0,4,8,12

    for (int k0 = 0; k0 < EMBD; k0 += 16) {
        // load A tile: 128x16 = 512 float4, 2 per thread
#pragma unroll
        for (int i = 0; i < 2; i++) {
            int lin = t + i * 256;
            int r = lin >> 2;
            int c = (lin & 3) << 2;
            float4 v = *(const float4*)(X + (size_t)(row0 + r) * EMBD + k0 + c);
            As[r][c + 0] = v.x; As[r][c + 1] = v.y;
            As[r][c + 2] = v.z; As[r][c + 3] = v.w;
        }
        // load B tile: 64x16 = 256 float4, 1 per thread
        {
            float4 v = *(const float4*)(W + (size_t)(col0 + br) * EMBD + k0 + bc4);
            Bs[br][bc4 + 0] = v.x; Bs[br][bc4 + 1] = v.y;
            Bs[br][bc4 + 2] = v.z; Bs[br][bc4 + 3] = v.w;
        }
        __syncthreads();
#pragma unroll
        for (int k = 0; k < 16; k++) {
            float a[8], b[4];
#pragma unroll
            for (int i = 0; i < 8; i++) a[i] = As[ty * 8 + i][k];
#pragma unroll
            for (int j = 0; j < 4; j++) b[j] = Bs[tx * 4 + j][k];
#pragma unroll
            for (int i = 0; i < 8; i++)
#pragma unroll
                for (int j = 0; j < 4; j++) acc[i][j] += a[i] * b[j];
        }
        __syncthreads();
    }

#pragma unroll
    for (int i = 0; i < 8; i++) {
        int r = row0 + ty * 8 + i;
        int bb = r / SEQ, s = r - bb * SEQ;
#pragma unroll
        for (int j = 0; j < 4; j++) {
            int c = col0 + tx * 4 + j;
            float v = acc[i][j] + bias[c];
            int h = c >> 6, d = c & 63;
            dst[(((size_t)bb * NH + h) * SEQ + s) * HD + d] = v;
        }
    }
}

__global__ __launch_bounds__(256) void oproj_gemm_kernel(
    const float* __restrict__ W, const float* __restrict__ bias,
    float* __restrict__ outp)
{
    __shared__ float As[128][17];
    __shared__ float Bs[64][17];

    const float* X = g_ctx;
    const int t  = threadIdx.x;
    const int tx = t & 15;
    const int ty = t >> 4;
    const int row0 = blockIdx.y * 128;
    const int col0 = blockIdx.x * 64;

    float acc[8][4];
#pragma unroll
    for (int i = 0; i < 8; i++)
#pragma unroll
        for (int j = 0; j < 4; j++) acc[i][j] = 0.f;

    const int br  = t >> 2;
    const int bc4 = (t & 3) << 2;

    for (int k0 = 0; k0 < EMBD; k0 += 16) {
#pragma unroll
        for (int i = 0; i < 2; i++) {
            int lin = t + i * 256;
            int r = lin >> 2;
            int c = (lin & 3) << 2;
            float4 v = *(const float4*)(X + (size_t)(row0 + r) * EMBD + k0 + c);
            As[r][c + 0] = v.x; As[r][c + 1] = v.y;
            As[r][c + 2] = v.z; As[r][c + 3] = v.w;
        }
        {
            float4 v = *(const float4*)(W + (size_t)(col0 + br) * EMBD + k0 + bc4);
            Bs[br][bc4 + 0] = v.x; Bs[br][bc4 + 1] = v.y;
            Bs[br][bc4 + 2] = v.z; Bs[br][bc4 + 3] = v.w;
        }
        __syncthreads();
#pragma unroll
        for (int k = 0; k < 16; k++) {
            float a[8], b[4];
#pragma unroll
            for (int i = 0; i < 8; i++) a[i] = As[ty * 8 + i][k];
#pragma unroll
            for (int j = 0; j < 4; j++) b[j] = Bs[tx * 4 + j][k];
#pragma unroll
            for (int i = 0; i < 8; i++)
#pragma unroll
                for (int j = 0; j < 4; j++) acc[i][j] += a[i] * b[j];
        }
        __syncthreads();
    }

#pragma unroll
    for (int i = 0; i < 8; i++) {
        int r = row0 + ty * 8 + i;
#pragma unroll
        for (int j = 0; j < 4; j++) {
            int c = col0 + tx * 4 + j;
            outp[(size_t)r * EMBD + c] = acc[i][j] + bias[c];
        }
    }
}

// =====================================================================
// Attention: one CTA per (bh, 64-row q tile).
// scores slab [64][577] lives fully in smem (no online softmax needed:
// the attn matrix must be materialized to d_out anyway).
// =====================================================================
__global__ __launch_bounds__(256) void attn_kernel(float* __restrict__ attn_out)
{
    extern __shared__ float sm[];
    float* sc = sm;                    // [64][577]  (577 pad: stride%32 != 0)
    float* Qs = sm + 64 * 577;         // [64][65]
    float* Ts = Qs + 64 * 65;          // [64][65]   K tile then V tile

    const int t  = threadIdx.x;
    const int tx = t & 15;             // key/dim col group (4 wide)
    const int ty = t >> 4;             // q row group (4 wide)
    const int qt = blockIdx.x;         // 0..8
    const int bh = blockIdx.y;         // 0..383
    const size_t base = (size_t)bh * SEQ * HD;

    // ---- load Q tile [64][64] ----
#pragma unroll
    for (int i = 0; i < 4; i++) {
        int lin = t + i * 256;         // 0..1023
        int r = lin >> 4;
        int c = (lin & 15) << 2;
        float4 v = *(const float4*)(g_q + base + (size_t)(qt * 64 + r) * HD + c);
        Qs[r * 65 + c + 0] = v.x; Qs[r * 65 + c + 1] = v.y;
        Qs[r * 65 + c + 2] = v.z; Qs[r * 65 + c + 3] = v.w;
    }

    // ---- scores: loop over 9 key tiles ----
    for (int kt = 0; kt < 9; kt++) {
        __syncthreads();
#pragma unroll
        for (int i = 0; i < 4; i++) {
            int lin = t + i * 256;
            int r = lin >> 4;
            int c = (lin & 15) << 2;
            float4 v = *(const float4*)(g_k + base + (size_t)(kt * 64 + r) * HD + c);
            Ts[r * 65 + c + 0] = v.x; Ts[r * 65 + c + 1] = v.y;
            Ts[r * 65 + c + 2] = v.z; Ts[r * 65 + c + 3] = v.w;
        }
        __syncthreads();

        float acc[4][4];
#pragma unroll
        for (int i = 0; i < 4; i++)
#pragma unroll
            for (int j = 0; j < 4; j++) acc[i][j] = 0.f;

#pragma unroll 16
        for (int d = 0; d < 64; d++) {
            float a[4], b[4];
#pragma unroll
            for (int i = 0; i < 4; i++) a[i] = Qs[(ty * 4 + i) * 65 + d];
#pragma unroll
            for (int j = 0; j < 4; j++) b[j] = Ts[(tx * 4 + j) * 65 + d];
#pragma unroll
            for (int i = 0; i < 4; i++)
#pragma unroll
                for (int j = 0; j < 4; j++) acc[i][j] += a[i] * b[j];
        }
#pragma unroll
        for (int i = 0; i < 4; i++)
#pragma unroll
            for (int j = 0; j < 4; j++)
                sc[(ty * 4 + i) * 577 + kt * 64 + tx * 4 + j] = acc[i][j] * ATT_SCALE;
    }
    __syncthreads();

    // ---- softmax: warp w owns rows w*8..w*8+7; write attn to d_out ----
    {
        const int w = t >> 5, lane = t & 31;
        for (int rr = 0; rr < 8; rr++) {
            int r = w * 8 + rr;
            float* row = sc + r * 577;
            float m = -1e30f;
            for (int c = lane; c < SEQ; c += 32) m = fmaxf(m, row[c]);
#pragma unroll
            for (int off = 16; off > 0; off >>= 1)
                m = fmaxf(m, __shfl_xor_sync(0xffffffffu, m, off));
            float s = 0.f;
            for (int c = lane; c < SEQ; c += 32) {
                float e = __expf(row[c] - m);
                row[c] = e;
                s += e;
            }
#pragma unroll
            for (int off = 16; off > 0; off >>= 1)
                s += __shfl_xor_sync(0xffffffffu, s, off);
            float inv = 1.f / s;
            size_t arow = ((size_t)bh * SEQ + (size_t)(qt * 64 + r)) * SEQ;
            for (int c = lane; c < SEQ; c += 32) {
                float p = row[c] * inv;
                row[c] = p;
                attn_out[arow + c] = p;
            }
        }
    }
    __syncthreads();

    // ---- P @ V ----
    float acc[4][4];
#pragma unroll
    for (int i = 0; i < 4; i++)
#pragma unroll
        for (int j = 0; j < 4; j++) acc[i][j] = 0.f;

    for (int kt = 0; kt < 9; kt++) {
#pragma unroll
        for (int i = 0; i < 4; i++) {
            int lin = t + i * 256;
            int r = lin >> 4;
            int c = (lin & 15) << 2;
            float4 v = *(const float4*)(g_v + base + (size_t)(kt * 64 + r) * HD + c);
            Ts[r * 65 + c + 0] = v.x; Ts[r * 65 + c + 1] = v.y;
            Ts[r * 65 + c + 2] = v.z; Ts[r * 65 + c + 3] = v.w;
        }
        __syncthreads();
#pragma unroll 16
        for (int d = 0; d < 64; d++) {       // d = key index within tile
            float p[4], vv[4];
#pragma unroll
            for (int i = 0; i < 4; i++) p[i] = sc[(ty * 4 + i) * 577 + kt * 64 + d];
#pragma unroll
            for (int j = 0; j < 4; j++) vv[j] = Ts[d * 65 + tx * 4 + j];
#pragma unroll
            for (int i = 0; i < 4; i++)
#pragma unroll
                for (int j = 0; j < 4; j++) acc[i][j] += p[i] * vv[j];
        }
        __syncthreads();
    }

    // ---- write ctx in [N, EMB] layout ----
    const int bb = bh / NH, h = bh % NH;
#pragma unroll
    for (int i = 0; i < 4; i++) {
        int qi = ty * 4 + i;
        size_t n = (size_t)bb * SEQ + (size_t)(qt * 64 + qi);
#pragma unroll
        for (int j = 0; j < 4; j++) {
            int d = tx * 4 + j;
            g_ctx[n * EMBD + h * 64 + d] = acc[i][j];
        }
    }
}

// =====================================================================
// launch
// =====================================================================
extern "C" void kernel_launch(void* const* d_in, const int* in_sizes, int n_in,
                              void* d_out, int out_size)
{
    const float* hs = (const float*)d_in[0];
    const float* qw = (const float*)d_in[1];
    const float* qb = (const float*)d_in[2];
    const float* kw = (const float*)d_in[3];
    const float* kb = (const float*)d_in[4];
    const float* vw = (const float*)d_in[5];
    const float* vb = (const float*)d_in[6];
    const float* ow = (const float*)d_in[7];
    const float* ob = (const float*)d_in[8];

    float* out  = (float*)d_out;             // [NT, EMB]
    float* attn = out + OUT_ELEMS;           // [B, H, S, S]

    // QKV projections (fused into one launch via grid.z)
    dim3 gQKV(EMBD / 64, NT / 128, 3);
    qkv_gemm_kernel<<<gQKV, 256>>>(hs, qw, qb, kw, kb, vw, vb);

    // Attention
    size_t shmem = (size_t)(64 * 577 + 2 * 64 * 65) * sizeof(float); // 180,992 B
    cudaFuncSetAttribute(attn_kernel, cudaFuncAttributeMaxDynamicSharedMemorySize,
                         (int)shmem);
    attn_kernel<<<dim3(9, BATCH * NH), 256, shmem>>>(attn);

    // Output projection
    dim3 gO(EMBD / 64, NT / 128, 1);
    oproj_gemm_kernel<<<gO, 256>>>(ow, ob, out);
}

// round 3
// speedup vs baseline: 1.4315x; 1.4315x over previous
#include <cuda_runtime.h>
#include <cuda_bf16.h>

// ---------------- problem constants ----------------
#define BATCH 32
#define SEQ   576
#define EMBD  768
#define NH    12
#define HD    64
#define NT    (BATCH * SEQ)        // 18432 tokens
#define OUT_ELEMS ((size_t)NT * EMBD)
#define ATT_SCALE 0.125f
#define KCHUNKS 24                 // K chunks of 32 (768 total)

typedef unsigned int u32;

// ---------------- scratch (__device__ globals; no allocation allowed) ----------------
__device__ float g_q[NT * EMBD];    // [B,H,S,D]
__device__ float g_k[NT * EMBD];
__device__ float g_v[NT * EMBD];
__device__ float g_ctx[NT * EMBD];  // [N, EMB]

// split-bf16 operands as uint4 (8 bf16 each)
__device__ uint4 g_xhi4[NT * EMBD / 8];
__device__ uint4 g_xlo4[NT * EMBD / 8];
__device__ uint4 g_whi4[4 * EMBD * EMBD / 8];   // q,k,v,o packed
__device__ uint4 g_wlo4[4 * EMBD * EMBD / 8];
__device__ uint4 g_chi4[NT * EMBD / 8];
__device__ uint4 g_clo4[NT * EMBD / 8];

// ---------------- helpers ----------------
__device__ __forceinline__ u32 smem_u32(const void* p) {
    u32 a;
    asm("{ .reg .u64 t; cvta.to.shared.u64 t, %1; cvt.u32.u64 %0, t; }"
        : "=r"(a) : "l"(p));
    return a;
}

#define CP_ASYNC16(dst, src) \
    asm volatile("cp.async.cg.shared.global [%0], [%1], 16;" \
                 :: "r"(dst), "l"(src) : "memory")
#define CP_COMMIT() asm volatile("cp.async.commit_group;" ::: "memory")
#define CP_WAIT1()  asm volatile("cp.async.wait_group 1;" ::: "memory")
#define CP_WAIT0()  asm volatile("cp.async.wait_group 0;" ::: "memory")

#define LDSM4(r0, r1, r2, r3, addr) \
    asm volatile("ldmatrix.sync.aligned.m8n8.x4.shared.b16 {%0,%1,%2,%3}, [%4];" \
                 : "=r"(r0), "=r"(r1), "=r"(r2), "=r"(r3) : "r"(addr))

#define MMA16816(d, a, b) \
    asm volatile("mma.sync.aligned.m16n8k16.row.col.f32.bf16.bf16.f32 " \
                 "{%0,%1,%2,%3}, {%4,%5,%6,%7}, {%8,%9}, {%0,%1,%2,%3};" \
                 : "+f"((d)[0]), "+f"((d)[1]), "+f"((d)[2]), "+f"((d)[3]) \
                 : "r"((a)[0]), "r"((a)[1]), "r"((a)[2]), "r"((a)[3]), \
                   "r"((b)[0]), "r"((b)[1]))

// =====================================================================
// hi/lo split conversion kernels
// =====================================================================
__device__ __forceinline__ void conv8(const float4* src2, uint4* hi, uint4* lo) {
    float4 a = src2[0], b = src2[1];
    float f[8] = {a.x, a.y, a.z, a.w, b.x, b.y, b.z, b.w};
    union { uint4 v; __nv_bfloat16 h[8]; } H, L;
#pragma unroll
    for (int j = 0; j < 8; j++) {
        __nv_bfloat16 hh = __float2bfloat16(f[j]);
        H.h[j] = hh;
        L.h[j] = __float2bfloat16(f[j] - __bfloat162float(hh));
    }
    *hi = H.v; *lo = L.v;
}

__global__ __launch_bounds__(256) void conv_x_kernel(const float* __restrict__ src) {
    int i = blockIdx.x * blockDim.x + threadIdx.x;
    if (i >= NT * EMBD / 8) return;
    conv8((const float4*)src + 2 * (size_t)i, &g_xhi4[i], &g_xlo4[i]);
}

__global__ __launch_bounds__(256) void conv_ctx_kernel() {
    int i = blockIdx.x * blockDim.x + threadIdx.x;
    if (i >= NT * EMBD / 8) return;
    conv8((const float4*)g_ctx + 2 * (size_t)i, &g_chi4[i], &g_clo4[i]);
}

__global__ __launch_bounds__(256) void conv_w_kernel(
    const float* __restrict__ qw, const float* __restrict__ kw,
    const float* __restrict__ vw, const float* __restrict__ ow) {
    int z = blockIdx.y;
    const float* src = z == 0 ? qw : z == 1 ? kw : z == 2 ? vw : ow;
    int i = blockIdx.x * blockDim.x + threadIdx.x;
    if (i >= EMBD * EMBD / 8) return;
    int di = z * (EMBD * EMBD / 8) + i;
    conv8((const float4*)src + 2 * (size_t)i, &g_whi4[di], &g_wlo4[di]);
}

// =====================================================================
// HMMA split-bf16 GEMM: C[128x128] = X[128,768] * W[128,768]^T + bias
// modes 0/1/2 -> Q/K/V scatter to [B,H,S,D]; mode 3 -> O proj into outp.
//
// smem per stage: A rows 128 x 128B (hi 64B | lo 64B), W same. 2 stages.
// Row layout: 16B chunk c (0..7) stored at  r*128 + ((c ^ (r&7))*16).
// =====================================================================
#define STAGE_BYTES 32768
#define MM_SMEM (2 * STAGE_BYTES + 512)

__global__ __launch_bounds__(256, 1) void mm_hmma_kernel(
    const float* __restrict__ qb, const float* __restrict__ kb,
    const float* __restrict__ vb, const float* __restrict__ ob,
    float* __restrict__ outp, int mode_base)
{
    extern __shared__ char smraw[];
    const u32 smbase = smem_u32(smraw);
    float* bias_s = (float*)(smraw + 2 * STAGE_BYTES);

    const int t = threadIdx.x, lane = t & 31, wid = t >> 5;
    const int warpM = wid & 3;          // 4 warps along M (32 rows each)
    const int warpN = wid >> 2;         // 2 warps along N (64 cols each)
    const int mode = mode_base + blockIdx.z;
    const int o0 = blockIdx.x * 128;
    const int n0 = blockIdx.y * 128;

    const float* bias = mode == 0 ? qb : mode == 1 ? kb : mode == 2 ? vb : ob;
    const uint4* AhiG = (mode < 3) ? g_xhi4 : g_chi4;
    const uint4* AloG = (mode < 3) ? g_xlo4 : g_clo4;
    const size_t woff = (size_t)(mode < 3 ? mode : 3) * (EMBD * EMBD / 8);

    if (t < 128) bias_s[t] = bias[o0 + t];

    // ---- gmem->smem loader state (cp.async) ----
    const int lr   = t >> 1;            // row 0..127
    const int half = t & 1;             // 0 = hi, 1 = lo
    const uint4* srcA = (half ? AloG : AhiG) + (size_t)(n0 + lr) * 96;
    const uint4* srcW = (half ? g_wlo4 : g_whi4) + woff + (size_t)(o0 + lr) * 96;
    const u32 arow_sw[4] = {
        (u32)(lr * 128 + (((half * 4 + 0) ^ (lr & 7)) << 4)),
        (u32)(lr * 128 + (((half * 4 + 1) ^ (lr & 7)) << 4)),
        (u32)(lr * 128 + (((half * 4 + 2) ^ (lr & 7)) << 4)),
        (u32)(lr * 128 + (((half * 4 + 3) ^ (lr & 7)) << 4))
    };

    float acc[2][8][4];
#pragma unroll
    for (int i = 0; i < 2; i++)
#pragma unroll
        for (int j = 0; j < 8; j++)
#pragma unroll
            for (int c = 0; c < 4; c++) acc[i][j][c] = 0.f;

    // prefetch chunk 0 into stage 0
    {
        const u32 Ab = smbase, Wb = smbase + 16384;
#pragma unroll
        for (int g = 0; g < 4; g++) {
            CP_ASYNC16(Ab + arow_sw[g], srcA + g);
            CP_ASYNC16(Wb + arow_sw[g], srcW + g);
        }
        CP_COMMIT();
    }

#pragma unroll 1
    for (int kc = 0; kc < KCHUNKS; kc++) {
        if (kc + 1 < KCHUNKS) {
            const u32 st = smbase + ((kc + 1) & 1) * STAGE_BYTES;
            const u32 Ab = st, Wb = st + 16384;
            const int ko = (kc + 1) * 4;
#pragma unroll
            for (int g = 0; g < 4; g++) {
                CP_ASYNC16(Ab + arow_sw[g], srcA + ko + g);
                CP_ASYNC16(Wb + arow_sw[g], srcW + ko + g);
            }
            CP_COMMIT();
            CP_WAIT1();
        } else {
            CP_WAIT0();
        }
        __syncthreads();

        const u32 st = smbase + (kc & 1) * STAGE_BYTES;
        const u32 Ab = st, Wb = st + 16384;

#pragma unroll
        for (int ks = 0; ks < 2; ks++) {
            u32 ah[2][4], al[2][4];
#pragma unroll
            for (int mt = 0; mt < 2; mt++) {
                int row = warpM * 32 + mt * 16 + (lane & 15);
                int c = ks * 2 + ((lane >> 4) & 1);
                u32 base = Ab + row * 128;
                u32 ahi = base + (((c)     ^ (row & 7)) << 4);
                u32 alo = base + (((c + 4) ^ (row & 7)) << 4);
                LDSM4(ah[mt][0], ah[mt][1], ah[mt][2], ah[mt][3], ahi);
                LDSM4(al[mt][0], al[mt][1], al[mt][2], al[mt][3], alo);
            }
            u32 bh[8][2], bl[8][2];
#pragma unroll
            for (int bt = 0; bt < 4; bt++) {
                int row = warpN * 64 + bt * 16 + (lane & 7) + ((lane >> 4) & 1) * 8;
                int c = ks * 2 + ((lane >> 3) & 1);
                u32 base = Wb + row * 128;
                u32 bhi = base + (((c)     ^ (row & 7)) << 4);
                u32 blo = base + (((c + 4) ^ (row & 7)) << 4);
                u32 r0, r1, r2, r3;
                LDSM4(r0, r1, r2, r3, bhi);
                bh[bt * 2][0] = r0; bh[bt * 2][1] = r1;
                bh[bt * 2 + 1][0] = r2; bh[bt * 2 + 1][1] = r3;
                LDSM4(r0, r1, r2, r3, blo);
                bl[bt * 2][0] = r0; bl[bt * 2][1] = r1;
                bl[bt * 2 + 1][0] = r2; bl[bt * 2 + 1][1] = r3;
            }
#pragma unroll
            for (int mt = 0; mt < 2; mt++)
#pragma unroll
                for (int nt = 0; nt < 8; nt++) {
                    MMA16816(acc[mt][nt], ah[mt], bh[nt]);
                    MMA16816(acc[mt][nt], ah[mt], bl[nt]);
                    MMA16816(acc[mt][nt], al[mt], bh[nt]);
                }
        }
        __syncthreads();
    }

    // ---- epilogue: bias + scatter ----
    float* dstq = mode == 0 ? g_q : mode == 1 ? g_k : g_v;
    const int h0 = blockIdx.x * 2;
#pragma unroll
    for (int mt = 0; mt < 2; mt++)
#pragma unroll
        for (int nt = 0; nt < 8; nt++)
#pragma unroll
            for (int cc = 0; cc < 2; cc++) {
                int rl = warpM * 32 + mt * 16 + (lane >> 2) + cc * 8;
                int cl = warpN * 64 + nt * 8 + (lane & 3) * 2;
                float v0 = acc[mt][nt][cc * 2 + 0] + bias_s[cl];
                float v1 = acc[mt][nt][cc * 2 + 1] + bias_s[cl + 1];
                int n = n0 + rl;
                if (mode < 3) {
                    int bb = n / SEQ, ss = n - bb * SEQ;
                    int h = h0 + (cl >> 6), d = cl & 63;
                    float2* p = (float2*)(dstq +
                        ((((size_t)bb * NH + h) * SEQ + ss) * HD + d));
                    *p = make_float2(v0, v1);
                } else {
                    float2* p = (float2*)(outp + (size_t)n * EMBD + o0 + cl);
                    *p = make_float2(v0, v1);
                }
            }
}

// =====================================================================
// Attention (unchanged, passing): one CTA per (bh, 64-row q tile)
// =====================================================================
__global__ __launch_bounds__(256) void attn_kernel(float* __restrict__ attn_out)
{
    extern __shared__ float sm[];
    float* sc = sm;                    // [64][577]
    float* Qs = sm + 64 * 577;         // [64][65]
    float* Ts = Qs + 64 * 65;          // [64][65]

    const int t  = threadIdx.x;
    const int tx = t & 15;
    const int ty = t >> 4;
    const int qt = blockIdx.x;
    const int bh = blockIdx.y;
    const size_t base = (size_t)bh * SEQ * HD;

#pragma unroll
    for (int i = 0; i < 4; i++) {
        int lin = t + i * 256;
        int r = lin >> 4;
        int c = (lin & 15) << 2;
        float4 v = *(const float4*)(g_q + base + (size_t)(qt * 64 + r) * HD + c);
        Qs[r * 65 + c + 0] = v.x; Qs[r * 65 + c + 1] = v.y;
        Qs[r * 65 + c + 2] = v.z; Qs[r * 65 + c + 3] = v.w;
    }

    for (int kt = 0; kt < 9; kt++) {
        __syncthreads();
#pragma unroll
        for (int i = 0; i < 4; i++) {
            int lin = t + i * 256;
            int r = lin >> 4;
            int c = (lin & 15) << 2;
            float4 v = *(const float4*)(g_k + base + (size_t)(kt * 64 + r) * HD + c);
            Ts[r * 65 + c + 0] = v.x; Ts[r * 65 + c + 1] = v.y;
            Ts[r * 65 + c + 2] = v.z; Ts[r * 65 + c + 3] = v.w;
        }
        __syncthreads();

        float acc[4][4];
#pragma unroll
        for (int i = 0; i < 4; i++)
#pragma unroll
            for (int j = 0; j < 4; j++) acc[i][j] = 0.f;

#pragma unroll 16
        for (int d = 0; d < 64; d++) {
            float a[4], b[4];
#pragma unroll
            for (int i = 0; i < 4; i++) a[i] = Qs[(ty * 4 + i) * 65 + d];
#pragma unroll
            for (int j = 0; j < 4; j++) b[j] = Ts[(tx * 4 + j) * 65 + d];
#pragma unroll
            for (int i = 0; i < 4; i++)
#pragma unroll
                for (int j = 0; j < 4; j++) acc[i][j] += a[i] * b[j];
        }
#pragma unroll
        for (int i = 0; i < 4; i++)
#pragma unroll
            for (int j = 0; j < 4; j++)
                sc[(ty * 4 + i) * 577 + kt * 64 + tx * 4 + j] = acc[i][j] * ATT_SCALE;
    }
    __syncthreads();

    {
        const int w = t >> 5, lane = t & 31;
        for (int rr = 0; rr < 8; rr++) {
            int r = w * 8 + rr;
            float* row = sc + r * 577;
            float m = -1e30f;
            for (int c = lane; c < SEQ; c += 32) m = fmaxf(m, row[c]);
#pragma unroll
            for (int off = 16; off > 0; off >>= 1)
                m = fmaxf(m, __shfl_xor_sync(0xffffffffu, m, off));
            float s = 0.f;
            for (int c = lane; c < SEQ; c += 32) {
                float e = __expf(row[c] - m);
                row[c] = e;
                s += e;
            }
#pragma unroll
            for (int off = 16; off > 0; off >>= 1)
                s += __shfl_xor_sync(0xffffffffu, s, off);
            float inv = 1.f / s;
            size_t arow = ((size_t)bh * SEQ + (size_t)(qt * 64 + r)) * SEQ;
            for (int c = lane; c < SEQ; c += 32) {
                float p = row[c] * inv;
                row[c] = p;
                attn_out[arow + c] = p;
            }
        }
    }
    __syncthreads();

    float acc[4][4];
#pragma unroll
    for (int i = 0; i < 4; i++)
#pragma unroll
        for (int j = 0; j < 4; j++) acc[i][j] = 0.f;

    for (int kt = 0; kt < 9; kt++) {
#pragma unroll
        for (int i = 0; i < 4; i++) {
            int lin = t + i * 256;
            int r = lin >> 4;
            int c = (lin & 15) << 2;
            float4 v = *(const float4*)(g_v + base + (size_t)(kt * 64 + r) * HD + c);
            Ts[r * 65 + c + 0] = v.x; Ts[r * 65 + c + 1] = v.y;
            Ts[r * 65 + c + 2] = v.z; Ts[r * 65 + c + 3] = v.w;
        }
        __syncthreads();
#pragma unroll 16
        for (int d = 0; d < 64; d++) {
            float p[4], vv[4];
#pragma unroll
            for (int i = 0; i < 4; i++) p[i] = sc[(ty * 4 + i) * 577 + kt * 64 + d];
#pragma unroll
            for (int j = 0; j < 4; j++) vv[j] = Ts[d * 65 + tx * 4 + j];
#pragma unroll
            for (int i = 0; i < 4; i++)
#pragma unroll
                for (int j = 0; j < 4; j++) acc[i][j] += p[i] * vv[j];
        }
        __syncthreads();
    }

    const int bb = bh / NH, h = bh % NH;
#pragma unroll
    for (int i = 0; i < 4; i++) {
        int qi = ty * 4 + i;
        size_t n = (size_t)bb * SEQ + (size_t)(qt * 64 + qi);
#pragma unroll
        for (int j = 0; j < 4; j++) {
            int d = tx * 4 + j;
            g_ctx[n * EMBD + h * 64 + d] = acc[i][j];
        }
    }
}

// =====================================================================
// launch
// =====================================================================
extern "C" void kernel_launch(void* const* d_in, const int* in_sizes, int n_in,
                              void* d_out, int out_size)
{
    const float* hs = (const float*)d_in[0];
    const float* qw = (const float*)d_in[1];
    const float* qb = (const float*)d_in[2];
    const float* kw = (const float*)d_in[3];
    const float* kb = (const float*)d_in[4];
    const float* vw = (const float*)d_in[5];
    const float* vb = (const float*)d_in[6];
    const float* ow = (const float*)d_in[7];
    const float* ob = (const float*)d_in[8];

    float* out  = (float*)d_out;             // [NT, EMB]
    float* attn = out + OUT_ELEMS;           // [B, H, S, S]

    cudaFuncSetAttribute(mm_hmma_kernel, cudaFuncAttributeMaxDynamicSharedMemorySize,
                         MM_SMEM);

    // split-bf16 prep
    conv_x_kernel<<<(NT * EMBD / 8 + 255) / 256, 256>>>(hs);
    conv_w_kernel<<<dim3((EMBD * EMBD / 8 + 255) / 256, 4), 256>>>(qw, kw, vw, ow);

    // QKV projections on tensor cores (HMMA)
    mm_hmma_kernel<<<dim3(EMBD / 128, NT / 128, 3), 256, MM_SMEM>>>(
        qb, kb, vb, ob, out, 0);

    // Attention (fp32 SIMT, unchanged)
    size_t shmem = (size_t)(64 * 577 + 2 * 64 * 65) * sizeof(float);
    cudaFuncSetAttribute(attn_kernel, cudaFuncAttributeMaxDynamicSharedMemorySize,
                         (int)shmem);
    attn_kernel<<<dim3(9, BATCH * NH), 256, shmem>>>(attn);

    // ctx split + O projection
    conv_ctx_kernel<<<(NT * EMBD / 8 + 255) / 256, 256>>>();
    mm_hmma_kernel<<<dim3(EMBD / 128, NT / 128, 1), 256, MM_SMEM>>>(
        qb, kb, vb, ob, out, 3);
}

// round 4
// speedup vs baseline: 1.8377x; 1.2837x over previous
#include <cuda_runtime.h>
#include <cuda_bf16.h>

// ---------------- problem constants ----------------
#define BATCH 32
#define SEQ   576
#define EMBD  768
#define NH    12
#define HD    64
#define NT    (BATCH * SEQ)
#define OUT_ELEMS ((size_t)NT * EMBD)
#define ATT_SCALE 0.125f
#define KCHUNKS 24

typedef unsigned int u32;
typedef unsigned short u16;

// ---------------- device scratch ----------------
// split-bf16 operands as uint4 (8 bf16 each)
__device__ uint4 g_xhi4[NT * EMBD / 8];
__device__ uint4 g_xlo4[NT * EMBD / 8];
__device__ uint4 g_whi4[4 * EMBD * EMBD / 8];
__device__ uint4 g_wlo4[4 * EMBD * EMBD / 8];
__device__ uint4 g_chi4[NT * EMBD / 8];          // ctx hi/lo ([N, EMB])
__device__ uint4 g_clo4[NT * EMBD / 8];
// Q/K/V in [B,H,S,D] bf16 hi/lo
__device__ uint4 g_qh4[NT * EMBD / 8];
__device__ uint4 g_ql4[NT * EMBD / 8];
__device__ uint4 g_kh4[NT * EMBD / 8];
__device__ uint4 g_kl4[NT * EMBD / 8];
__device__ uint4 g_vh4[NT * EMBD / 8];
__device__ uint4 g_vl4[NT * EMBD / 8];

// ---------------- helpers ----------------
__device__ __forceinline__ u32 smem_u32(const void* p) {
    u32 a;
    asm("{ .reg .u64 t; cvta.to.shared.u64 t, %1; cvt.u32.u64 %0, t; }"
        : "=r"(a) : "l"(p));
    return a;
}

#define CP_ASYNC16(dst, src) \
    asm volatile("cp.async.cg.shared.global [%0], [%1], 16;" \
                 :: "r"(dst), "l"(src) : "memory")
#define CP_COMMIT() asm volatile("cp.async.commit_group;" ::: "memory")
#define CP_WAIT1()  asm volatile("cp.async.wait_group 1;" ::: "memory")
#define CP_WAIT0()  asm volatile("cp.async.wait_group 0;" ::: "memory")

#define LDSM4(r0, r1, r2, r3, addr) \
    asm volatile("ldmatrix.sync.aligned.m8n8.x4.shared.b16 {%0,%1,%2,%3}, [%4];" \
                 : "=r"(r0), "=r"(r1), "=r"(r2), "=r"(r3) : "r"(addr))
#define LDSM4T(r0, r1, r2, r3, addr) \
    asm volatile("ldmatrix.sync.aligned.m8n8.x4.trans.shared.b16 {%0,%1,%2,%3}, [%4];" \
                 : "=r"(r0), "=r"(r1), "=r"(r2), "=r"(r3) : "r"(addr))

#define MMA16816(d, a, b) \
    asm volatile("mma.sync.aligned.m16n8k16.row.col.f32.bf16.bf16.f32 " \
                 "{%0,%1,%2,%3}, {%4,%5,%6,%7}, {%8,%9}, {%0,%1,%2,%3};" \
                 : "+f"((d)[0]), "+f"((d)[1]), "+f"((d)[2]), "+f"((d)[3]) \
                 : "r"((a)[0]), "r"((a)[1]), "r"((a)[2]), "r"((a)[3]), \
                   "r"((b)[0]), "r"((b)[1]))

#define STS128(addr, a, b, c, d) \
    asm volatile("st.shared.v4.b32 [%0], {%1, %2, %3, %4};" \
                 :: "r"(addr), "r"(a), "r"(b), "r"(c), "r"(d) : "memory")

__device__ __forceinline__ void pack_hilo(float v0, float v1, u32& hp, u32& lp) {
    __nv_bfloat16 h0 = __float2bfloat16(v0);
    __nv_bfloat16 h1 = __float2bfloat16(v1);
    __nv_bfloat16 l0 = __float2bfloat16(v0 - __bfloat162float(h0));
    __nv_bfloat16 l1 = __float2bfloat16(v1 - __bfloat162float(h1));
    hp = (u32)*(u16*)&h0 | ((u32)*(u16*)&h1 << 16);
    lp = (u32)*(u16*)&l0 | ((u32)*(u16*)&l1 << 16);
}

// =====================================================================
// hi/lo split conversion (X, W)
// =====================================================================
__device__ __forceinline__ void conv8(const float4* src2, uint4* hi, uint4* lo) {
    float4 a = src2[0], b = src2[1];
    float f[8] = {a.x, a.y, a.z, a.w, b.x, b.y, b.z, b.w};
    union { uint4 v; __nv_bfloat16 h[8]; } H, L;
#pragma unroll
    for (int j = 0; j < 8; j++) {
        __nv_bfloat16 hh = __float2bfloat16(f[j]);
        H.h[j] = hh;
        L.h[j] = __float2bfloat16(f[j] - __bfloat162float(hh));
    }
    *hi = H.v; *lo = L.v;
}

__global__ __launch_bounds__(256) void conv_x_kernel(const float* __restrict__ src) {
    int i = blockIdx.x * blockDim.x + threadIdx.x;
    if (i >= NT * EMBD / 8) return;
    conv8((const float4*)src + 2 * (size_t)i, &g_xhi4[i], &g_xlo4[i]);
}

__global__ __launch_bounds__(256) void conv_w_kernel(
    const float* __restrict__ qw, const float* __restrict__ kw,
    const float* __restrict__ vw, const float* __restrict__ ow) {
    int z = blockIdx.y;
    const float* src = z == 0 ? qw : z == 1 ? kw : z == 2 ? vw : ow;
    int i = blockIdx.x * blockDim.x + threadIdx.x;
    if (i >= EMBD * EMBD / 8) return;
    int di = z * (EMBD * EMBD / 8) + i;
    conv8((const float4*)src + 2 * (size_t)i, &g_whi4[di], &g_wlo4[di]);
}

// =====================================================================
// HMMA split-bf16 GEMM (same mainloop as R3 passing kernel).
// modes 0/1/2: epilogue scatters bf16 hi/lo q/k/v; mode 3: fp32 out.
// =====================================================================
#define STAGE_BYTES 32768
#define MM_SMEM (2 * STAGE_BYTES + 512)

__global__ __launch_bounds__(256, 1) void mm_hmma_kernel(
    const float* __restrict__ qb, const float* __restrict__ kb,
    const float* __restrict__ vb, const float* __restrict__ ob,
    float* __restrict__ outp, int mode_base)
{
    extern __shared__ char smraw[];
    const u32 smbase = smem_u32(smraw);
    float* bias_s = (float*)(smraw + 2 * STAGE_BYTES);

    const int t = threadIdx.x, lane = t & 31, wid = t >> 5;
    const int warpM = wid & 3;
    const int warpN = wid >> 2;
    const int mode = mode_base + blockIdx.z;
    const int o0 = blockIdx.x * 128;
    const int n0 = blockIdx.y * 128;

    const float* bias = mode == 0 ? qb : mode == 1 ? kb : mode == 2 ? vb : ob;
    const uint4* AhiG = (mode < 3) ? g_xhi4 : g_chi4;
    const uint4* AloG = (mode < 3) ? g_xlo4 : g_clo4;
    const size_t woff = (size_t)(mode < 3 ? mode : 3) * (EMBD * EMBD / 8);

    if (t < 128) bias_s[t] = bias[o0 + t];

    const int lr   = t >> 1;
    const int half = t & 1;
    const uint4* srcA = (half ? AloG : AhiG) + (size_t)(n0 + lr) * 96;
    const uint4* srcW = (half ? g_wlo4 : g_whi4) + woff + (size_t)(o0 + lr) * 96;
    const u32 arow_sw[4] = {
        (u32)(lr * 128 + (((half * 4 + 0) ^ (lr & 7)) << 4)),
        (u32)(lr * 128 + (((half * 4 + 1) ^ (lr & 7)) << 4)),
        (u32)(lr * 128 + (((half * 4 + 2) ^ (lr & 7)) << 4)),
        (u32)(lr * 128 + (((half * 4 + 3) ^ (lr & 7)) << 4))
    };

    float acc[2][8][4];
#pragma unroll
    for (int i = 0; i < 2; i++)
#pragma unroll
        for (int j = 0; j < 8; j++)
#pragma unroll
            for (int c = 0; c < 4; c++) acc[i][j][c] = 0.f;

    {
        const u32 Ab = smbase, Wb = smbase + 16384;
#pragma unroll
        for (int g = 0; g < 4; g++) {
            CP_ASYNC16(Ab + arow_sw[g], srcA + g);
            CP_ASYNC16(Wb + arow_sw[g], srcW + g);
        }
        CP_COMMIT();
    }

#pragma unroll 1
    for (int kc = 0; kc < KCHUNKS; kc++) {
        if (kc + 1 < KCHUNKS) {
            const u32 st = smbase + ((kc + 1) & 1) * STAGE_BYTES;
            const u32 Ab = st, Wb = st + 16384;
            const int ko = (kc + 1) * 4;
#pragma unroll
            for (int g = 0; g < 4; g++) {
                CP_ASYNC16(Ab + arow_sw[g], srcA + ko + g);
                CP_ASYNC16(Wb + arow_sw[g], srcW + ko + g);
            }
            CP_COMMIT();
            CP_WAIT1();
        } else {
            CP_WAIT0();
        }
        __syncthreads();

        const u32 st = smbase + (kc & 1) * STAGE_BYTES;
        const u32 Ab = st, Wb = st + 16384;

#pragma unroll
        for (int ks = 0; ks < 2; ks++) {
            u32 ah[2][4], al[2][4];
#pragma unroll
            for (int mt = 0; mt < 2; mt++) {
                int row = warpM * 32 + mt * 16 + (lane & 15);
                int c = ks * 2 + ((lane >> 4) & 1);
                u32 base = Ab + row * 128;
                u32 ahi = base + (((c)     ^ (row & 7)) << 4);
                u32 alo = base + (((c + 4) ^ (row & 7)) << 4);
                LDSM4(ah[mt][0], ah[mt][1], ah[mt][2], ah[mt][3], ahi);
                LDSM4(al[mt][0], al[mt][1], al[mt][2], al[mt][3], alo);
            }
            u32 bh[8][2], bl[8][2];
#pragma unroll
            for (int bt = 0; bt < 4; bt++) {
                int row = warpN * 64 + bt * 16 + (lane & 7) + ((lane >> 4) & 1) * 8;
                int c = ks * 2 + ((lane >> 3) & 1);
                u32 base = Wb + row * 128;
                u32 bhi = base + (((c)     ^ (row & 7)) << 4);
                u32 blo = base + (((c + 4) ^ (row & 7)) << 4);
                u32 r0, r1, r2, r3;
                LDSM4(r0, r1, r2, r3, bhi);
                bh[bt * 2][0] = r0; bh[bt * 2][1] = r1;
                bh[bt * 2 + 1][0] = r2; bh[bt * 2 + 1][1] = r3;
                LDSM4(r0, r1, r2, r3, blo);
                bl[bt * 2][0] = r0; bl[bt * 2][1] = r1;
                bl[bt * 2 + 1][0] = r2; bl[bt * 2 + 1][1] = r3;
            }
#pragma unroll
            for (int mt = 0; mt < 2; mt++)
#pragma unroll
                for (int nt = 0; nt < 8; nt++) {
                    MMA16816(acc[mt][nt], ah[mt], bh[nt]);
                    MMA16816(acc[mt][nt], ah[mt], bl[nt]);
                    MMA16816(acc[mt][nt], al[mt], bh[nt]);
                }
        }
        __syncthreads();
    }

    // ---- epilogue ----
    u32* dsth = (u32*)(mode == 0 ? g_qh4 : mode == 1 ? g_kh4 : g_vh4);
    u32* dstl = (u32*)(mode == 0 ? g_ql4 : mode == 1 ? g_kl4 : g_vl4);
    const int h0 = blockIdx.x * 2;
#pragma unroll
    for (int mt = 0; mt < 2; mt++)
#pragma unroll
        for (int nt = 0; nt < 8; nt++)
#pragma unroll
            for (int cc = 0; cc < 2; cc++) {
                int rl = warpM * 32 + mt * 16 + (lane >> 2) + cc * 8;
                int cl = warpN * 64 + nt * 8 + (lane & 3) * 2;
                float v0 = acc[mt][nt][cc * 2 + 0] + bias_s[cl];
                float v1 = acc[mt][nt][cc * 2 + 1] + bias_s[cl + 1];
                int n = n0 + rl;
                if (mode < 3) {
                    int bb = n / SEQ, ss = n - bb * SEQ;
                    int h = h0 + (cl >> 6), d = cl & 63;
                    size_t idx = ((((size_t)bb * NH + h) * SEQ + ss) * HD + d);
                    u32 hp, lp; pack_hilo(v0, v1, hp, lp);
                    dsth[idx >> 1] = hp;
                    dstl[idx >> 1] = lp;
                } else {
                    float2* p = (float2*)(outp + (size_t)n * EMBD + o0 + cl);
                    *p = make_float2(v0, v1);
                }
            }
}

// =====================================================================
// HMMA attention: one CTA per (bh, 64-row q tile), 256 thr = 8 warps.
// smem: fp32 score slab [64][577] + bf16 hi/lo tiles (Q, K/V, P).
// =====================================================================
#define SC_B  0
#define QH_B  147712
#define QL_B  (QH_B + 8192)
#define KH_B  (QL_B + 8192)
#define KL_B  (KH_B + 8192)
#define PH_B  (KL_B + 8192)
#define PL_B  (PH_B + 8192)
#define ATTN_SMEM (PL_B + 8192)   // 196,864 B

__device__ __forceinline__ void load_tile64(
    char* smc, u32 dsth, u32 dstl,
    const uint4* __restrict__ srch, const uint4* __restrict__ srcl,
    int tokbase, int t)
{
#pragma unroll
    for (int it = 0; it < 2; it++) {
        int idx = t + it * 256;
        int r = idx >> 3, c = idx & 7;
        uint4 a = srch[(size_t)(tokbase + r) * 8 + c];
        uint4 b = srcl[(size_t)(tokbase + r) * 8 + c];
        u32 off = (u32)(r * 128 + ((c ^ (r & 7)) << 4));
        STS128(dsth + off, a.x, a.y, a.z, a.w);
        STS128(dstl + off, b.x, b.y, b.z, b.w);
    }
}

__global__ __launch_bounds__(256, 1) void attn_kernel(float* __restrict__ attn_out)
{
    extern __shared__ char smc[];
    const u32 smb = smem_u32(smc);
    float* sc = (float*)smc;

    const int t = threadIdx.x, lane = t & 31, wid = t >> 5;
    const int warpM = wid & 3;     // 16 q rows
    const int warpN = wid >> 2;    // 32 keys / 32 dims
    const int qt = blockIdx.x;
    const int bh = blockIdx.y;
    const int qtok = bh * SEQ + qt * 64;
    const int ktok0 = bh * SEQ;

    // load Q tile
    load_tile64(smc, smb + QH_B, smb + QL_B, g_qh4, g_ql4, qtok, t);

    // ================= scores =================
#pragma unroll 1
    for (int kt = 0; kt < 9; kt++) {
        __syncthreads();   // prev mma done / Q visible on kt=0
        load_tile64(smc, smb + KH_B, smb + KL_B, g_kh4, g_kl4, ktok0 + kt * 64, t);
        __syncthreads();

        float acc[4][4];
#pragma unroll
        for (int i = 0; i < 4; i++)
#pragma unroll
            for (int j = 0; j < 4; j++) acc[i][j] = 0.f;

#pragma unroll
        for (int ks = 0; ks < 4; ks++) {
            u32 ah[4], al[4];
            {
                int row = warpM * 16 + (lane & 15);
                int c = ks * 2 + ((lane >> 4) & 1);
                u32 sw = (u32)(row * 128 + ((c ^ (row & 7)) << 4));
                LDSM4(ah[0], ah[1], ah[2], ah[3], smb + QH_B + sw);
                LDSM4(al[0], al[1], al[2], al[3], smb + QL_B + sw);
            }
            u32 bh2[4][2], bl2[4][2];
#pragma unroll
            for (int bt = 0; bt < 2; bt++) {
                int row = warpN * 32 + bt * 16 + (lane & 7) + ((lane >> 4) & 1) * 8;
                int c = ks * 2 + ((lane >> 3) & 1);
                u32 sw = (u32)(row * 128 + ((c ^ (row & 7)) << 4));
                u32 r0, r1, r2, r3;
                LDSM4(r0, r1, r2, r3, smb + KH_B + sw);
                bh2[bt * 2][0] = r0; bh2[bt * 2][1] = r1;
                bh2[bt * 2 + 1][0] = r2; bh2[bt * 2 + 1][1] = r3;
                LDSM4(r0, r1, r2, r3, smb + KL_B + sw);
                bl2[bt * 2][0] = r0; bl2[bt * 2][1] = r1;
                bl2[bt * 2 + 1][0] = r2; bl2[bt * 2 + 1][1] = r3;
            }
#pragma unroll
            for (int nt = 0; nt < 4; nt++) {
                MMA16816(acc[nt], ah, bh2[nt]);
                MMA16816(acc[nt], ah, bl2[nt]);
                MMA16816(acc[nt], al, bh2[nt]);
            }
        }
        // write scaled scores to slab
#pragma unroll
        for (int nt = 0; nt < 4; nt++)
#pragma unroll
            for (int cc = 0; cc < 2; cc++) {
                int r = warpM * 16 + (lane >> 2) + cc * 8;
                int col = kt * 64 + warpN * 32 + nt * 8 + (lane & 3) * 2;
                sc[r * 577 + col]     = acc[nt][cc * 2]     * ATT_SCALE;
                sc[r * 577 + col + 1] = acc[nt][cc * 2 + 1] * ATT_SCALE;
            }
    }
    __syncthreads();

    // ================= softmax (+ write P to d_out) =================
    {
        for (int rr = 0; rr < 8; rr++) {
            int r = wid * 8 + rr;
            float* row = sc + r * 577;
            float m = -1e30f;
            for (int c = lane; c < SEQ; c += 32) m = fmaxf(m, row[c]);
#pragma unroll
            for (int off = 16; off > 0; off >>= 1)
                m = fmaxf(m, __shfl_xor_sync(0xffffffffu, m, off));
            float s = 0.f;
            for (int c = lane; c < SEQ; c += 32) {
                float e = __expf(row[c] - m);
                row[c] = e;
                s += e;
            }
#pragma unroll
            for (int off = 16; off > 0; off >>= 1)
                s += __shfl_xor_sync(0xffffffffu, s, off);
            float inv = 1.f / s;
            size_t arow = ((size_t)bh * SEQ + (size_t)(qt * 64 + r)) * SEQ;
            for (int c = lane; c < SEQ; c += 32) {
                float p = row[c] * inv;
                row[c] = p;
                attn_out[arow + c] = p;
            }
        }
    }
    __syncthreads();

    // ================= P @ V =================
    float acc2[4][4];
#pragma unroll
    for (int i = 0; i < 4; i++)
#pragma unroll
        for (int j = 0; j < 4; j++) acc2[i][j] = 0.f;

#pragma unroll 1
    for (int kt = 0; kt < 9; kt++) {
        // convert P chunk -> bf16 hi/lo swizzled tiles
#pragma unroll
        for (int i = 0; i < 8; i++) {
            int r = (t >> 5) * 8 + i;
            int u = t & 31;
            float p0 = sc[r * 577 + kt * 64 + u * 2];
            float p1 = sc[r * 577 + kt * 64 + u * 2 + 1];
            u32 hp, lp; pack_hilo(p0, p1, hp, lp);
            u32 off = (u32)(r * 128 + (((u >> 2) ^ (r & 7)) << 4) + (u & 3) * 4);
            *(u32*)(smc + PH_B + off) = hp;
            *(u32*)(smc + PL_B + off) = lp;
        }
        load_tile64(smc, smb + KH_B, smb + KL_B, g_vh4, g_vl4, ktok0 + kt * 64, t);
        __syncthreads();

#pragma unroll
        for (int ks = 0; ks < 4; ks++) {
            u32 ph[4], pl[4];
            {
                int row = warpM * 16 + (lane & 15);
                int c = ks * 2 + ((lane >> 4) & 1);
                u32 sw = (u32)(row * 128 + ((c ^ (row & 7)) << 4));
                LDSM4(ph[0], ph[1], ph[2], ph[3], smb + PH_B + sw);
                LDSM4(pl[0], pl[1], pl[2], pl[3], smb + PL_B + sw);
            }
            u32 vh[4][2], vl[4][2];
#pragma unroll
            for (int bt = 0; bt < 2; bt++) {
                int m = lane >> 3;
                int row_s = ks * 16 + ((m & 1) << 3) + (lane & 7);
                int chunk = warpN * 4 + bt * 2 + (m >> 1);
                u32 sw = (u32)(row_s * 128 + ((chunk ^ (row_s & 7)) << 4));
                u32 r0, r1, r2, r3;
                LDSM4T(r0, r1, r2, r3, smb + KH_B + sw);
                vh[bt * 2][0] = r0; vh[bt * 2][1] = r1;
                vh[bt * 2 + 1][0] = r2; vh[bt * 2 + 1][1] = r3;
                LDSM4T(r0, r1, r2, r3, smb + KL_B + sw);
                vl[bt * 2][0] = r0; vl[bt * 2][1] = r1;
                vl[bt * 2 + 1][0] = r2; vl[bt * 2 + 1][1] = r3;
            }
#pragma unroll
            for (int nt = 0; nt < 4; nt++) {
                MMA16816(acc2[nt], ph, vh[nt]);
                MMA16816(acc2[nt], ph, vl[nt]);
                MMA16816(acc2[nt], pl, vh[nt]);
            }
        }
        __syncthreads();
    }

    // ================= ctx epilogue (bf16 hi/lo) =================
    const int bb = bh / NH, h = bh % NH;
    u32* ch = (u32*)g_chi4;
    u32* cl2 = (u32*)g_clo4;
#pragma unroll
    for (int nt = 0; nt < 4; nt++)
#pragma unroll
        for (int cc = 0; cc < 2; cc++) {
            int r = warpM * 16 + (lane >> 2) + cc * 8;
            int d = warpN * 32 + nt * 8 + (lane & 3) * 2;
            size_t n = (size_t)bb * SEQ + (size_t)(qt * 64 + r);
            size_t idx = n * EMBD + h * 64 + d;
            u32 hp, lp;
            pack_hilo(acc2[nt][cc * 2], acc2[nt][cc * 2 + 1], hp, lp);
            ch[idx >> 1] = hp;
            cl2[idx >> 1] = lp;
        }
}

// =====================================================================
// launch
// =====================================================================
extern "C" void kernel_launch(void* const* d_in, const int* in_sizes, int n_in,
                              void* d_out, int out_size)
{
    const float* hs = (const float*)d_in[0];
    const float* qw = (const float*)d_in[1];
    const float* qb = (const float*)d_in[2];
    const float* kw = (const float*)d_in[3];
    const float* kb = (const float*)d_in[4];
    const float* vw = (const float*)d_in[5];
    const float* vb = (const float*)d_in[6];
    const float* ow = (const float*)d_in[7];
    const float* ob = (const float*)d_in[8];

    float* out  = (float*)d_out;
    float* attn = out + OUT_ELEMS;

    cudaFuncSetAttribute(mm_hmma_kernel, cudaFuncAttributeMaxDynamicSharedMemorySize,
                         MM_SMEM);
    cudaFuncSetAttribute(attn_kernel, cudaFuncAttributeMaxDynamicSharedMemorySize,
                         ATTN_SMEM);

    conv_x_kernel<<<(NT * EMBD / 8 + 255) / 256, 256>>>(hs);
    conv_w_kernel<<<dim3((EMBD * EMBD / 8 + 255) / 256, 4), 256>>>(qw, kw, vw, ow);

    mm_hmma_kernel<<<dim3(EMBD / 128, NT / 128, 3), 256, MM_SMEM>>>(
        qb, kb, vb, ob, out, 0);

    attn_kernel<<<dim3(9, BATCH * NH), 256, ATTN_SMEM>>>(attn);

    mm_hmma_kernel<<<dim3(EMBD / 128, NT / 128, 1), 256, MM_SMEM>>>(
        qb, kb, vb, ob, out, 3);
}

// round 5
// speedup vs baseline: 2.1193x; 1.1532x over previous
#include <cuda_runtime.h>
#include <cuda_bf16.h>

// ---------------- problem constants ----------------
#define BATCH 32
#define SEQ   576
#define EMBD  768
#define NH    12
#define HD    64
#define NT    (BATCH * SEQ)
#define OUT_ELEMS ((size_t)NT * EMBD)
#define ATT_SCALE 0.125f
#define KCHUNKS 24

typedef unsigned int u32;
typedef unsigned short u16;

// ---------------- device scratch ----------------
__device__ uint4 g_xhi4[NT * EMBD / 8];
__device__ uint4 g_xlo4[NT * EMBD / 8];
__device__ uint4 g_whi4[4 * EMBD * EMBD / 8];
__device__ uint4 g_wlo4[4 * EMBD * EMBD / 8];
__device__ uint4 g_chi4[NT * EMBD / 8];          // ctx hi/lo ([N, EMB])
__device__ uint4 g_clo4[NT * EMBD / 8];
__device__ uint4 g_qh4[NT * EMBD / 8];           // [B,H,S,D] bf16 hi/lo
__device__ uint4 g_ql4[NT * EMBD / 8];
__device__ uint4 g_kh4[NT * EMBD / 8];
__device__ uint4 g_kl4[NT * EMBD / 8];
__device__ uint4 g_vh4[NT * EMBD / 8];
__device__ uint4 g_vl4[NT * EMBD / 8];

// ---------------- helpers ----------------
__device__ __forceinline__ u32 smem_u32(const void* p) {
    u32 a;
    asm("{ .reg .u64 t; cvta.to.shared.u64 t, %1; cvt.u32.u64 %0, t; }"
        : "=r"(a) : "l"(p));
    return a;
}

#define CP_ASYNC16(dst, src) \
    asm volatile("cp.async.cg.shared.global [%0], [%1], 16;" \
                 :: "r"(dst), "l"(src) : "memory")
#define CP_COMMIT() asm volatile("cp.async.commit_group;" ::: "memory")
#define CP_WAIT1()  asm volatile("cp.async.wait_group 1;" ::: "memory")
#define CP_WAIT0()  asm volatile("cp.async.wait_group 0;" ::: "memory")

#define LDSM4(r0, r1, r2, r3, addr) \
    asm volatile("ldmatrix.sync.aligned.m8n8.x4.shared.b16 {%0,%1,%2,%3}, [%4];" \
                 : "=r"(r0), "=r"(r1), "=r"(r2), "=r"(r3) : "r"(addr))
#define LDSM4T(r0, r1, r2, r3, addr) \
    asm volatile("ldmatrix.sync.aligned.m8n8.x4.trans.shared.b16 {%0,%1,%2,%3}, [%4];" \
                 : "=r"(r0), "=r"(r1), "=r"(r2), "=r"(r3) : "r"(addr))

#define MMA16816(d, a, b) \
    asm volatile("mma.sync.aligned.m16n8k16.row.col.f32.bf16.bf16.f32 " \
                 "{%0,%1,%2,%3}, {%4,%5,%6,%7}, {%8,%9}, {%0,%1,%2,%3};" \
                 : "+f"((d)[0]), "+f"((d)[1]), "+f"((d)[2]), "+f"((d)[3]) \
                 : "r"((a)[0]), "r"((a)[1]), "r"((a)[2]), "r"((a)[3]), \
                   "r"((b)[0]), "r"((b)[1]))

#define STS128(addr, a, b, c, d) \
    asm volatile("st.shared.v4.b32 [%0], {%1, %2, %3, %4};" \
                 :: "r"(addr), "r"(a), "r"(b), "r"(c), "r"(d) : "memory")

__device__ __forceinline__ void pack_hilo(float v0, float v1, u32& hp, u32& lp) {
    __nv_bfloat16 h0 = __float2bfloat16(v0);
    __nv_bfloat16 h1 = __float2bfloat16(v1);
    __nv_bfloat16 l0 = __float2bfloat16(v0 - __bfloat162float(h0));
    __nv_bfloat16 l1 = __float2bfloat16(v1 - __bfloat162float(h1));
    hp = (u32)*(u16*)&h0 | ((u32)*(u16*)&h1 << 16);
    lp = (u32)*(u16*)&l0 | ((u32)*(u16*)&l1 << 16);
}

// =====================================================================
// hi/lo split conversion (X, W)
// =====================================================================
__device__ __forceinline__ void conv8(const float4* src2, uint4* hi, uint4* lo) {
    float4 a = src2[0], b = src2[1];
    float f[8] = {a.x, a.y, a.z, a.w, b.x, b.y, b.z, b.w};
    union { uint4 v; __nv_bfloat16 h[8]; } H, L;
#pragma unroll
    for (int j = 0; j < 8; j++) {
        __nv_bfloat16 hh = __float2bfloat16(f[j]);
        H.h[j] = hh;
        L.h[j] = __float2bfloat16(f[j] - __bfloat162float(hh));
    }
    *hi = H.v; *lo = L.v;
}

__global__ __launch_bounds__(256) void conv_x_kernel(const float* __restrict__ src) {
    int i = blockIdx.x * blockDim.x + threadIdx.x;
    if (i >= NT * EMBD / 8) return;
    conv8((const float4*)src + 2 * (size_t)i, &g_xhi4[i], &g_xlo4[i]);
}

__global__ __launch_bounds__(256) void conv_w_kernel(
    const float* __restrict__ qw, const float* __restrict__ kw,
    const float* __restrict__ vw, const float* __restrict__ ow) {
    int z = blockIdx.y;
    const float* src = z == 0 ? qw : z == 1 ? kw : z == 2 ? vw : ow;
    int i = blockIdx.x * blockDim.x + threadIdx.x;
    if (i >= EMBD * EMBD / 8) return;
    int di = z * (EMBD * EMBD / 8) + i;
    conv8((const float4*)src + 2 * (size_t)i, &g_whi4[di], &g_wlo4[di]);
}

// =====================================================================
// HMMA split-bf16 GEMM. 2 CTAs/SM (regs capped via launch_bounds).
// =====================================================================
#define STAGE_BYTES 32768
#define MM_SMEM (2 * STAGE_BYTES + 512)

__global__ __launch_bounds__(256, 2) void mm_hmma_kernel(
    const float* __restrict__ qb, const float* __restrict__ kb,
    const float* __restrict__ vb, const float* __restrict__ ob,
    float* __restrict__ outp, int mode_base)
{
    extern __shared__ char smraw[];
    const u32 smbase = smem_u32(smraw);
    float* bias_s = (float*)(smraw + 2 * STAGE_BYTES);

    const int t = threadIdx.x, lane = t & 31, wid = t >> 5;
    const int warpM = wid & 3;
    const int warpN = wid >> 2;
    const int mode = mode_base + blockIdx.z;
    const int o0 = blockIdx.x * 128;
    const int n0 = blockIdx.y * 128;

    const float* bias = mode == 0 ? qb : mode == 1 ? kb : mode == 2 ? vb : ob;
    const uint4* AhiG = (mode < 3) ? g_xhi4 : g_chi4;
    const uint4* AloG = (mode < 3) ? g_xlo4 : g_clo4;
    const size_t woff = (size_t)(mode < 3 ? mode : 3) * (EMBD * EMBD / 8);

    if (t < 128) bias_s[t] = bias[o0 + t];

    const int lr   = t >> 1;
    const int half = t & 1;
    const uint4* srcA = (half ? AloG : AhiG) + (size_t)(n0 + lr) * 96;
    const uint4* srcW = (half ? g_wlo4 : g_whi4) + woff + (size_t)(o0 + lr) * 96;
    const u32 arow_sw[4] = {
        (u32)(lr * 128 + (((half * 4 + 0) ^ (lr & 7)) << 4)),
        (u32)(lr * 128 + (((half * 4 + 1) ^ (lr & 7)) << 4)),
        (u32)(lr * 128 + (((half * 4 + 2) ^ (lr & 7)) << 4)),
        (u32)(lr * 128 + (((half * 4 + 3) ^ (lr & 7)) << 4))
    };

    float acc[2][8][4];
#pragma unroll
    for (int i = 0; i < 2; i++)
#pragma unroll
        for (int j = 0; j < 8; j++)
#pragma unroll
            for (int c = 0; c < 4; c++) acc[i][j][c] = 0.f;

    {
        const u32 Ab = smbase, Wb = smbase + 16384;
#pragma unroll
        for (int g = 0; g < 4; g++) {
            CP_ASYNC16(Ab + arow_sw[g], srcA + g);
            CP_ASYNC16(Wb + arow_sw[g], srcW + g);
        }
        CP_COMMIT();
    }

#pragma unroll 1
    for (int kc = 0; kc < KCHUNKS; kc++) {
        if (kc + 1 < KCHUNKS) {
            const u32 st = smbase + ((kc + 1) & 1) * STAGE_BYTES;
            const u32 Ab = st, Wb = st + 16384;
            const int ko = (kc + 1) * 4;
#pragma unroll
            for (int g = 0; g < 4; g++) {
                CP_ASYNC16(Ab + arow_sw[g], srcA + ko + g);
                CP_ASYNC16(Wb + arow_sw[g], srcW + ko + g);
            }
            CP_COMMIT();
            CP_WAIT1();
        } else {
            CP_WAIT0();
        }
        __syncthreads();

        const u32 st = smbase + (kc & 1) * STAGE_BYTES;
        const u32 Ab = st, Wb = st + 16384;

#pragma unroll
        for (int ks = 0; ks < 2; ks++) {
            u32 ah[2][4], al[2][4];
#pragma unroll
            for (int mt = 0; mt < 2; mt++) {
                int row = warpM * 32 + mt * 16 + (lane & 15);
                int c = ks * 2 + ((lane >> 4) & 1);
                u32 base = Ab + row * 128;
                u32 ahi = base + (((c)     ^ (row & 7)) << 4);
                u32 alo = base + (((c + 4) ^ (row & 7)) << 4);
                LDSM4(ah[mt][0], ah[mt][1], ah[mt][2], ah[mt][3], ahi);
                LDSM4(al[mt][0], al[mt][1], al[mt][2], al[mt][3], alo);
            }
            u32 bh[8][2], bl[8][2];
#pragma unroll
            for (int bt = 0; bt < 4; bt++) {
                int row = warpN * 64 + bt * 16 + (lane & 7) + ((lane >> 4) & 1) * 8;
                int c = ks * 2 + ((lane >> 3) & 1);
                u32 base = Wb + row * 128;
                u32 bhi = base + (((c)     ^ (row & 7)) << 4);
                u32 blo = base + (((c + 4) ^ (row & 7)) << 4);
                u32 r0, r1, r2, r3;
                LDSM4(r0, r1, r2, r3, bhi);
                bh[bt * 2][0] = r0; bh[bt * 2][1] = r1;
                bh[bt * 2 + 1][0] = r2; bh[bt * 2 + 1][1] = r3;
                LDSM4(r0, r1, r2, r3, blo);
                bl[bt * 2][0] = r0; bl[bt * 2][1] = r1;
                bl[bt * 2 + 1][0] = r2; bl[bt * 2 + 1][1] = r3;
            }
#pragma unroll
            for (int mt = 0; mt < 2; mt++)
#pragma unroll
                for (int nt = 0; nt < 8; nt++) {
                    MMA16816(acc[mt][nt], ah[mt], bh[nt]);
                    MMA16816(acc[mt][nt], ah[mt], bl[nt]);
                    MMA16816(acc[mt][nt], al[mt], bh[nt]);
                }
        }
        __syncthreads();
    }

    // ---- epilogue ----
    u32* dsth = (u32*)(mode == 0 ? g_qh4 : mode == 1 ? g_kh4 : g_vh4);
    u32* dstl = (u32*)(mode == 0 ? g_ql4 : mode == 1 ? g_kl4 : g_vl4);
    const int h0 = blockIdx.x * 2;
#pragma unroll
    for (int mt = 0; mt < 2; mt++)
#pragma unroll
        for (int nt = 0; nt < 8; nt++)
#pragma unroll
            for (int cc = 0; cc < 2; cc++) {
                int rl = warpM * 32 + mt * 16 + (lane >> 2) + cc * 8;
                int cl = warpN * 64 + nt * 8 + (lane & 3) * 2;
                float v0 = acc[mt][nt][cc * 2 + 0] + bias_s[cl];
                float v1 = acc[mt][nt][cc * 2 + 1] + bias_s[cl + 1];
                int n = n0 + rl;
                if (mode < 3) {
                    int bb = n / SEQ, ss = n - bb * SEQ;
                    int h = h0 + (cl >> 6), d = cl & 63;
                    size_t idx = ((((size_t)bb * NH + h) * SEQ + ss) * HD + d);
                    u32 hp, lp; pack_hilo(v0, v1, hp, lp);
                    dsth[idx >> 1] = hp;
                    dstl[idx >> 1] = lp;
                } else {
                    float2* p = (float2*)(outp + (size_t)n * EMBD + o0 + cl);
                    *p = make_float2(v0, v1);
                }
            }
}

// =====================================================================
// HMMA attention, 32-row q tiles, 2 CTAs/SM.
// warps: warpM = wid&1 (16 rows), warpN = wid>>1 (16 cols of 64-key tile)
// =====================================================================
#define SC_B  0
#define QH_B  73856
#define QL_B  (QH_B + 4096)
#define KH_B  (QL_B + 4096)
#define KL_B  (KH_B + 8192)
#define PH_B  (KL_B + 8192)
#define PL_B  (PH_B + 4096)
#define ATTN_SMEM (PL_B + 4096)   // 106,624 B

__device__ __forceinline__ void load_tile64(
    u32 dsth, u32 dstl,
    const uint4* __restrict__ srch, const uint4* __restrict__ srcl,
    int tokbase, int t)
{
#pragma unroll
    for (int it = 0; it < 2; it++) {
        int idx = t + it * 256;
        int r = idx >> 3, c = idx & 7;
        uint4 a = srch[(size_t)(tokbase + r) * 8 + c];
        uint4 b = srcl[(size_t)(tokbase + r) * 8 + c];
        u32 off = (u32)(r * 128 + ((c ^ (r & 7)) << 4));
        STS128(dsth + off, a.x, a.y, a.z, a.w);
        STS128(dstl + off, b.x, b.y, b.z, b.w);
    }
}

__global__ __launch_bounds__(256, 2) void attn_kernel(float* __restrict__ attn_out)
{
    extern __shared__ char smc[];
    const u32 smb = smem_u32(smc);
    float* sc = (float*)smc;

    const int t = threadIdx.x, lane = t & 31, wid = t >> 5;
    const int warpM = wid & 1;     // 16 q rows
    const int warpN = wid >> 1;    // 16 keys / 16 dims
    const int qt = blockIdx.x;     // 0..17 (32-row tiles)
    const int bh = blockIdx.y;
    const int qtok = bh * SEQ + qt * 32;
    const int ktok0 = bh * SEQ;

    // load Q tile (32 rows x 64 dims, hi/lo)
    {
        int r = t >> 3, c = t & 7;
        uint4 a = g_qh4[(size_t)(qtok + r) * 8 + c];
        uint4 b = g_ql4[(size_t)(qtok + r) * 8 + c];
        u32 off = (u32)(r * 128 + ((c ^ (r & 7)) << 4));
        STS128(smb + QH_B + off, a.x, a.y, a.z, a.w);
        STS128(smb + QL_B + off, b.x, b.y, b.z, b.w);
    }

    // ================= scores =================
#pragma unroll 1
    for (int kt = 0; kt < 9; kt++) {
        __syncthreads();
        load_tile64(smb + KH_B, smb + KL_B, g_kh4, g_kl4, ktok0 + kt * 64, t);
        __syncthreads();

        float acc[2][4];
#pragma unroll
        for (int i = 0; i < 2; i++)
#pragma unroll
            for (int j = 0; j < 4; j++) acc[i][j] = 0.f;

#pragma unroll
        for (int ks = 0; ks < 4; ks++) {
            u32 ah[4], al[4];
            {
                int row = warpM * 16 + (lane & 15);
                int c = ks * 2 + ((lane >> 4) & 1);
                u32 sw = (u32)(row * 128 + ((c ^ (row & 7)) << 4));
                LDSM4(ah[0], ah[1], ah[2], ah[3], smb + QH_B + sw);
                LDSM4(al[0], al[1], al[2], al[3], smb + QL_B + sw);
            }
            u32 bh2[2][2], bl2[2][2];
            {
                int row = warpN * 16 + (lane & 7) + ((lane >> 4) & 1) * 8;
                int c = ks * 2 + ((lane >> 3) & 1);
                u32 sw = (u32)(row * 128 + ((c ^ (row & 7)) << 4));
                u32 r0, r1, r2, r3;
                LDSM4(r0, r1, r2, r3, smb + KH_B + sw);
                bh2[0][0] = r0; bh2[0][1] = r1;
                bh2[1][0] = r2; bh2[1][1] = r3;
                LDSM4(r0, r1, r2, r3, smb + KL_B + sw);
                bl2[0][0] = r0; bl2[0][1] = r1;
                bl2[1][0] = r2; bl2[1][1] = r3;
            }
#pragma unroll
            for (int nt = 0; nt < 2; nt++) {
                MMA16816(acc[nt], ah, bh2[nt]);
                MMA16816(acc[nt], ah, bl2[nt]);
                MMA16816(acc[nt], al, bh2[nt]);
            }
        }
#pragma unroll
        for (int nt = 0; nt < 2; nt++)
#pragma unroll
            for (int cc = 0; cc < 2; cc++) {
                int r = warpM * 16 + (lane >> 2) + cc * 8;
                int col = kt * 64 + warpN * 16 + nt * 8 + (lane & 3) * 2;
                sc[r * 577 + col]     = acc[nt][cc * 2]     * ATT_SCALE;
                sc[r * 577 + col + 1] = acc[nt][cc * 2 + 1] * ATT_SCALE;
            }
    }
    __syncthreads();

    // ================= softmax (+ write P to d_out) =================
    {
        for (int rr = 0; rr < 4; rr++) {
            int r = wid * 4 + rr;
            float* row = sc + r * 577;
            float m = -1e30f;
            for (int c = lane; c < SEQ; c += 32) m = fmaxf(m, row[c]);
#pragma unroll
            for (int off = 16; off > 0; off >>= 1)
                m = fmaxf(m, __shfl_xor_sync(0xffffffffu, m, off));
            float s = 0.f;
            for (int c = lane; c < SEQ; c += 32) {
                float e = __expf(row[c] - m);
                row[c] = e;
                s += e;
            }
#pragma unroll
            for (int off = 16; off > 0; off >>= 1)
                s += __shfl_xor_sync(0xffffffffu, s, off);
            float inv = 1.f / s;
            size_t arow = ((size_t)bh * SEQ + (size_t)(qt * 32 + r)) * SEQ;
            for (int c = lane; c < SEQ; c += 32) {
                float p = row[c] * inv;
                row[c] = p;
                attn_out[arow + c] = p;
            }
        }
    }
    __syncthreads();

    // ================= P @ V =================
    float acc2[2][4];
#pragma unroll
    for (int i = 0; i < 2; i++)
#pragma unroll
        for (int j = 0; j < 4; j++) acc2[i][j] = 0.f;

#pragma unroll 1
    for (int kt = 0; kt < 9; kt++) {
        // P chunk -> bf16 hi/lo swizzled tiles (32 rows x 64 cols)
#pragma unroll
        for (int i = 0; i < 4; i++) {
            int r = wid * 4 + i;
            int u = lane;
            float p0 = sc[r * 577 + kt * 64 + u * 2];
            float p1 = sc[r * 577 + kt * 64 + u * 2 + 1];
            u32 hp, lp; pack_hilo(p0, p1, hp, lp);
            u32 off = (u32)(r * 128 + (((u >> 2) ^ (r & 7)) << 4) + (u & 3) * 4);
            *(u32*)(smc + PH_B + off) = hp;
            *(u32*)(smc + PL_B + off) = lp;
        }
        load_tile64(smb + KH_B, smb + KL_B, g_vh4, g_vl4, ktok0 + kt * 64, t);
        __syncthreads();

#pragma unroll
        for (int ks = 0; ks < 4; ks++) {
            u32 ph[4], pl[4];
            {
                int row = warpM * 16 + (lane & 15);
                int c = ks * 2 + ((lane >> 4) & 1);
                u32 sw = (u32)(row * 128 + ((c ^ (row & 7)) << 4));
                LDSM4(ph[0], ph[1], ph[2], ph[3], smb + PH_B + sw);
                LDSM4(pl[0], pl[1], pl[2], pl[3], smb + PL_B + sw);
            }
            u32 vh[2][2], vl[2][2];
            {
                int m = lane >> 3;
                int row_s = ks * 16 + ((m & 1) << 3) + (lane & 7);
                int chunk = warpN * 2 + (m >> 1);
                u32 sw = (u32)(row_s * 128 + ((chunk ^ (row_s & 7)) << 4));
                u32 r0, r1, r2, r3;
                LDSM4T(r0, r1, r2, r3, smb + KH_B + sw);
                vh[0][0] = r0; vh[0][1] = r1;
                vh[1][0] = r2; vh[1][1] = r3;
                LDSM4T(r0, r1, r2, r3, smb + KL_B + sw);
                vl[0][0] = r0; vl[0][1] = r1;
                vl[1][0] = r2; vl[1][1] = r3;
            }
#pragma unroll
            for (int nt = 0; nt < 2; nt++) {
                MMA16816(acc2[nt], ph, vh[nt]);
                MMA16816(acc2[nt], ph, vl[nt]);
                MMA16816(acc2[nt], pl, vh[nt]);
            }
        }
        __syncthreads();
    }

    // ================= ctx epilogue (bf16 hi/lo) =================
    const int bb = bh / NH, h = bh % NH;
    u32* ch = (u32*)g_chi4;
    u32* cl2 = (u32*)g_clo4;
#pragma unroll
    for (int nt = 0; nt < 2; nt++)
#pragma unroll
        for (int cc = 0; cc < 2; cc++) {
            int r = warpM * 16 + (lane >> 2) + cc * 8;
            int d = warpN * 16 + nt * 8 + (lane & 3) * 2;
            size_t n = (size_t)bb * SEQ + (size_t)(qt * 32 + r);
            size_t idx = n * EMBD + h * 64 + d;
            u32 hp, lp;
            pack_hilo(acc2[nt][cc * 2], acc2[nt][cc * 2 + 1], hp, lp);
            ch[idx >> 1] = hp;
            cl2[idx >> 1] = lp;
        }
}

// =====================================================================
// launch
// =====================================================================
extern "C" void kernel_launch(void* const* d_in, const int* in_sizes, int n_in,
                              void* d_out, int out_size)
{
    const float* hs = (const float*)d_in[0];
    const float* qw = (const float*)d_in[1];
    const float* qb = (const float*)d_in[2];
    const float* kw = (const float*)d_in[3];
    const float* kb = (const float*)d_in[4];
    const float* vw = (const float*)d_in[5];
    const float* vb = (const float*)d_in[6];
    const float* ow = (const float*)d_in[7];
    const float* ob = (const float*)d_in[8];

    float* out  = (float*)d_out;
    float* attn = out + OUT_ELEMS;

    cudaFuncSetAttribute(mm_hmma_kernel, cudaFuncAttributeMaxDynamicSharedMemorySize,
                         MM_SMEM);
    cudaFuncSetAttribute(attn_kernel, cudaFuncAttributeMaxDynamicSharedMemorySize,
                         ATTN_SMEM);

    conv_x_kernel<<<(NT * EMBD / 8 + 255) / 256, 256>>>(hs);
    conv_w_kernel<<<dim3((EMBD * EMBD / 8 + 255) / 256, 4), 256>>>(qw, kw, vw, ow);

    mm_hmma_kernel<<<dim3(EMBD / 128, NT / 128, 3), 256, MM_SMEM>>>(
        qb, kb, vb, ob, out, 0);

    attn_kernel<<<dim3(18, BATCH * NH), 256, ATTN_SMEM>>>(attn);

    mm_hmma_kernel<<<dim3(EMBD / 128, NT / 128, 1), 256, MM_SMEM>>>(
        qb, kb, vb, ob, out, 3);
}

// round 6
// speedup vs baseline: 2.4579x; 1.1598x over previous
#include <cuda_runtime.h>
#include <cuda_fp16.h>

// ---------------- problem constants ----------------
#define BATCH 32
#define SEQ   576
#define EMBD  768
#define NH    12
#define HD    64
#define NT    (BATCH * SEQ)
#define OUT_ELEMS ((size_t)NT * EMBD)
#define ATT_SCALE 0.125f
#define KCHUNKS 24

typedef unsigned int u32;
typedef unsigned short u16;

// ---------------- device scratch ----------------
__device__ uint4 g_xhi4[NT * EMBD / 8];
__device__ uint4 g_xlo4[NT * EMBD / 8];
__device__ uint4 g_whi4[4 * EMBD * EMBD / 8];
__device__ uint4 g_wlo4[4 * EMBD * EMBD / 8];
__device__ uint4 g_chi4[NT * EMBD / 8];          // ctx hi only ([N, EMB], fp16)
__device__ uint4 g_qh4[NT * EMBD / 8];           // [B,H,S,D] fp16 hi/lo
__device__ uint4 g_ql4[NT * EMBD / 8];
__device__ uint4 g_kh4[NT * EMBD / 8];
__device__ uint4 g_kl4[NT * EMBD / 8];
__device__ uint4 g_vh4[NT * EMBD / 8];
__device__ uint4 g_vl4[NT * EMBD / 8];

// ---------------- helpers ----------------
__device__ __forceinline__ u32 smem_u32(const void* p) {
    u32 a;
    asm("{ .reg .u64 t; cvta.to.shared.u64 t, %1; cvt.u32.u64 %0, t; }"
        : "=r"(a) : "l"(p));
    return a;
}

#define CP_ASYNC16(dst, src) \
    asm volatile("cp.async.cg.shared.global [%0], [%1], 16;" \
                 :: "r"(dst), "l"(src) : "memory")
#define CP_COMMIT() asm volatile("cp.async.commit_group;" ::: "memory")
#define CP_WAIT1()  asm volatile("cp.async.wait_group 1;" ::: "memory")
#define CP_WAIT0()  asm volatile("cp.async.wait_group 0;" ::: "memory")

#define LDSM4(r0, r1, r2, r3, addr) \
    asm volatile("ldmatrix.sync.aligned.m8n8.x4.shared.b16 {%0,%1,%2,%3}, [%4];" \
                 : "=r"(r0), "=r"(r1), "=r"(r2), "=r"(r3) : "r"(addr))
#define LDSM4T(r0, r1, r2, r3, addr) \
    asm volatile("ldmatrix.sync.aligned.m8n8.x4.trans.shared.b16 {%0,%1,%2,%3}, [%4];" \
                 : "=r"(r0), "=r"(r1), "=r"(r2), "=r"(r3) : "r"(addr))

#define MMA16816(d, a, b) \
    asm volatile("mma.sync.aligned.m16n8k16.row.col.f32.f16.f16.f32 " \
                 "{%0,%1,%2,%3}, {%4,%5,%6,%7}, {%8,%9}, {%0,%1,%2,%3};" \
                 : "+f"((d)[0]), "+f"((d)[1]), "+f"((d)[2]), "+f"((d)[3]) \
                 : "r"((a)[0]), "r"((a)[1]), "r"((a)[2]), "r"((a)[3]), \
                   "r"((b)[0]), "r"((b)[1]))

#define STS128(addr, a, b, c, d) \
    asm volatile("st.shared.v4.b32 [%0], {%1, %2, %3, %4};" \
                 :: "r"(addr), "r"(a), "r"(b), "r"(c), "r"(d) : "memory")

__device__ __forceinline__ void pack_hilo(float v0, float v1, u32& hp, u32& lp) {
    __half h0 = __float2half_rn(v0);
    __half h1 = __float2half_rn(v1);
    __half l0 = __float2half_rn(v0 - __half2float(h0));
    __half l1 = __float2half_rn(v1 - __half2float(h1));
    hp = (u32)*(u16*)&h0 | ((u32)*(u16*)&h1 << 16);
    lp = (u32)*(u16*)&l0 | ((u32)*(u16*)&l1 << 16);
}
__device__ __forceinline__ u32 pack_hi(float v0, float v1) {
    __half h0 = __float2half_rn(v0);
    __half h1 = __float2half_rn(v1);
    return (u32)*(u16*)&h0 | ((u32)*(u16*)&h1 << 16);
}

// =====================================================================
// hi/lo split conversion (fp16)
// =====================================================================
__device__ __forceinline__ void conv8(const float4* src2, uint4* hi, uint4* lo) {
    float4 a = src2[0], b = src2[1];
    float f[8] = {a.x, a.y, a.z, a.w, b.x, b.y, b.z, b.w};
    union { uint4 v; __half h[8]; } H, L;
#pragma unroll
    for (int j = 0; j < 8; j++) {
        __half hh = __float2half_rn(f[j]);
        H.h[j] = hh;
        L.h[j] = __float2half_rn(f[j] - __half2float(hh));
    }
    *hi = H.v; *lo = L.v;
}

__global__ __launch_bounds__(256) void conv_x_kernel(const float* __restrict__ src) {
    int i = blockIdx.x * blockDim.x + threadIdx.x;
    if (i >= NT * EMBD / 8) return;
    conv8((const float4*)src + 2 * (size_t)i, &g_xhi4[i], &g_xlo4[i]);
}

__global__ __launch_bounds__(256) void conv_w_kernel(
    const float* __restrict__ qw, const float* __restrict__ kw,
    const float* __restrict__ vw, const float* __restrict__ ow) {
    int z = blockIdx.y;
    const float* src = z == 0 ? qw : z == 1 ? kw : z == 2 ? vw : ow;
    int i = blockIdx.x * blockDim.x + threadIdx.x;
    if (i >= EMBD * EMBD / 8) return;
    int di = z * (EMBD * EMBD / 8) + i;
    conv8((const float4*)src + 2 * (size_t)i, &g_whi4[di], &g_wlo4[di]);
}

// =====================================================================
// HMMA split-fp16 GEMM.
// modes 0,1 (Q,K): 3-term. mode 2 (V): 2-term (hh+hl). mode 3 (O): 2-term,
// A = ctx hi only. Epilogue: modes<3 -> fp16 hi/lo scatter; mode3 -> fp32 out.
// =====================================================================
#define STAGE_BYTES 32768
#define MM_SMEM (2 * STAGE_BYTES + 512)

__global__ __launch_bounds__(256, 2) void mm_hmma_kernel(
    const float* __restrict__ qb, const float* __restrict__ kb,
    const float* __restrict__ vb, const float* __restrict__ ob,
    float* __restrict__ outp, int mode_base)
{
    extern __shared__ char smraw[];
    const u32 smbase = smem_u32(smraw);
    float* bias_s = (float*)(smraw + 2 * STAGE_BYTES);

    const int t = threadIdx.x, lane = t & 31, wid = t >> 5;
    const int warpM = wid & 3;
    const int warpN = wid >> 2;
    const int mode = mode_base + blockIdx.z;
    const bool need3 = (mode < 2);
    const int o0 = blockIdx.x * 128;
    const int n0 = blockIdx.y * 128;

    const float* bias = mode == 0 ? qb : mode == 1 ? kb : mode == 2 ? vb : ob;
    const uint4* AhiG = (mode < 3) ? g_xhi4 : g_chi4;
    const uint4* AloG = g_xlo4;   // only used when mode<2 (half==1 loader)
    const size_t woff = (size_t)(mode < 3 ? mode : 3) * (EMBD * EMBD / 8);

    if (t < 128) bias_s[t] = bias[o0 + t];

    const int lr   = t >> 1;
    const int half = t & 1;
    const bool loadA = need3 || (half == 0);
    const uint4* srcA = (half ? AloG : AhiG) + (size_t)(n0 + lr) * 96;
    const uint4* srcW = (half ? g_wlo4 : g_whi4) + woff + (size_t)(o0 + lr) * 96;
    const u32 arow_sw[4] = {
        (u32)(lr * 128 + (((half * 4 + 0) ^ (lr & 7)) << 4)),
        (u32)(lr * 128 + (((half * 4 + 1) ^ (lr & 7)) << 4)),
        (u32)(lr * 128 + (((half * 4 + 2) ^ (lr & 7)) << 4)),
        (u32)(lr * 128 + (((half * 4 + 3) ^ (lr & 7)) << 4))
    };

    float acc[2][8][4];
#pragma unroll
    for (int i = 0; i < 2; i++)
#pragma unroll
        for (int j = 0; j < 8; j++)
#pragma unroll
            for (int c = 0; c < 4; c++) acc[i][j][c] = 0.f;

    {
        const u32 Ab = smbase, Wb = smbase + 16384;
#pragma unroll
        for (int g = 0; g < 4; g++) {
            if (loadA) CP_ASYNC16(Ab + arow_sw[g], srcA + g);
            CP_ASYNC16(Wb + arow_sw[g], srcW + g);
        }
        CP_COMMIT();
    }

#pragma unroll 1
    for (int kc = 0; kc < KCHUNKS; kc++) {
        if (kc + 1 < KCHUNKS) {
            const u32 st = smbase + ((kc + 1) & 1) * STAGE_BYTES;
            const u32 Ab = st, Wb = st + 16384;
            const int ko = (kc + 1) * 4;
#pragma unroll
            for (int g = 0; g < 4; g++) {
                if (loadA) CP_ASYNC16(Ab + arow_sw[g], srcA + ko + g);
                CP_ASYNC16(Wb + arow_sw[g], srcW + ko + g);
            }
            CP_COMMIT();
            CP_WAIT1();
        } else {
            CP_WAIT0();
        }
        __syncthreads();

        const u32 st = smbase + (kc & 1) * STAGE_BYTES;
        const u32 Ab = st, Wb = st + 16384;

#pragma unroll
        for (int ks = 0; ks < 2; ks++) {
            u32 ah[2][4], al[2][4];
#pragma unroll
            for (int mt = 0; mt < 2; mt++) {
                int row = warpM * 32 + mt * 16 + (lane & 15);
                int c = ks * 2 + ((lane >> 4) & 1);
                u32 base = Ab + row * 128;
                u32 ahi = base + (((c)     ^ (row & 7)) << 4);
                LDSM4(ah[mt][0], ah[mt][1], ah[mt][2], ah[mt][3], ahi);
                if (need3) {
                    u32 alo = base + (((c + 4) ^ (row & 7)) << 4);
                    LDSM4(al[mt][0], al[mt][1], al[mt][2], al[mt][3], alo);
                }
            }
            u32 bh[8][2], bl[8][2];
#pragma unroll
            for (int bt = 0; bt < 4; bt++) {
                int row = warpN * 64 + bt * 16 + (lane & 7) + ((lane >> 4) & 1) * 8;
                int c = ks * 2 + ((lane >> 3) & 1);
                u32 base = Wb + row * 128;
                u32 bhi = base + (((c)     ^ (row & 7)) << 4);
                u32 blo = base + (((c + 4) ^ (row & 7)) << 4);
                u32 r0, r1, r2, r3;
                LDSM4(r0, r1, r2, r3, bhi);
                bh[bt * 2][0] = r0; bh[bt * 2][1] = r1;
                bh[bt * 2 + 1][0] = r2; bh[bt * 2 + 1][1] = r3;
                LDSM4(r0, r1, r2, r3, blo);
                bl[bt * 2][0] = r0; bl[bt * 2][1] = r1;
                bl[bt * 2 + 1][0] = r2; bl[bt * 2 + 1][1] = r3;
            }
#pragma unroll
            for (int mt = 0; mt < 2; mt++)
#pragma unroll
                for (int nt = 0; nt < 8; nt++) {
                    MMA16816(acc[mt][nt], ah[mt], bh[nt]);
                    MMA16816(acc[mt][nt], ah[mt], bl[nt]);
                    if (need3) MMA16816(acc[mt][nt], al[mt], bh[nt]);
                }
        }
        __syncthreads();
    }

    // ---- epilogue ----
    u32* dsth = (u32*)(mode == 0 ? g_qh4 : mode == 1 ? g_kh4 : g_vh4);
    u32* dstl = (u32*)(mode == 0 ? g_ql4 : mode == 1 ? g_kl4 : g_vl4);
    const int h0 = blockIdx.x * 2;
#pragma unroll
    for (int mt = 0; mt < 2; mt++)
#pragma unroll
        for (int nt = 0; nt < 8; nt++)
#pragma unroll
            for (int cc = 0; cc < 2; cc++) {
                int rl = warpM * 32 + mt * 16 + (lane >> 2) + cc * 8;
                int cl = warpN * 64 + nt * 8 + (lane & 3) * 2;
                float v0 = acc[mt][nt][cc * 2 + 0] + bias_s[cl];
                float v1 = acc[mt][nt][cc * 2 + 1] + bias_s[cl + 1];
                int n = n0 + rl;
                if (mode < 3) {
                    int bb = n / SEQ, ss = n - bb * SEQ;
                    int h = h0 + (cl >> 6), d = cl & 63;
                    size_t idx = ((((size_t)bb * NH + h) * SEQ + ss) * HD + d);
                    u32 hp, lp; pack_hilo(v0, v1, hp, lp);
                    dsth[idx >> 1] = hp;
                    dstl[idx >> 1] = lp;
                } else {
                    float2* p = (float2*)(outp + (size_t)n * EMBD + o0 + cl);
                    *p = make_float2(v0, v1);
                }
            }
}

// =====================================================================
// HMMA attention, 32-row q tiles, 2 CTAs/SM.
// scores 3-term fp16; P·V 2-term (P hi only); ctx epilogue hi only.
// =====================================================================
#define SLAB_W 578
#define SC_B  0
#define QH_B  (32 * SLAB_W * 4)            // 73,984
#define QL_B  (QH_B + 4096)
#define KH_B  (QL_B + 4096)
#define KL_B  (KH_B + 8192)
#define PH_B  (KL_B + 8192)
#define INV_B (PH_B + 4096)
#define ATTN_SMEM (INV_B + 128)            // 102,912 B

__device__ __forceinline__ void load_tile64_async(
    u32 dsth, u32 dstl,
    const uint4* __restrict__ srch, const uint4* __restrict__ srcl,
    int tokbase, int t)
{
#pragma unroll
    for (int it = 0; it < 2; it++) {
        int idx = t + it * 256;
        int r = idx >> 3, c = idx & 7;
        u32 off = (u32)(r * 128 + ((c ^ (r & 7)) << 4));
        CP_ASYNC16(dsth + off, srch + (size_t)(tokbase + r) * 8 + c);
        CP_ASYNC16(dstl + off, srcl + (size_t)(tokbase + r) * 8 + c);
    }
    CP_COMMIT();
}

__global__ __launch_bounds__(256, 2) void attn_kernel(float* __restrict__ attn_out)
{
    extern __shared__ char smc[];
    const u32 smb = smem_u32(smc);
    float* sc = (float*)smc;
    float* inv_s = (float*)(smc + INV_B);

    const int t = threadIdx.x, lane = t & 31, wid = t >> 5;
    const int warpM = wid & 1;
    const int warpN = wid >> 1;
    const int qt = blockIdx.x;
    const int bh = blockIdx.y;
    const int qtok = bh * SEQ + qt * 32;
    const int ktok0 = bh * SEQ;

    // load Q tile (32 x 64, hi/lo)
    {
        int r = t >> 3, c = t & 7;
        uint4 a = g_qh4[(size_t)(qtok + r) * 8 + c];
        uint4 b = g_ql4[(size_t)(qtok + r) * 8 + c];
        u32 off = (u32)(r * 128 + ((c ^ (r & 7)) << 4));
        STS128(smb + QH_B + off, a.x, a.y, a.z, a.w);
        STS128(smb + QL_B + off, b.x, b.y, b.z, b.w);
    }
    __syncthreads();

    // hoist Q fragments for all 4 k-steps
    u32 qh[4][4], ql[4][4];
#pragma unroll
    for (int ks = 0; ks < 4; ks++) {
        int row = warpM * 16 + (lane & 15);
        int c = ks * 2 + ((lane >> 4) & 1);
        u32 sw = (u32)(row * 128 + ((c ^ (row & 7)) << 4));
        LDSM4(qh[ks][0], qh[ks][1], qh[ks][2], qh[ks][3], smb + QH_B + sw);
        LDSM4(ql[ks][0], ql[ks][1], ql[ks][2], ql[ks][3], smb + QL_B + sw);
    }

    // ================= scores =================
#pragma unroll 1
    for (int kt = 0; kt < 9; kt++) {
        __syncthreads();
        load_tile64_async(smb + KH_B, smb + KL_B, g_kh4, g_kl4, ktok0 + kt * 64, t);
        CP_WAIT0();
        __syncthreads();

        float acc[2][4];
#pragma unroll
        for (int i = 0; i < 2; i++)
#pragma unroll
            for (int j = 0; j < 4; j++) acc[i][j] = 0.f;

#pragma unroll
        for (int ks = 0; ks < 4; ks++) {
            u32 bh2[2][2], bl2[2][2];
            {
                int row = warpN * 16 + (lane & 7) + ((lane >> 4) & 1) * 8;
                int c = ks * 2 + ((lane >> 3) & 1);
                u32 sw = (u32)(row * 128 + ((c ^ (row & 7)) << 4));
                u32 r0, r1, r2, r3;
                LDSM4(r0, r1, r2, r3, smb + KH_B + sw);
                bh2[0][0] = r0; bh2[0][1] = r1;
                bh2[1][0] = r2; bh2[1][1] = r3;
                LDSM4(r0, r1, r2, r3, smb + KL_B + sw);
                bl2[0][0] = r0; bl2[0][1] = r1;
                bl2[1][0] = r2; bl2[1][1] = r3;
            }
#pragma unroll
            for (int nt = 0; nt < 2; nt++) {
                MMA16816(acc[nt], qh[ks], bh2[nt]);
                MMA16816(acc[nt], qh[ks], bl2[nt]);
                MMA16816(acc[nt], ql[ks], bh2[nt]);
            }
        }
#pragma unroll
        for (int nt = 0; nt < 2; nt++)
#pragma unroll
            for (int cc = 0; cc < 2; cc++) {
                int r = warpM * 16 + (lane >> 2) + cc * 8;
                int col = kt * 64 + warpN * 16 + nt * 8 + (lane & 3) * 2;
                float2* p = (float2*)(sc + r * SLAB_W + col);
                *p = make_float2(acc[nt][cc * 2] * ATT_SCALE,
                                 acc[nt][cc * 2 + 1] * ATT_SCALE);
            }
    }
    __syncthreads();

    // ================= softmax: store exp + 1/sum =================
    {
        for (int rr = 0; rr < 4; rr++) {
            int r = wid * 4 + rr;
            float* row = sc + r * SLAB_W;
            float m = -1e30f;
            for (int c = lane; c < SEQ; c += 32) m = fmaxf(m, row[c]);
#pragma unroll
            for (int off = 16; off > 0; off >>= 1)
                m = fmaxf(m, __shfl_xor_sync(0xffffffffu, m, off));
            float s = 0.f;
            for (int c = lane; c < SEQ; c += 32) {
                float e = __expf(row[c] - m);
                row[c] = e;
                s += e;
            }
#pragma unroll
            for (int off = 16; off > 0; off >>= 1)
                s += __shfl_xor_sync(0xffffffffu, s, off);
            if (lane == 0) inv_s[r] = 1.f / s;
        }
    }
    __syncthreads();

    // ================= P @ V (2-term, P hi only) =================
    float acc2[2][4];
#pragma unroll
    for (int i = 0; i < 2; i++)
#pragma unroll
        for (int j = 0; j < 4; j++) acc2[i][j] = 0.f;

#pragma unroll 1
    for (int kt = 0; kt < 9; kt++) {
        __syncthreads();
        load_tile64_async(smb + KH_B, smb + KL_B, g_vh4, g_vl4, ktok0 + kt * 64, t);
        // normalize P chunk, write attn to gmem, pack fp16 hi into PH tile
#pragma unroll
        for (int i = 0; i < 4; i++) {
            int r = wid * 4 + i;
            float inv = inv_s[r];
            float2 e = *(const float2*)(sc + r * SLAB_W + kt * 64 + lane * 2);
            float p0 = e.x * inv, p1 = e.y * inv;
            size_t arow = ((size_t)bh * SEQ + (size_t)(qt * 32 + r)) * SEQ;
            *(float2*)(attn_out + arow + kt * 64 + lane * 2) = make_float2(p0, p1);
            u32 off = (u32)(r * 128 + (((lane >> 2) ^ (r & 7)) << 4) + (lane & 3) * 4);
            *(u32*)(smc + PH_B + off) = pack_hi(p0, p1);
        }
        CP_WAIT0();
        __syncthreads();

#pragma unroll
        for (int ks = 0; ks < 4; ks++) {
            u32 ph[4];
            {
                int row = warpM * 16 + (lane & 15);
                int c = ks * 2 + ((lane >> 4) & 1);
                u32 sw = (u32)(row * 128 + ((c ^ (row & 7)) << 4));
                LDSM4(ph[0], ph[1], ph[2], ph[3], smb + PH_B + sw);
            }
            u32 vh[2][2], vl[2][2];
            {
                int m = lane >> 3;
                int row_s = ks * 16 + ((m & 1) << 3) + (lane & 7);
                int chunk = warpN * 2 + (m >> 1);
                u32 sw = (u32)(row_s * 128 + ((chunk ^ (row_s & 7)) << 4));
                u32 r0, r1, r2, r3;
                LDSM4T(r0, r1, r2, r3, smb + KH_B + sw);
                vh[0][0] = r0; vh[0][1] = r1;
                vh[1][0] = r2; vh[1][1] = r3;
                LDSM4T(r0, r1, r2, r3, smb + KL_B + sw);
                vl[0][0] = r0; vl[0][1] = r1;
                vl[1][0] = r2; vl[1][1] = r3;
            }
#pragma unroll
            for (int nt = 0; nt < 2; nt++) {
                MMA16816(acc2[nt], ph, vh[nt]);
                MMA16816(acc2[nt], ph, vl[nt]);
            }
        }
    }

    // ================= ctx epilogue (fp16 hi only) =================
    const int bb = bh / NH, h = bh % NH;
    u32* ch = (u32*)g_chi4;
#pragma unroll
    for (int nt = 0; nt < 2; nt++)
#pragma unroll
        for (int cc = 0; cc < 2; cc++) {
            int r = warpM * 16 + (lane >> 2) + cc * 8;
            int d = warpN * 16 + nt * 8 + (lane & 3) * 2;
            size_t n = (size_t)bb * SEQ + (size_t)(qt * 32 + r);
            size_t idx = n * EMBD + h * 64 + d;
            ch[idx >> 1] = pack_hi(acc2[nt][cc * 2], acc2[nt][cc * 2 + 1]);
        }
}

// =====================================================================
// launch
// =====================================================================
extern "C" void kernel_launch(void* const* d_in, const int* in_sizes, int n_in,
                              void* d_out, int out_size)
{
    const float* hs = (const float*)d_in[0];
    const float* qw = (const float*)d_in[1];
    const float* qb = (const float*)d_in[2];
    const float* kw = (const float*)d_in[3];
    const float* kb = (const float*)d_in[4];
    const float* vw = (const float*)d_in[5];
    const float* vb = (const float*)d_in[6];
    const float* ow = (const float*)d_in[7];
    const float* ob = (const float*)d_in[8];

    float* out  = (float*)d_out;
    float* attn = out + OUT_ELEMS;

    cudaFuncSetAttribute(mm_hmma_kernel, cudaFuncAttributeMaxDynamicSharedMemorySize,
                         MM_SMEM);
    cudaFuncSetAttribute(attn_kernel, cudaFuncAttributeMaxDynamicSharedMemorySize,
                         ATTN_SMEM);

    conv_x_kernel<<<(NT * EMBD / 8 + 255) / 256, 256>>>(hs);
    conv_w_kernel<<<dim3((EMBD * EMBD / 8 + 255) / 256, 4), 256>>>(qw, kw, vw, ow);

    mm_hmma_kernel<<<dim3(EMBD / 128, NT / 128, 3), 256, MM_SMEM>>>(
        qb, kb, vb, ob, out, 0);

    attn_kernel<<<dim3(18, BATCH * NH), 256, ATTN_SMEM>>>(attn);

    mm_hmma_kernel<<<dim3(EMBD / 128, NT / 128, 1), 256, MM_SMEM>>>(
        qb, kb, vb, ob, out, 3);
}

// round 7
// speedup vs baseline: 2.6151x; 1.0640x over previous
#include <cuda_runtime.h>
#include <cuda_fp16.h>

// ---------------- problem constants ----------------
#define BATCH 32
#define SEQ   576
#define EMBD  768
#define NH    12
#define HD    64
#define NT    (BATCH * SEQ)
#define OUT_ELEMS ((size_t)NT * EMBD)
#define ATT_SCALE 0.125f
#define KCHUNKS 24

typedef unsigned int u32;
typedef unsigned short u16;

// ---------------- device scratch ----------------
__device__ uint4 g_xhi4[NT * EMBD / 8];
__device__ uint4 g_xlo4[NT * EMBD / 8];
__device__ uint4 g_whi4[4 * EMBD * EMBD / 8];
__device__ uint4 g_wlo4[4 * EMBD * EMBD / 8];
__device__ uint4 g_chi4[NT * EMBD / 8];          // ctx hi only ([N, EMB], fp16)
__device__ uint4 g_qh4[NT * EMBD / 8];           // [B,H,S,D] fp16 hi/lo
__device__ uint4 g_ql4[NT * EMBD / 8];
__device__ uint4 g_kh4[NT * EMBD / 8];
__device__ uint4 g_kl4[NT * EMBD / 8];
__device__ uint4 g_vh4[NT * EMBD / 8];
__device__ uint4 g_vl4[NT * EMBD / 8];

// ---------------- helpers ----------------
__device__ __forceinline__ u32 smem_u32(const void* p) {
    u32 a;
    asm("{ .reg .u64 t; cvta.to.shared.u64 t, %1; cvt.u32.u64 %0, t; }"
        : "=r"(a) : "l"(p));
    return a;
}

#define CP_ASYNC16(dst, src) \
    asm volatile("cp.async.cg.shared.global [%0], [%1], 16;" \
                 :: "r"(dst), "l"(src) : "memory")
#define CP_COMMIT() asm volatile("cp.async.commit_group;" ::: "memory")
#define CP_WAIT1()  asm volatile("cp.async.wait_group 1;" ::: "memory")
#define CP_WAIT0()  asm volatile("cp.async.wait_group 0;" ::: "memory")

#define LDSM4(r0, r1, r2, r3, addr) \
    asm volatile("ldmatrix.sync.aligned.m8n8.x4.shared.b16 {%0,%1,%2,%3}, [%4];" \
                 : "=r"(r0), "=r"(r1), "=r"(r2), "=r"(r3) : "r"(addr))
#define LDSM4T(r0, r1, r2, r3, addr) \
    asm volatile("ldmatrix.sync.aligned.m8n8.x4.trans.shared.b16 {%0,%1,%2,%3}, [%4];" \
                 : "=r"(r0), "=r"(r1), "=r"(r2), "=r"(r3) : "r"(addr))

#define MMA16816(d, a, b) \
    asm volatile("mma.sync.aligned.m16n8k16.row.col.f32.f16.f16.f32 " \
                 "{%0,%1,%2,%3}, {%4,%5,%6,%7}, {%8,%9}, {%0,%1,%2,%3};" \
                 : "+f"((d)[0]), "+f"((d)[1]), "+f"((d)[2]), "+f"((d)[3]) \
                 : "r"((a)[0]), "r"((a)[1]), "r"((a)[2]), "r"((a)[3]), \
                   "r"((b)[0]), "r"((b)[1]))

#define STS128(addr, a, b, c, d) \
    asm volatile("st.shared.v4.b32 [%0], {%1, %2, %3, %4};" \
                 :: "r"(addr), "r"(a), "r"(b), "r"(c), "r"(d) : "memory")

__device__ __forceinline__ void pack_hilo(float v0, float v1, u32& hp, u32& lp) {
    __half h0 = __float2half_rn(v0);
    __half h1 = __float2half_rn(v1);
    __half l0 = __float2half_rn(v0 - __half2float(h0));
    __half l1 = __float2half_rn(v1 - __half2float(h1));
    hp = (u32)*(u16*)&h0 | ((u32)*(u16*)&h1 << 16);
    lp = (u32)*(u16*)&l0 | ((u32)*(u16*)&l1 << 16);
}
__device__ __forceinline__ u32 pack_hi(float v0, float v1) {
    __half h0 = __float2half_rn(v0);
    __half h1 = __float2half_rn(v1);
    return (u32)*(u16*)&h0 | ((u32)*(u16*)&h1 << 16);
}

// =====================================================================
// hi/lo split conversion (fp16)
// =====================================================================
__device__ __forceinline__ void conv8(const float4* src2, uint4* hi, uint4* lo) {
    float4 a = src2[0], b = src2[1];
    float f[8] = {a.x, a.y, a.z, a.w, b.x, b.y, b.z, b.w};
    union { uint4 v; __half h[8]; } H, L;
#pragma unroll
    for (int j = 0; j < 8; j++) {
        __half hh = __float2half_rn(f[j]);
        H.h[j] = hh;
        L.h[j] = __float2half_rn(f[j] - __half2float(hh));
    }
    *hi = H.v; *lo = L.v;
}

__global__ __launch_bounds__(256) void conv_x_kernel(const float* __restrict__ src) {
    int i = blockIdx.x * blockDim.x + threadIdx.x;
    if (i >= NT * EMBD / 8) return;
    conv8((const float4*)src + 2 * (size_t)i, &g_xhi4[i], &g_xlo4[i]);
}

__global__ __launch_bounds__(256) void conv_w_kernel(
    const float* __restrict__ qw, const float* __restrict__ kw,
    const float* __restrict__ vw, const float* __restrict__ ow) {
    int z = blockIdx.y;
    const float* src = z == 0 ? qw : z == 1 ? kw : z == 2 ? vw : ow;
    int i = blockIdx.x * blockDim.x + threadIdx.x;
    if (i >= EMBD * EMBD / 8) return;
    int di = z * (EMBD * EMBD / 8) + i;
    conv8((const float4*)src + 2 * (size_t)i, &g_whi4[di], &g_wlo4[di]);
}

// =====================================================================
// HMMA split-fp16 GEMM, 3-stage cp.async pipeline, 1 sync per chunk.
// modes 0,1 (Q,K): 3-term. mode 2 (V): 2-term. mode 3 (O): 2-term.
// =====================================================================
#define STAGE_BYTES 32768
#define MM_SMEM (3 * STAGE_BYTES + 512)

__global__ __launch_bounds__(256, 2) void mm_hmma_kernel(
    const float* __restrict__ qb, const float* __restrict__ kb,
    const float* __restrict__ vb, const float* __restrict__ ob,
    float* __restrict__ outp, int mode_base)
{
    extern __shared__ char smraw[];
    const u32 smbase = smem_u32(smraw);
    float* bias_s = (float*)(smraw + 3 * STAGE_BYTES);

    const int t = threadIdx.x, lane = t & 31, wid = t >> 5;
    const int warpM = wid & 3;
    const int warpN = wid >> 2;
    const int mode = mode_base + blockIdx.z;
    const bool need3 = (mode < 2);
    const int o0 = blockIdx.x * 128;
    const int n0 = blockIdx.y * 128;

    const float* bias = mode == 0 ? qb : mode == 1 ? kb : mode == 2 ? vb : ob;
    const uint4* AhiG = (mode < 3) ? g_xhi4 : g_chi4;
    const uint4* AloG = g_xlo4;
    const size_t woff = (size_t)(mode < 3 ? mode : 3) * (EMBD * EMBD / 8);

    if (t < 128) bias_s[t] = bias[o0 + t];

    const int lr   = t >> 1;
    const int half = t & 1;
    const bool loadA = need3 || (half == 0);
    const uint4* srcA = (half ? AloG : AhiG) + (size_t)(n0 + lr) * 96;
    const uint4* srcW = (half ? g_wlo4 : g_whi4) + woff + (size_t)(o0 + lr) * 96;
    const u32 arow_sw[4] = {
        (u32)(lr * 128 + (((half * 4 + 0) ^ (lr & 7)) << 4)),
        (u32)(lr * 128 + (((half * 4 + 1) ^ (lr & 7)) << 4)),
        (u32)(lr * 128 + (((half * 4 + 2) ^ (lr & 7)) << 4)),
        (u32)(lr * 128 + (((half * 4 + 3) ^ (lr & 7)) << 4))
    };

    float acc[2][8][4];
#pragma unroll
    for (int i = 0; i < 2; i++)
#pragma unroll
        for (int j = 0; j < 8; j++)
#pragma unroll
            for (int c = 0; c < 4; c++) acc[i][j][c] = 0.f;

    // prefetch chunks 0 and 1
#pragma unroll
    for (int pc = 0; pc < 2; pc++) {
        const u32 st = smbase + pc * STAGE_BYTES;
        const u32 Ab = st, Wb = st + 16384;
        const int ko = pc * 4;
#pragma unroll
        for (int g = 0; g < 4; g++) {
            if (loadA) CP_ASYNC16(Ab + arow_sw[g], srcA + ko + g);
            CP_ASYNC16(Wb + arow_sw[g], srcW + ko + g);
        }
        CP_COMMIT();
    }

#pragma unroll 1
    for (int kc = 0; kc < KCHUNKS; kc++) {
        if (kc == KCHUNKS - 1) { CP_WAIT0(); } else { CP_WAIT1(); }
        __syncthreads();
        if (kc + 2 < KCHUNKS) {
            int nc = kc + 2;
            const u32 st = smbase + (nc % 3) * STAGE_BYTES;
            const u32 Ab = st, Wb = st + 16384;
            const int ko = nc * 4;
#pragma unroll
            for (int g = 0; g < 4; g++) {
                if (loadA) CP_ASYNC16(Ab + arow_sw[g], srcA + ko + g);
                CP_ASYNC16(Wb + arow_sw[g], srcW + ko + g);
            }
            CP_COMMIT();
        }

        const u32 st = smbase + (kc % 3) * STAGE_BYTES;
        const u32 Ab = st, Wb = st + 16384;

#pragma unroll
        for (int ks = 0; ks < 2; ks++) {
            u32 ah[2][4], al[2][4];
#pragma unroll
            for (int mt = 0; mt < 2; mt++) {
                int row = warpM * 32 + mt * 16 + (lane & 15);
                int c = ks * 2 + ((lane >> 4) & 1);
                u32 base = Ab + row * 128;
                u32 ahi = base + (((c)     ^ (row & 7)) << 4);
                LDSM4(ah[mt][0], ah[mt][1], ah[mt][2], ah[mt][3], ahi);
                if (need3) {
                    u32 alo = base + (((c + 4) ^ (row & 7)) << 4);
                    LDSM4(al[mt][0], al[mt][1], al[mt][2], al[mt][3], alo);
                }
            }
            u32 bh[8][2], bl[8][2];
#pragma unroll
            for (int bt = 0; bt < 4; bt++) {
                int row = warpN * 64 + bt * 16 + (lane & 7) + ((lane >> 4) & 1) * 8;
                int c = ks * 2 + ((lane >> 3) & 1);
                u32 base = Wb + row * 128;
                u32 bhi = base + (((c)     ^ (row & 7)) << 4);
                u32 blo = base + (((c + 4) ^ (row & 7)) << 4);
                u32 r0, r1, r2, r3;
                LDSM4(r0, r1, r2, r3, bhi);
                bh[bt * 2][0] = r0; bh[bt * 2][1] = r1;
                bh[bt * 2 + 1][0] = r2; bh[bt * 2 + 1][1] = r3;
                LDSM4(r0, r1, r2, r3, blo);
                bl[bt * 2][0] = r0; bl[bt * 2][1] = r1;
                bl[bt * 2 + 1][0] = r2; bl[bt * 2 + 1][1] = r3;
            }
#pragma unroll
            for (int mt = 0; mt < 2; mt++)
#pragma unroll
                for (int nt = 0; nt < 8; nt++) {
                    MMA16816(acc[mt][nt], ah[mt], bh[nt]);
                    MMA16816(acc[mt][nt], ah[mt], bl[nt]);
                    if (need3) MMA16816(acc[mt][nt], al[mt], bh[nt]);
                }
        }
    }

    // ---- epilogue ----
    u32* dsth = (u32*)(mode == 0 ? g_qh4 : mode == 1 ? g_kh4 : g_vh4);
    u32* dstl = (u32*)(mode == 0 ? g_ql4 : mode == 1 ? g_kl4 : g_vl4);
    const int h0 = blockIdx.x * 2;
#pragma unroll
    for (int mt = 0; mt < 2; mt++)
#pragma unroll
        for (int nt = 0; nt < 8; nt++)
#pragma unroll
            for (int cc = 0; cc < 2; cc++) {
                int rl = warpM * 32 + mt * 16 + (lane >> 2) + cc * 8;
                int cl = warpN * 64 + nt * 8 + (lane & 3) * 2;
                float v0 = acc[mt][nt][cc * 2 + 0] + bias_s[cl];
                float v1 = acc[mt][nt][cc * 2 + 1] + bias_s[cl + 1];
                int n = n0 + rl;
                if (mode < 3) {
                    int bb = n / SEQ, ss = n - bb * SEQ;
                    int h = h0 + (cl >> 6), d = cl & 63;
                    size_t idx = ((((size_t)bb * NH + h) * SEQ + ss) * HD + d);
                    u32 hp, lp; pack_hilo(v0, v1, hp, lp);
                    dsth[idx >> 1] = hp;
                    dstl[idx >> 1] = lp;
                } else {
                    float2* p = (float2*)(outp + (size_t)n * EMBD + o0 + cl);
                    *p = make_float2(v0, v1);
                }
            }
}

// =====================================================================
// HMMA attention, 32-row q tiles, 2 CTAs/SM, double-buffered K/V tiles.
// smem: slab | stage0(16K) | stage1(16K) | PH(4K) | inv
// =====================================================================
#define SLAB_W 578
#define SC_B   0
#define ST0_B  (32 * SLAB_W * 4)           // 73,984
#define ST1_B  (ST0_B + 16384)             // 90,368
#define PH_B   (ST1_B + 16384)             // 106,752
#define INV_B  (PH_B + 4096)               // 110,848
#define ATTN_SMEM (INV_B + 128)            // 110,976

__device__ __forceinline__ void load_tile64_async(
    u32 dsth, u32 dstl,
    const uint4* __restrict__ srch, const uint4* __restrict__ srcl,
    int tokbase, int t)
{
#pragma unroll
    for (int it = 0; it < 2; it++) {
        int idx = t + it * 256;
        int r = idx >> 3, c = idx & 7;
        u32 off = (u32)(r * 128 + ((c ^ (r & 7)) << 4));
        CP_ASYNC16(dsth + off, srch + (size_t)(tokbase + r) * 8 + c);
        CP_ASYNC16(dstl + off, srcl + (size_t)(tokbase + r) * 8 + c);
    }
    CP_COMMIT();
}

__global__ __launch_bounds__(256, 2) void attn_kernel(float* __restrict__ attn_out)
{
    extern __shared__ char smc[];
    const u32 smb = smem_u32(smc);
    float* sc = (float*)smc;
    float* inv_s = (float*)(smc + INV_B);

    const int t = threadIdx.x, lane = t & 31, wid = t >> 5;
    const int warpM = wid & 1;
    const int warpN = wid >> 1;
    const int qt = blockIdx.x;
    const int bh = blockIdx.y;
    const int qtok = bh * SEQ + qt * 32;
    const int ktok0 = bh * SEQ;

    // ---- load Q (32 x 64 hi/lo) into stage0 area, hoist fragments ----
    {
        int r = t >> 3, c = t & 7;
        uint4 a = g_qh4[(size_t)(qtok + r) * 8 + c];
        uint4 b = g_ql4[(size_t)(qtok + r) * 8 + c];
        u32 off = (u32)(r * 128 + ((c ^ (r & 7)) << 4));
        STS128(smb + ST0_B + off, a.x, a.y, a.z, a.w);
        STS128(smb + ST0_B + 4096 + off, b.x, b.y, b.z, b.w);
    }
    __syncthreads();

    u32 qh[4][4], ql[4][4];
#pragma unroll
    for (int ks = 0; ks < 4; ks++) {
        int row = warpM * 16 + (lane & 15);
        int c = ks * 2 + ((lane >> 4) & 1);
        u32 sw = (u32)(row * 128 + ((c ^ (row & 7)) << 4));
        LDSM4(qh[ks][0], qh[ks][1], qh[ks][2], qh[ks][3], smb + ST0_B + sw);
        LDSM4(ql[ks][0], ql[ks][1], ql[ks][2], ql[ks][3], smb + ST0_B + 4096 + sw);
    }

    // preload K tile 0 into stage1 (doesn't touch Q area)
    load_tile64_async(smb + ST1_B, smb + ST1_B + 8192, g_kh4, g_kl4, ktok0, t);

    // ================= scores (buf(kt) = stage (kt+1)&1) =================
#pragma unroll 1
    for (int kt = 0; kt < 9; kt++) {
        CP_WAIT0();
        __syncthreads();   // K(kt) visible to all; all warps done with buf being refilled
        if (kt < 9 - 1) {
            u32 nb = smb + (((kt + 1 + 1) & 1) ? ST1_B : ST0_B);
            load_tile64_async(nb, nb + 8192, g_kh4, g_kl4, ktok0 + (kt + 1) * 64, t);
        }
        const u32 kb = smb + (((kt + 1) & 1) ? ST1_B : ST0_B);
        const u32 klb = kb + 8192;

        float acc[2][4];
#pragma unroll
        for (int i = 0; i < 2; i++)
#pragma unroll
            for (int j = 0; j < 4; j++) acc[i][j] = 0.f;

#pragma unroll
        for (int ks = 0; ks < 4; ks++) {
            u32 bh2[2][2], bl2[2][2];
            {
                int row = warpN * 16 + (lane & 7) + ((lane >> 4) & 1) * 8;
                int c = ks * 2 + ((lane >> 3) & 1);
                u32 sw = (u32)(row * 128 + ((c ^ (row & 7)) << 4));
                u32 r0, r1, r2, r3;
                LDSM4(r0, r1, r2, r3, kb + sw);
                bh2[0][0] = r0; bh2[0][1] = r1;
                bh2[1][0] = r2; bh2[1][1] = r3;
                LDSM4(r0, r1, r2, r3, klb + sw);
                bl2[0][0] = r0; bl2[0][1] = r1;
                bl2[1][0] = r2; bl2[1][1] = r3;
            }
#pragma unroll
            for (int nt = 0; nt < 2; nt++) {
                MMA16816(acc[nt], qh[ks], bh2[nt]);
                MMA16816(acc[nt], qh[ks], bl2[nt]);
                MMA16816(acc[nt], ql[ks], bh2[nt]);
            }
        }
#pragma unroll
        for (int nt = 0; nt < 2; nt++)
#pragma unroll
            for (int cc = 0; cc < 2; cc++) {
                int r = warpM * 16 + (lane >> 2) + cc * 8;
                int col = kt * 64 + warpN * 16 + nt * 8 + (lane & 3) * 2;
                float2* p = (float2*)(sc + r * SLAB_W + col);
                *p = make_float2(acc[nt][cc * 2] * ATT_SCALE,
                                 acc[nt][cc * 2 + 1] * ATT_SCALE);
            }
    }
    __syncthreads();   // slab complete; all warps past last K mma

    // preload V tile 0 into stage0 (K7's old buffer, now safe) — overlaps softmax
    load_tile64_async(smb + ST0_B, smb + ST0_B + 8192, g_vh4, g_vl4, ktok0, t);

    // ================= softmax: exp in slab + 1/sum =================
    {
        for (int rr = 0; rr < 4; rr++) {
            int r = wid * 4 + rr;
            float* row = sc + r * SLAB_W;
            float m = -1e30f;
            for (int c = lane; c < SEQ; c += 32) m = fmaxf(m, row[c]);
#pragma unroll
            for (int off = 16; off > 0; off >>= 1)
                m = fmaxf(m, __shfl_xor_sync(0xffffffffu, m, off));
            float s = 0.f;
            for (int c = lane; c < SEQ; c += 32) {
                float e = __expf(row[c] - m);
                row[c] = e;
                s += e;
            }
#pragma unroll
            for (int off = 16; off > 0; off >>= 1)
                s += __shfl_xor_sync(0xffffffffu, s, off);
            if (lane == 0) inv_s[r] = 1.f / s;
        }
    }

    // ================= P @ V (buf(kt) = stage kt&1) =================
    float acc2[2][4];
#pragma unroll
    for (int i = 0; i < 2; i++)
#pragma unroll
        for (int j = 0; j < 4; j++) acc2[i][j] = 0.f;

#pragma unroll 1
    for (int kt = 0; kt < 9; kt++) {
        CP_WAIT0();
        __syncthreads();   // V(kt) visible; all warps done with PH(kt-1) + refill buf
        if (kt < 9 - 1) {
            u32 nb = smb + (((kt + 1) & 1) ? ST1_B : ST0_B);
            load_tile64_async(nb, nb + 8192, g_vh4, g_vl4, ktok0 + (kt + 1) * 64, t);
        }
        // normalize P chunk, write attn to gmem, pack fp16 hi into PH tile
#pragma unroll
        for (int i = 0; i < 4; i++) {
            int r = wid * 4 + i;
            float inv = inv_s[r];
            float2 e = *(const float2*)(sc + r * SLAB_W + kt * 64 + lane * 2);
            float p0 = e.x * inv, p1 = e.y * inv;
            size_t arow = ((size_t)bh * SEQ + (size_t)(qt * 32 + r)) * SEQ;
            *(float2*)(attn_out + arow + kt * 64 + lane * 2) = make_float2(p0, p1);
            u32 off = (u32)(r * 128 + (((lane >> 2) ^ (r & 7)) << 4) + (lane & 3) * 4);
            *(u32*)(smc + PH_B + off) = pack_hi(p0, p1);
        }
        __syncthreads();   // PH visible

        const u32 vb2 = smb + ((kt & 1) ? ST1_B : ST0_B);
        const u32 vlb = vb2 + 8192;

#pragma unroll
        for (int ks = 0; ks < 4; ks++) {
            u32 ph[4];
            {
                int row = warpM * 16 + (lane & 15);
                int c = ks * 2 + ((lane >> 4) & 1);
                u32 sw = (u32)(row * 128 + ((c ^ (row & 7)) << 4));
                LDSM4(ph[0], ph[1], ph[2], ph[3], smb + PH_B + sw);
            }
            u32 vh[2][2], vl[2][2];
            {
                int m = lane >> 3;
                int row_s = ks * 16 + ((m & 1) << 3) + (lane & 7);
                int chunk = warpN * 2 + (m >> 1);
                u32 sw = (u32)(row_s * 128 + ((chunk ^ (row_s & 7)) << 4));
                u32 r0, r1, r2, r3;
                LDSM4T(r0, r1, r2, r3, vb2 + sw);
                vh[0][0] = r0; vh[0][1] = r1;
                vh[1][0] = r2; vh[1][1] = r3;
                LDSM4T(r0, r1, r2, r3, vlb + sw);
                vl[0][0] = r0; vl[0][1] = r1;
                vl[1][0] = r2; vl[1][1] = r3;
            }
#pragma unroll
            for (int nt = 0; nt < 2; nt++) {
                MMA16816(acc2[nt], ph, vh[nt]);
                MMA16816(acc2[nt], ph, vl[nt]);
            }
        }
    }

    // ================= ctx epilogue (fp16 hi only) =================
    const int bb = bh / NH, h = bh % NH;
    u32* ch = (u32*)g_chi4;
#pragma unroll
    for (int nt = 0; nt < 2; nt++)
#pragma unroll
        for (int cc = 0; cc < 2; cc++) {
            int r = warpM * 16 + (lane >> 2) + cc * 8;
            int d = warpN * 16 + nt * 8 + (lane & 3) * 2;
            size_t n = (size_t)bb * SEQ + (size_t)(qt * 32 + r);
            size_t idx = n * EMBD + h * 64 + d;
            ch[idx >> 1] = pack_hi(acc2[nt][cc * 2], acc2[nt][cc * 2 + 1]);
        }
}

// =====================================================================
// launch
// =====================================================================
extern "C" void kernel_launch(void* const* d_in, const int* in_sizes, int n_in,
                              void* d_out, int out_size)
{
    const float* hs = (const float*)d_in[0];
    const float* qw = (const float*)d_in[1];
    const float* qb = (const float*)d_in[2];
    const float* kw = (const float*)d_in[3];
    const float* kb = (const float*)d_in[4];
    const float* vw = (const float*)d_in[5];
    const float* vb = (const float*)d_in[6];
    const float* ow = (const float*)d_in[7];
    const float* ob = (const float*)d_in[8];

    float* out  = (float*)d_out;
    float* attn = out + OUT_ELEMS;

    cudaFuncSetAttribute(mm_hmma_kernel, cudaFuncAttributeMaxDynamicSharedMemorySize,
                         MM_SMEM);
    cudaFuncSetAttribute(attn_kernel, cudaFuncAttributeMaxDynamicSharedMemorySize,
                         ATTN_SMEM);

    conv_x_kernel<<<(NT * EMBD / 8 + 255) / 256, 256>>>(hs);
    conv_w_kernel<<<dim3((EMBD * EMBD / 8 + 255) / 256, 4), 256>>>(qw, kw, vw, ow);

    mm_hmma_kernel<<<dim3(EMBD / 128, NT / 128, 3), 256, MM_SMEM>>>(
        qb, kb, vb, ob, out, 0);

    attn_kernel<<<dim3(18, BATCH * NH), 256, ATTN_SMEM>>>(attn);

    mm_hmma_kernel<<<dim3(EMBD / 128, NT / 128, 1), 256, MM_SMEM>>>(
        qb, kb, vb, ob, out, 3);
}

// round 8
// speedup vs baseline: 2.6801x; 1.0248x over previous
#include <cuda_runtime.h>
#include <cuda_fp16.h>

// ---------------- problem constants ----------------
#define BATCH 32
#define SEQ   576
#define EMBD  768
#define NH    12
#define HD    64
#define NT    (BATCH * SEQ)
#define OUT_ELEMS ((size_t)NT * EMBD)
#define ATT_SCALE 0.125f
#define KCHUNKS 24

typedef unsigned int u32;
typedef unsigned short u16;

// ---------------- device scratch ----------------
__device__ uint4 g_xhi4[NT * EMBD / 8];
__device__ uint4 g_xlo4[NT * EMBD / 8];
__device__ uint4 g_whi4[4 * EMBD * EMBD / 8];
__device__ uint4 g_wlo4[4 * EMBD * EMBD / 8];
__device__ uint4 g_chi4[NT * EMBD / 8];          // ctx hi only ([N, EMB], fp16)
__device__ uint4 g_qh4[NT * EMBD / 8];           // [B,H,S,D] fp16 hi/lo
__device__ uint4 g_ql4[NT * EMBD / 8];
__device__ uint4 g_kh4[NT * EMBD / 8];
__device__ uint4 g_kl4[NT * EMBD / 8];
__device__ uint4 g_vh4[NT * EMBD / 8];           // V hi only

// ---------------- helpers ----------------
__device__ __forceinline__ u32 smem_u32(const void* p) {
    u32 a;
    asm("{ .reg .u64 t; cvta.to.shared.u64 t, %1; cvt.u32.u64 %0, t; }"
        : "=r"(a) : "l"(p));
    return a;
}

#define CP_ASYNC16(dst, src) \
    asm volatile("cp.async.cg.shared.global [%0], [%1], 16;" \
                 :: "r"(dst), "l"(src) : "memory")
#define CP_COMMIT() asm volatile("cp.async.commit_group;" ::: "memory")
#define CP_WAIT1()  asm volatile("cp.async.wait_group 1;" ::: "memory")
#define CP_WAIT0()  asm volatile("cp.async.wait_group 0;" ::: "memory")

#define LDSM4(r0, r1, r2, r3, addr) \
    asm volatile("ldmatrix.sync.aligned.m8n8.x4.shared.b16 {%0,%1,%2,%3}, [%4];" \
                 : "=r"(r0), "=r"(r1), "=r"(r2), "=r"(r3) : "r"(addr))
#define LDSM4T(r0, r1, r2, r3, addr) \
    asm volatile("ldmatrix.sync.aligned.m8n8.x4.trans.shared.b16 {%0,%1,%2,%3}, [%4];" \
                 : "=r"(r0), "=r"(r1), "=r"(r2), "=r"(r3) : "r"(addr))

#define MMA16816(d, a, b) \
    asm volatile("mma.sync.aligned.m16n8k16.row.col.f32.f16.f16.f32 " \
                 "{%0,%1,%2,%3}, {%4,%5,%6,%7}, {%8,%9}, {%0,%1,%2,%3};" \
                 : "+f"((d)[0]), "+f"((d)[1]), "+f"((d)[2]), "+f"((d)[3]) \
                 : "r"((a)[0]), "r"((a)[1]), "r"((a)[2]), "r"((a)[3]), \
                   "r"((b)[0]), "r"((b)[1]))

#define STS128(addr, a, b, c, d) \
    asm volatile("st.shared.v4.b32 [%0], {%1, %2, %3, %4};" \
                 :: "r"(addr), "r"(a), "r"(b), "r"(c), "r"(d) : "memory")

__device__ __forceinline__ void pack_hilo(float v0, float v1, u32& hp, u32& lp) {
    __half h0 = __float2half_rn(v0);
    __half h1 = __float2half_rn(v1);
    __half l0 = __float2half_rn(v0 - __half2float(h0));
    __half l1 = __float2half_rn(v1 - __half2float(h1));
    hp = (u32)*(u16*)&h0 | ((u32)*(u16*)&h1 << 16);
    lp = (u32)*(u16*)&l0 | ((u32)*(u16*)&l1 << 16);
}
__device__ __forceinline__ u32 pack_hi(float v0, float v1) {
    __half h0 = __float2half_rn(v0);
    __half h1 = __float2half_rn(v1);
    return (u32)*(u16*)&h0 | ((u32)*(u16*)&h1 << 16);
}

// =====================================================================
// hi/lo split conversion (fp16)
// =====================================================================
__device__ __forceinline__ void conv8(const float4* src2, uint4* hi, uint4* lo) {
    float4 a = src2[0], b = src2[1];
    float f[8] = {a.x, a.y, a.z, a.w, b.x, b.y, b.z, b.w};
    union { uint4 v; __half h[8]; } H, L;
#pragma unroll
    for (int j = 0; j < 8; j++) {
        __half hh = __float2half_rn(f[j]);
        H.h[j] = hh;
        L.h[j] = __float2half_rn(f[j] - __half2float(hh));
    }
    *hi = H.v; *lo = L.v;
}

__global__ __launch_bounds__(256) void conv_x_kernel(const float* __restrict__ src) {
    int i = blockIdx.x * blockDim.x + threadIdx.x;
    if (i >= NT * EMBD / 8) return;
    conv8((const float4*)src + 2 * (size_t)i, &g_xhi4[i], &g_xlo4[i]);
}

__global__ __launch_bounds__(256) void conv_w_kernel(
    const float* __restrict__ qw, const float* __restrict__ kw,
    const float* __restrict__ vw, const float* __restrict__ ow) {
    int z = blockIdx.y;
    const float* src = z == 0 ? qw : z == 1 ? kw : z == 2 ? vw : ow;
    int i = blockIdx.x * blockDim.x + threadIdx.x;
    if (i >= EMBD * EMBD / 8) return;
    int di = z * (EMBD * EMBD / 8) + i;
    conv8((const float4*)src + 2 * (size_t)i, &g_whi4[di], &g_wlo4[di]);
}

// =====================================================================
// HMMA split-fp16 GEMM, 3-stage cp.async pipeline, 1 sync per chunk.
// modes 0,1 (Q,K): 3-term. mode 2 (V): 2-term, stores hi only.
// mode 3 (O): 2-term, fp32 out.
// =====================================================================
#define STAGE_BYTES 32768
#define MM_SMEM (3 * STAGE_BYTES + 512)

__global__ __launch_bounds__(256, 2) void mm_hmma_kernel(
    const float* __restrict__ qb, const float* __restrict__ kb,
    const float* __restrict__ vb, const float* __restrict__ ob,
    float* __restrict__ outp, int mode_base)
{
    extern __shared__ char smraw[];
    const u32 smbase = smem_u32(smraw);
    float* bias_s = (float*)(smraw + 3 * STAGE_BYTES);

    const int t = threadIdx.x, lane = t & 31, wid = t >> 5;
    const int warpM = wid & 3;
    const int warpN = wid >> 2;
    const int mode = mode_base + blockIdx.z;
    const bool need3 = (mode < 2);
    const int o0 = blockIdx.x * 128;
    const int n0 = blockIdx.y * 128;

    const float* bias = mode == 0 ? qb : mode == 1 ? kb : mode == 2 ? vb : ob;
    const uint4* AhiG = (mode < 3) ? g_xhi4 : g_chi4;
    const uint4* AloG = g_xlo4;
    const size_t woff = (size_t)(mode < 3 ? mode : 3) * (EMBD * EMBD / 8);

    if (t < 128) bias_s[t] = bias[o0 + t];

    const int lr   = t >> 1;
    const int half = t & 1;
    const bool loadA = need3 || (half == 0);
    const uint4* srcA = (half ? AloG : AhiG) + (size_t)(n0 + lr) * 96;
    const uint4* srcW = (half ? g_wlo4 : g_whi4) + woff + (size_t)(o0 + lr) * 96;
    const u32 arow_sw[4] = {
        (u32)(lr * 128 + (((half * 4 + 0) ^ (lr & 7)) << 4)),
        (u32)(lr * 128 + (((half * 4 + 1) ^ (lr & 7)) << 4)),
        (u32)(lr * 128 + (((half * 4 + 2) ^ (lr & 7)) << 4)),
        (u32)(lr * 128 + (((half * 4 + 3) ^ (lr & 7)) << 4))
    };

    float acc[2][8][4];
#pragma unroll
    for (int i = 0; i < 2; i++)
#pragma unroll
        for (int j = 0; j < 8; j++)
#pragma unroll
            for (int c = 0; c < 4; c++) acc[i][j][c] = 0.f;

    // prefetch chunks 0 and 1
#pragma unroll
    for (int pc = 0; pc < 2; pc++) {
        const u32 st = smbase + pc * STAGE_BYTES;
        const u32 Ab = st, Wb = st + 16384;
        const int ko = pc * 4;
#pragma unroll
        for (int g = 0; g < 4; g++) {
            if (loadA) CP_ASYNC16(Ab + arow_sw[g], srcA + ko + g);
            CP_ASYNC16(Wb + arow_sw[g], srcW + ko + g);
        }
        CP_COMMIT();
    }

#pragma unroll 1
    for (int kc = 0; kc < KCHUNKS; kc++) {
        if (kc == KCHUNKS - 1) { CP_WAIT0(); } else { CP_WAIT1(); }
        __syncthreads();
        if (kc + 2 < KCHUNKS) {
            int nc = kc + 2;
            const u32 st = smbase + (nc % 3) * STAGE_BYTES;
            const u32 Ab = st, Wb = st + 16384;
            const int ko = nc * 4;
#pragma unroll
            for (int g = 0; g < 4; g++) {
                if (loadA) CP_ASYNC16(Ab + arow_sw[g], srcA + ko + g);
                CP_ASYNC16(Wb + arow_sw[g], srcW + ko + g);
            }
            CP_COMMIT();
        }

        const u32 st = smbase + (kc % 3) * STAGE_BYTES;
        const u32 Ab = st, Wb = st + 16384;

#pragma unroll
        for (int ks = 0; ks < 2; ks++) {
            u32 ah[2][4], al[2][4];
#pragma unroll
            for (int mt = 0; mt < 2; mt++) {
                int row = warpM * 32 + mt * 16 + (lane & 15);
                int c = ks * 2 + ((lane >> 4) & 1);
                u32 base = Ab + row * 128;
                u32 ahi = base + (((c)     ^ (row & 7)) << 4);
                LDSM4(ah[mt][0], ah[mt][1], ah[mt][2], ah[mt][3], ahi);
                if (need3) {
                    u32 alo = base + (((c + 4) ^ (row & 7)) << 4);
                    LDSM4(al[mt][0], al[mt][1], al[mt][2], al[mt][3], alo);
                }
            }
            u32 bh[8][2], bl[8][2];
#pragma unroll
            for (int bt = 0; bt < 4; bt++) {
                int row = warpN * 64 + bt * 16 + (lane & 7) + ((lane >> 4) & 1) * 8;
                int c = ks * 2 + ((lane >> 3) & 1);
                u32 base = Wb + row * 128;
                u32 bhi = base + (((c)     ^ (row & 7)) << 4);
                u32 blo = base + (((c + 4) ^ (row & 7)) << 4);
                u32 r0, r1, r2, r3;
                LDSM4(r0, r1, r2, r3, bhi);
                bh[bt * 2][0] = r0; bh[bt * 2][1] = r1;
                bh[bt * 2 + 1][0] = r2; bh[bt * 2 + 1][1] = r3;
                LDSM4(r0, r1, r2, r3, blo);
                bl[bt * 2][0] = r0; bl[bt * 2][1] = r1;
                bl[bt * 2 + 1][0] = r2; bl[bt * 2 + 1][1] = r3;
            }
#pragma unroll
            for (int mt = 0; mt < 2; mt++)
#pragma unroll
                for (int nt = 0; nt < 8; nt++) {
                    MMA16816(acc[mt][nt], ah[mt], bh[nt]);
                    MMA16816(acc[mt][nt], ah[mt], bl[nt]);
                    if (need3) MMA16816(acc[mt][nt], al[mt], bh[nt]);
                }
        }
    }

    // ---- epilogue ----
    u32* dsth = (u32*)(mode == 0 ? g_qh4 : mode == 1 ? g_kh4 : g_vh4);
    u32* dstl = (u32*)(mode == 0 ? g_ql4 : g_kl4);   // unused for mode 2
    const int h0 = blockIdx.x * 2;
#pragma unroll
    for (int mt = 0; mt < 2; mt++)
#pragma unroll
        for (int nt = 0; nt < 8; nt++)
#pragma unroll
            for (int cc = 0; cc < 2; cc++) {
                int rl = warpM * 32 + mt * 16 + (lane >> 2) + cc * 8;
                int cl = warpN * 64 + nt * 8 + (lane & 3) * 2;
                float v0 = acc[mt][nt][cc * 2 + 0] + bias_s[cl];
                float v1 = acc[mt][nt][cc * 2 + 1] + bias_s[cl + 1];
                int n = n0 + rl;
                if (mode < 3) {
                    int bb = n / SEQ, ss = n - bb * SEQ;
                    int h = h0 + (cl >> 6), d = cl & 63;
                    size_t idx = ((((size_t)bb * NH + h) * SEQ + ss) * HD + d);
                    u32 hp, lp; pack_hilo(v0, v1, hp, lp);
                    dsth[idx >> 1] = hp;
                    if (mode != 2) dstl[idx >> 1] = lp;
                } else {
                    float2* p = (float2*)(outp + (size_t)n * EMBD + o0 + cl);
                    *p = make_float2(v0, v1);
                }
            }
}

// =====================================================================
// HMMA attention, 32-row q tiles, 2 CTAs/SM, double-buffered K/V tiles.
// scores: 3-term (Q hi/lo x K hi/lo). P·V: P hi x V hi (single).
// smem: slab | stage0(16K) | stage1(16K) | PH(4K) | inv
// =====================================================================
#define SLAB_W 578
#define SC_B   0
#define ST0_B  (32 * SLAB_W * 4)           // 73,984
#define ST1_B  (ST0_B + 16384)             // 90,368
#define PH_B   (ST1_B + 16384)             // 106,752
#define INV_B  (PH_B + 4096)               // 110,848
#define ATTN_SMEM (INV_B + 128)            // 110,976

__device__ __forceinline__ void load_tile64_async(
    u32 dsth, u32 dstl,
    const uint4* __restrict__ srch, const uint4* __restrict__ srcl,
    int tokbase, int t)
{
#pragma unroll
    for (int it = 0; it < 2; it++) {
        int idx = t + it * 256;
        int r = idx >> 3, c = idx & 7;
        u32 off = (u32)(r * 128 + ((c ^ (r & 7)) << 4));
        CP_ASYNC16(dsth + off, srch + (size_t)(tokbase + r) * 8 + c);
        CP_ASYNC16(dstl + off, srcl + (size_t)(tokbase + r) * 8 + c);
    }
    CP_COMMIT();
}

// hi-only tile load (V): 64 rows x 64 dims fp16 = 8 KB
__device__ __forceinline__ void load_v_async(
    u32 dsth, const uint4* __restrict__ srch, int tokbase, int t)
{
#pragma unroll
    for (int it = 0; it < 2; it++) {
        int idx = t + it * 256;
        int r = idx >> 3, c = idx & 7;
        u32 off = (u32)(r * 128 + ((c ^ (r & 7)) << 4));
        CP_ASYNC16(dsth + off, srch + (size_t)(tokbase + r) * 8 + c);
    }
    CP_COMMIT();
}

__global__ __launch_bounds__(256, 2) void attn_kernel(float* __restrict__ attn_out)
{
    extern __shared__ char smc[];
    const u32 smb = smem_u32(smc);
    float* sc = (float*)smc;
    float* inv_s = (float*)(smc + INV_B);

    const int t = threadIdx.x, lane = t & 31, wid = t >> 5;
    const int warpM = wid & 1;
    const int warpN = wid >> 1;
    const int qt = blockIdx.x;
    const int bh = blockIdx.y;
    const int qtok = bh * SEQ + qt * 32;
    const int ktok0 = bh * SEQ;

    // ---- load Q (32 x 64 hi/lo) into stage0 area, hoist fragments ----
    {
        int r = t >> 3, c = t & 7;
        uint4 a = g_qh4[(size_t)(qtok + r) * 8 + c];
        uint4 b = g_ql4[(size_t)(qtok + r) * 8 + c];
        u32 off = (u32)(r * 128 + ((c ^ (r & 7)) << 4));
        STS128(smb + ST0_B + off, a.x, a.y, a.z, a.w);
        STS128(smb + ST0_B + 4096 + off, b.x, b.y, b.z, b.w);
    }
    __syncthreads();

    u32 qh[4][4], ql[4][4];
#pragma unroll
    for (int ks = 0; ks < 4; ks++) {
        int row = warpM * 16 + (lane & 15);
        int c = ks * 2 + ((lane >> 4) & 1);
        u32 sw = (u32)(row * 128 + ((c ^ (row & 7)) << 4));
        LDSM4(qh[ks][0], qh[ks][1], qh[ks][2], qh[ks][3], smb + ST0_B + sw);
        LDSM4(ql[ks][0], ql[ks][1], ql[ks][2], ql[ks][3], smb + ST0_B + 4096 + sw);
    }

    // preload K tile 0 into stage1 (doesn't touch Q area)
    load_tile64_async(smb + ST1_B, smb + ST1_B + 8192, g_kh4, g_kl4, ktok0, t);

    // ================= scores (buf(kt) = stage (kt+1)&1) =================
#pragma unroll 1
    for (int kt = 0; kt < 9; kt++) {
        CP_WAIT0();
        __syncthreads();
        if (kt < 9 - 1) {
            u32 nb = smb + (((kt + 1 + 1) & 1) ? ST1_B : ST0_B);
            load_tile64_async(nb, nb + 8192, g_kh4, g_kl4, ktok0 + (kt + 1) * 64, t);
        }
        const u32 kb = smb + (((kt + 1) & 1) ? ST1_B : ST0_B);
        const u32 klb = kb + 8192;

        float acc[2][4];
#pragma unroll
        for (int i = 0; i < 2; i++)
#pragma unroll
            for (int j = 0; j < 4; j++) acc[i][j] = 0.f;

#pragma unroll
        for (int ks = 0; ks < 4; ks++) {
            u32 bh2[2][2], bl2[2][2];
            {
                int row = warpN * 16 + (lane & 7) + ((lane >> 4) & 1) * 8;
                int c = ks * 2 + ((lane >> 3) & 1);
                u32 sw = (u32)(row * 128 + ((c ^ (row & 7)) << 4));
                u32 r0, r1, r2, r3;
                LDSM4(r0, r1, r2, r3, kb + sw);
                bh2[0][0] = r0; bh2[0][1] = r1;
                bh2[1][0] = r2; bh2[1][1] = r3;
                LDSM4(r0, r1, r2, r3, klb + sw);
                bl2[0][0] = r0; bl2[0][1] = r1;
                bl2[1][0] = r2; bl2[1][1] = r3;
            }
#pragma unroll
            for (int nt = 0; nt < 2; nt++) {
                MMA16816(acc[nt], qh[ks], bh2[nt]);
                MMA16816(acc[nt], qh[ks], bl2[nt]);
                MMA16816(acc[nt], ql[ks], bh2[nt]);
            }
        }
#pragma unroll
        for (int nt = 0; nt < 2; nt++)
#pragma unroll
            for (int cc = 0; cc < 2; cc++) {
                int r = warpM * 16 + (lane >> 2) + cc * 8;
                int col = kt * 64 + warpN * 16 + nt * 8 + (lane & 3) * 2;
                float2* p = (float2*)(sc + r * SLAB_W + col);
                *p = make_float2(acc[nt][cc * 2] * ATT_SCALE,
                                 acc[nt][cc * 2 + 1] * ATT_SCALE);
            }
    }
    __syncthreads();   // slab complete; all warps past last K mma

    // preload V tile 0 (hi only) into stage0 — overlaps softmax
    load_v_async(smb + ST0_B, g_vh4, ktok0, t);

    // ================= softmax: exp in slab + 1/sum =================
    {
        for (int rr = 0; rr < 4; rr++) {
            int r = wid * 4 + rr;
            float* row = sc + r * SLAB_W;
            float m = -1e30f;
            for (int c = lane; c < SEQ; c += 32) m = fmaxf(m, row[c]);
#pragma unroll
            for (int off = 16; off > 0; off >>= 1)
                m = fmaxf(m, __shfl_xor_sync(0xffffffffu, m, off));
            float s = 0.f;
            for (int c = lane; c < SEQ; c += 32) {
                float e = __expf(row[c] - m);
                row[c] = e;
                s += e;
            }
#pragma unroll
            for (int off = 16; off > 0; off >>= 1)
                s += __shfl_xor_sync(0xffffffffu, s, off);
            if (lane == 0) inv_s[r] = 1.f / s;
        }
    }

    // ================= P @ V (buf(kt) = stage kt&1; V hi only) ==========
    float acc2[2][4];
#pragma unroll
    for (int i = 0; i < 2; i++)
#pragma unroll
        for (int j = 0; j < 4; j++) acc2[i][j] = 0.f;

#pragma unroll 1
    for (int kt = 0; kt < 9; kt++) {
        CP_WAIT0();
        __syncthreads();   // V(kt) visible; all warps done with PH(kt-1) + refill buf
        if (kt < 9 - 1) {
            u32 nb = smb + (((kt + 1) & 1) ? ST1_B : ST0_B);
            load_v_async(nb, g_vh4, ktok0 + (kt + 1) * 64, t);
        }
        // normalize P chunk, write attn to gmem, pack fp16 hi into PH tile
#pragma unroll
        for (int i = 0; i < 4; i++) {
            int r = wid * 4 + i;
            float inv = inv_s[r];
            float2 e = *(const float2*)(sc + r * SLAB_W + kt * 64 + lane * 2);
            float p0 = e.x * inv, p1 = e.y * inv;
            size_t arow = ((size_t)bh * SEQ + (size_t)(qt * 32 + r)) * SEQ;
            *(float2*)(attn_out + arow + kt * 64 + lane * 2) = make_float2(p0, p1);
            u32 off = (u32)(r * 128 + (((lane >> 2) ^ (r & 7)) << 4) + (lane & 3) * 4);
            *(u32*)(smc + PH_B + off) = pack_hi(p0, p1);
        }
        __syncthreads();   // PH visible

        const u32 vb2 = smb + ((kt & 1) ? ST1_B : ST0_B);

#pragma unroll
        for (int ks = 0; ks < 4; ks++) {
            u32 ph[4];
            {
                int row = warpM * 16 + (lane & 15);
                int c = ks * 2 + ((lane >> 4) & 1);
                u32 sw = (u32)(row * 128 + ((c ^ (row & 7)) << 4));
                LDSM4(ph[0], ph[1], ph[2], ph[3], smb + PH_B + sw);
            }
            u32 vh[2][2];
            {
                int m = lane >> 3;
                int row_s = ks * 16 + ((m & 1) << 3) + (lane & 7);
                int chunk = warpN * 2 + (m >> 1);
                u32 sw = (u32)(row_s * 128 + ((chunk ^ (row_s & 7)) << 4));
                u32 r0, r1, r2, r3;
                LDSM4T(r0, r1, r2, r3, vb2 + sw);
                vh[0][0] = r0; vh[0][1] = r1;
                vh[1][0] = r2; vh[1][1] = r3;
            }
#pragma unroll
            for (int nt = 0; nt < 2; nt++) {
                MMA16816(acc2[nt], ph, vh[nt]);
            }
        }
    }

    // ================= ctx epilogue (fp16 hi only) =================
    const int bb = bh / NH, h = bh % NH;
    u32* ch = (u32*)g_chi4;
#pragma unroll
    for (int nt = 0; nt < 2; nt++)
#pragma unroll
        for (int cc = 0; cc < 2; cc++) {
            int r = warpM * 16 + (lane >> 2) + cc * 8;
            int d = warpN * 16 + nt * 8 + (lane & 3) * 2;
            size_t n = (size_t)bb * SEQ + (size_t)(qt * 32 + r);
            size_t idx = n * EMBD + h * 64 + d;
            ch[idx >> 1] = pack_hi(acc2[nt][cc * 2], acc2[nt][cc * 2 + 1]);
        }
}

// =====================================================================
// launch
// =====================================================================
extern "C" void kernel_launch(void* const* d_in, const int* in_sizes, int n_in,
                              void* d_out, int out_size)
{
    const float* hs = (const float*)d_in[0];
    const float* qw = (const float*)d_in[1];
    const float* qb = (const float*)d_in[2];
    const float* kw = (const float*)d_in[3];
    const float* kb = (const float*)d_in[4];
    const float* vw = (const float*)d_in[5];
    const float* vb = (const float*)d_in[6];
    const float* ow = (const float*)d_in[7];
    const float* ob = (const float*)d_in[8];

    float* out  = (float*)d_out;
    float* attn = out + OUT_ELEMS;

    cudaFuncSetAttribute(mm_hmma_kernel, cudaFuncAttributeMaxDynamicSharedMemorySize,
                         MM_SMEM);
    cudaFuncSetAttribute(attn_kernel, cudaFuncAttributeMaxDynamicSharedMemorySize,
                         ATTN_SMEM);

    conv_x_kernel<<<(NT * EMBD / 8 + 255) / 256, 256>>>(hs);
    conv_w_kernel<<<dim3((EMBD * EMBD / 8 + 255) / 256, 4), 256>>>(qw, kw, vw, ow);

    mm_hmma_kernel<<<dim3(EMBD / 128, NT / 128, 3), 256, MM_SMEM>>>(
        qb, kb, vb, ob, out, 0);

    attn_kernel<<<dim3(18, BATCH * NH), 256, ATTN_SMEM>>>(attn);

    mm_hmma_kernel<<<dim3(EMBD / 128, NT / 128, 1), 256, MM_SMEM>>>(
        qb, kb, vb, ob, out, 3);
}

// round 9
// speedup vs baseline: 2.7638x; 1.0312x over previous
#include <cuda_runtime.h>
#include <cuda_fp16.h>

// ---------------- problem constants ----------------
#define BATCH 32
#define SEQ   576
#define EMBD  768
#define NH    12
#define HD    64
#define NT    (BATCH * SEQ)
#define OUT_ELEMS ((size_t)NT * EMBD)
#define ATT_SCALE 0.125f
#define KCHUNKS 24

typedef unsigned int u32;
typedef unsigned short u16;

// ---------------- device scratch ----------------
__device__ uint4 g_xhi4[NT * EMBD / 8];
__device__ uint4 g_xlo4[NT * EMBD / 8];
__device__ uint4 g_whi4[4 * EMBD * EMBD / 8];
__device__ uint4 g_wlo4[4 * EMBD * EMBD / 8];
__device__ uint4 g_chi4[NT * EMBD / 8];          // ctx hi only ([N, EMB], fp16)
__device__ uint4 g_qh4[NT * EMBD / 8];           // [B,H,S,D] fp16 hi/lo
__device__ uint4 g_ql4[NT * EMBD / 8];
__device__ uint4 g_kh4[NT * EMBD / 8];
__device__ uint4 g_kl4[NT * EMBD / 8];
__device__ uint4 g_vh4[NT * EMBD / 8];           // V hi only

// ---------------- helpers ----------------
__device__ __forceinline__ u32 smem_u32(const void* p) {
    u32 a;
    asm("{ .reg .u64 t; cvta.to.shared.u64 t, %1; cvt.u32.u64 %0, t; }"
        : "=r"(a) : "l"(p));
    return a;
}

#define CP_ASYNC16(dst, src) \
    asm volatile("cp.async.cg.shared.global [%0], [%1], 16;" \
                 :: "r"(dst), "l"(src) : "memory")
#define CP_COMMIT() asm volatile("cp.async.commit_group;" ::: "memory")
#define CP_WAIT1()  asm volatile("cp.async.wait_group 1;" ::: "memory")
#define CP_WAIT0()  asm volatile("cp.async.wait_group 0;" ::: "memory")

#define LDSM4(r0, r1, r2, r3, addr) \
    asm volatile("ldmatrix.sync.aligned.m8n8.x4.shared.b16 {%0,%1,%2,%3}, [%4];" \
                 : "=r"(r0), "=r"(r1), "=r"(r2), "=r"(r3) : "r"(addr))
#define LDSM4T(r0, r1, r2, r3, addr) \
    asm volatile("ldmatrix.sync.aligned.m8n8.x4.trans.shared.b16 {%0,%1,%2,%3}, [%4];" \
                 : "=r"(r0), "=r"(r1), "=r"(r2), "=r"(r3) : "r"(addr))

#define MMA16816(d, a, b) \
    asm volatile("mma.sync.aligned.m16n8k16.row.col.f32.f16.f16.f32 " \
                 "{%0,%1,%2,%3}, {%4,%5,%6,%7}, {%8,%9}, {%0,%1,%2,%3};" \
                 : "+f"((d)[0]), "+f"((d)[1]), "+f"((d)[2]), "+f"((d)[3]) \
                 : "r"((a)[0]), "r"((a)[1]), "r"((a)[2]), "r"((a)[3]), \
                   "r"((b)[0]), "r"((b)[1]))

#define STS128(addr, a, b, c, d) \
    asm volatile("st.shared.v4.b32 [%0], {%1, %2, %3, %4};" \
                 :: "r"(addr), "r"(a), "r"(b), "r"(c), "r"(d) : "memory")

__device__ __forceinline__ void pack_hilo(float v0, float v1, u32& hp, u32& lp) {
    __half h0 = __float2half_rn(v0);
    __half h1 = __float2half_rn(v1);
    __half l0 = __float2half_rn(v0 - __half2float(h0));
    __half l1 = __float2half_rn(v1 - __half2float(h1));
    hp = (u32)*(u16*)&h0 | ((u32)*(u16*)&h1 << 16);
    lp = (u32)*(u16*)&l0 | ((u32)*(u16*)&l1 << 16);
}
__device__ __forceinline__ u32 pack_hi(float v0, float v1) {
    __half h0 = __float2half_rn(v0);
    __half h1 = __float2half_rn(v1);
    return (u32)*(u16*)&h0 | ((u32)*(u16*)&h1 << 16);
}

// =====================================================================
// hi/lo split conversion (fp16)
// =====================================================================
__device__ __forceinline__ void conv8(const float4* src2, uint4* hi, uint4* lo) {
    float4 a = src2[0], b = src2[1];
    float f[8] = {a.x, a.y, a.z, a.w, b.x, b.y, b.z, b.w};
    union { uint4 v; __half h[8]; } H, L;
#pragma unroll
    for (int j = 0; j < 8; j++) {
        __half hh = __float2half_rn(f[j]);
        H.h[j] = hh;
        L.h[j] = __float2half_rn(f[j] - __half2float(hh));
    }
    *hi = H.v; *lo = L.v;
}

__global__ __launch_bounds__(256) void conv_x_kernel(const float* __restrict__ src) {
    int i = blockIdx.x * blockDim.x + threadIdx.x;
    if (i >= NT * EMBD / 8) return;
    conv8((const float4*)src + 2 * (size_t)i, &g_xhi4[i], &g_xlo4[i]);
}

__global__ __launch_bounds__(256) void conv_w_kernel(
    const float* __restrict__ qw, const float* __restrict__ kw,
    const float* __restrict__ vw, const float* __restrict__ ow) {
    int z = blockIdx.y;
    const float* src = z == 0 ? qw : z == 1 ? kw : z == 2 ? vw : ow;
    int i = blockIdx.x * blockDim.x + threadIdx.x;
    if (i >= EMBD * EMBD / 8) return;
    int di = z * (EMBD * EMBD / 8) + i;
    conv8((const float4*)src + 2 * (size_t)i, &g_whi4[di], &g_wlo4[di]);
}

// =====================================================================
// HMMA split-fp16 GEMM, CTA tile 128x64, 3-stage pipeline.
// modes 0,1 (Q,K): 3-term. mode 2 (V): 2-term, hi only. mode 3 (O): 2-term.
// warps: 4 along M (32 rows), 2 along N (32 cols).
// =====================================================================
#define STAGE_BYTES 24576            // A 16K + W 8K
#define MM_SMEM (3 * STAGE_BYTES + 512)

__global__ __launch_bounds__(256, 2) void mm_hmma_kernel(
    const float* __restrict__ qb, const float* __restrict__ kb,
    const float* __restrict__ vb, const float* __restrict__ ob,
    float* __restrict__ outp, int mode_base)
{
    extern __shared__ char smraw[];
    const u32 smbase = smem_u32(smraw);
    float* bias_s = (float*)(smraw + 3 * STAGE_BYTES);

    const int t = threadIdx.x, lane = t & 31, wid = t >> 5;
    const int warpM = wid & 3;          // 32 rows
    const int warpN = wid >> 2;         // 32 cols
    const int mode = mode_base + blockIdx.z;
    const bool need3 = (mode < 2);
    const int o0 = blockIdx.x * 64;
    const int n0 = blockIdx.y * 128;

    const float* bias = mode == 0 ? qb : mode == 1 ? kb : mode == 2 ? vb : ob;
    const uint4* AhiG = (mode < 3) ? g_xhi4 : g_chi4;
    const uint4* AloG = g_xlo4;
    const size_t woff = (size_t)(mode < 3 ? mode : 3) * (EMBD * EMBD / 8);

    if (t < 64) bias_s[t] = bias[o0 + t];

    // ---- A loader: 128 rows x 2 halves, 4 chunks each (t>>1 = row, t&1 = half)
    const int lr   = t >> 1;
    const int half = t & 1;
    const bool loadA = need3 || (half == 0);
    const uint4* srcA = (half ? AloG : AhiG) + (size_t)(n0 + lr) * 96;
    const u32 arow_sw[4] = {
        (u32)(lr * 128 + (((half * 4 + 0) ^ (lr & 7)) << 4)),
        (u32)(lr * 128 + (((half * 4 + 1) ^ (lr & 7)) << 4)),
        (u32)(lr * 128 + (((half * 4 + 2) ^ (lr & 7)) << 4)),
        (u32)(lr * 128 + (((half * 4 + 3) ^ (lr & 7)) << 4))
    };
    // ---- W loader: 64 rows x 8 (half,g) units = 512 uint4, 2 per thread
    u32 wdst[2];
    const uint4* srcW[2];
#pragma unroll
    for (int j = 0; j < 2; j++) {
        int idx = t + j * 256;
        int row = idx >> 3, rem = idx & 7;
        int wh = rem >> 2, g = rem & 3;
        wdst[j] = (u32)(row * 128 + (((wh * 4 + g) ^ (row & 7)) << 4));
        srcW[j] = (wh ? g_wlo4 : g_whi4) + woff + (size_t)(o0 + row) * 96 + g;
    }

    float acc[2][4][4];
#pragma unroll
    for (int i = 0; i < 2; i++)
#pragma unroll
        for (int j = 0; j < 4; j++)
#pragma unroll
            for (int c = 0; c < 4; c++) acc[i][j][c] = 0.f;

    // prefetch chunks 0 and 1
#pragma unroll
    for (int pc = 0; pc < 2; pc++) {
        const u32 st = smbase + pc * STAGE_BYTES;
        const int ko = pc * 4;
#pragma unroll
        for (int g = 0; g < 4; g++)
            if (loadA) CP_ASYNC16(st + arow_sw[g], srcA + ko + g);
#pragma unroll
        for (int j = 0; j < 2; j++)
            CP_ASYNC16(st + 16384 + wdst[j], srcW[j] + ko);
        CP_COMMIT();
    }

#pragma unroll 1
    for (int kc = 0; kc < KCHUNKS; kc++) {
        if (kc == KCHUNKS - 1) { CP_WAIT0(); } else { CP_WAIT1(); }
        __syncthreads();
        if (kc + 2 < KCHUNKS) {
            int nc = kc + 2;
            const u32 st = smbase + (nc % 3) * STAGE_BYTES;
            const int ko = nc * 4;
#pragma unroll
            for (int g = 0; g < 4; g++)
                if (loadA) CP_ASYNC16(st + arow_sw[g], srcA + ko + g);
#pragma unroll
            for (int j = 0; j < 2; j++)
                CP_ASYNC16(st + 16384 + wdst[j], srcW[j] + ko);
            CP_COMMIT();
        }

        const u32 Ab = smbase + (kc % 3) * STAGE_BYTES;
        const u32 Wb = Ab + 16384;

#pragma unroll
        for (int ks = 0; ks < 2; ks++) {
            u32 ah[2][4], al[2][4];
#pragma unroll
            for (int mt = 0; mt < 2; mt++) {
                int row = warpM * 32 + mt * 16 + (lane & 15);
                int c = ks * 2 + ((lane >> 4) & 1);
                u32 base = Ab + row * 128;
                LDSM4(ah[mt][0], ah[mt][1], ah[mt][2], ah[mt][3],
                      base + (((c) ^ (row & 7)) << 4));
                if (need3)
                    LDSM4(al[mt][0], al[mt][1], al[mt][2], al[mt][3],
                          base + (((c + 4) ^ (row & 7)) << 4));
            }
            u32 bh[4][2], bl[4][2];
#pragma unroll
            for (int bt = 0; bt < 2; bt++) {
                int row = warpN * 32 + bt * 16 + (lane & 7) + ((lane >> 4) & 1) * 8;
                int c = ks * 2 + ((lane >> 3) & 1);
                u32 base = Wb + row * 128;
                u32 r0, r1, r2, r3;
                LDSM4(r0, r1, r2, r3, base + (((c) ^ (row & 7)) << 4));
                bh[bt * 2][0] = r0; bh[bt * 2][1] = r1;
                bh[bt * 2 + 1][0] = r2; bh[bt * 2 + 1][1] = r3;
                LDSM4(r0, r1, r2, r3, base + (((c + 4) ^ (row & 7)) << 4));
                bl[bt * 2][0] = r0; bl[bt * 2][1] = r1;
                bl[bt * 2 + 1][0] = r2; bl[bt * 2 + 1][1] = r3;
            }
#pragma unroll
            for (int mt = 0; mt < 2; mt++)
#pragma unroll
                for (int nt = 0; nt < 4; nt++) {
                    MMA16816(acc[mt][nt], ah[mt], bh[nt]);
                    MMA16816(acc[mt][nt], ah[mt], bl[nt]);
                    if (need3) MMA16816(acc[mt][nt], al[mt], bh[nt]);
                }
        }
    }

    // ---- epilogue (64 cols = exactly one head for modes<3) ----
    u32* dsth = (u32*)(mode == 0 ? g_qh4 : mode == 1 ? g_kh4 : g_vh4);
    u32* dstl = (u32*)(mode == 0 ? g_ql4 : g_kl4);   // unused for mode 2
    const int h = blockIdx.x;
#pragma unroll
    for (int mt = 0; mt < 2; mt++)
#pragma unroll
        for (int nt = 0; nt < 4; nt++)
#pragma unroll
            for (int cc = 0; cc < 2; cc++) {
                int rl = warpM * 32 + mt * 16 + (lane >> 2) + cc * 8;
                int cl = warpN * 32 + nt * 8 + (lane & 3) * 2;
                float v0 = acc[mt][nt][cc * 2 + 0] + bias_s[cl];
                float v1 = acc[mt][nt][cc * 2 + 1] + bias_s[cl + 1];
                int n = n0 + rl;
                if (mode < 3) {
                    int bb = n / SEQ, ss = n - bb * SEQ;
                    size_t idx = ((((size_t)bb * NH + h) * SEQ + ss) * HD + cl);
                    u32 hp, lp; pack_hilo(v0, v1, hp, lp);
                    dsth[idx >> 1] = hp;
                    if (mode != 2) dstl[idx >> 1] = lp;
                } else {
                    float2* p = (float2*)(outp + (size_t)n * EMBD + o0 + cl);
                    *p = make_float2(v0, v1);
                }
            }
}

// =====================================================================
// HMMA attention, 32-row q tiles, 2 CTAs/SM, double-buffered K/V tiles.
// Row max fused into score phase; softmax is a single slab pass.
// =====================================================================
#define SLAB_W 578
#define SC_B   0
#define ST0_B  (32 * SLAB_W * 4)           // 73,984
#define ST1_B  (ST0_B + 16384)             // 90,368
#define PH_B   (ST1_B + 16384)             // 106,752
#define INV_B  (PH_B + 4096)               // 110,848
#define MAXP_B (INV_B + 128)               // 110,976
#define ATTN_SMEM (MAXP_B + 512)           // 111,488

__device__ __forceinline__ void load_tile64_async(
    u32 dsth, u32 dstl,
    const uint4* __restrict__ srch, const uint4* __restrict__ srcl,
    int tokbase, int t)
{
#pragma unroll
    for (int it = 0; it < 2; it++) {
        int idx = t + it * 256;
        int r = idx >> 3, c = idx & 7;
        u32 off = (u32)(r * 128 + ((c ^ (r & 7)) << 4));
        CP_ASYNC16(dsth + off, srch + (size_t)(tokbase + r) * 8 + c);
        CP_ASYNC16(dstl + off, srcl + (size_t)(tokbase + r) * 8 + c);
    }
    CP_COMMIT();
}

__device__ __forceinline__ void load_v_async(
    u32 dsth, const uint4* __restrict__ srch, int tokbase, int t)
{
#pragma unroll
    for (int it = 0; it < 2; it++) {
        int idx = t + it * 256;
        int r = idx >> 3, c = idx & 7;
        u32 off = (u32)(r * 128 + ((c ^ (r & 7)) << 4));
        CP_ASYNC16(dsth + off, srch + (size_t)(tokbase + r) * 8 + c);
    }
    CP_COMMIT();
}

__global__ __launch_bounds__(256, 2) void attn_kernel(float* __restrict__ attn_out)
{
    extern __shared__ char smc[];
    const u32 smb = smem_u32(smc);
    float* sc = (float*)smc;
    float* inv_s = (float*)(smc + INV_B);
    float* maxp  = (float*)(smc + MAXP_B);   // [4 warpN][32 rows]

    const int t = threadIdx.x, lane = t & 31, wid = t >> 5;
    const int warpM = wid & 1;
    const int warpN = wid >> 1;
    const int qt = blockIdx.x;
    const int bh = blockIdx.y;
    const int qtok = bh * SEQ + qt * 32;
    const int ktok0 = bh * SEQ;

    // ---- load Q (32 x 64 hi/lo) into stage0 area, hoist fragments ----
    {
        int r = t >> 3, c = t & 7;
        uint4 a = g_qh4[(size_t)(qtok + r) * 8 + c];
        uint4 b = g_ql4[(size_t)(qtok + r) * 8 + c];
        u32 off = (u32)(r * 128 + ((c ^ (r & 7)) << 4));
        STS128(smb + ST0_B + off, a.x, a.y, a.z, a.w);
        STS128(smb + ST0_B + 4096 + off, b.x, b.y, b.z, b.w);
    }
    __syncthreads();

    u32 qh[4][4], ql[4][4];
#pragma unroll
    for (int ks = 0; ks < 4; ks++) {
        int row = warpM * 16 + (lane & 15);
        int c = ks * 2 + ((lane >> 4) & 1);
        u32 sw = (u32)(row * 128 + ((c ^ (row & 7)) << 4));
        LDSM4(qh[ks][0], qh[ks][1], qh[ks][2], qh[ks][3], smb + ST0_B + sw);
        LDSM4(ql[ks][0], ql[ks][1], ql[ks][2], ql[ks][3], smb + ST0_B + 4096 + sw);
    }

    // preload K tile 0 into stage1
    load_tile64_async(smb + ST1_B, smb + ST1_B + 8192, g_kh4, g_kl4, ktok0, t);

    float fm[2] = {-1e30f, -1e30f};    // per-thread raw row max (cc = 0, 1)

    // ================= scores =================
#pragma unroll 1
    for (int kt = 0; kt < 9; kt++) {
        CP_WAIT0();
        __syncthreads();
        if (kt < 9 - 1) {
            u32 nb = smb + (((kt + 1 + 1) & 1) ? ST1_B : ST0_B);
            load_tile64_async(nb, nb + 8192, g_kh4, g_kl4, ktok0 + (kt + 1) * 64, t);
        }
        const u32 kb = smb + (((kt + 1) & 1) ? ST1_B : ST0_B);
        const u32 klb = kb + 8192;

        float acc[2][4];
#pragma unroll
        for (int i = 0; i < 2; i++)
#pragma unroll
            for (int j = 0; j < 4; j++) acc[i][j] = 0.f;

#pragma unroll
        for (int ks = 0; ks < 4; ks++) {
            u32 bh2[2][2], bl2[2][2];
            {
                int row = warpN * 16 + (lane & 7) + ((lane >> 4) & 1) * 8;
                int c = ks * 2 + ((lane >> 3) & 1);
                u32 sw = (u32)(row * 128 + ((c ^ (row & 7)) << 4));
                u32 r0, r1, r2, r3;
                LDSM4(r0, r1, r2, r3, kb + sw);
                bh2[0][0] = r0; bh2[0][1] = r1;
                bh2[1][0] = r2; bh2[1][1] = r3;
                LDSM4(r0, r1, r2, r3, klb + sw);
                bl2[0][0] = r0; bl2[0][1] = r1;
                bl2[1][0] = r2; bl2[1][1] = r3;
            }
#pragma unroll
            for (int nt = 0; nt < 2; nt++) {
                MMA16816(acc[nt], qh[ks], bh2[nt]);
                MMA16816(acc[nt], qh[ks], bl2[nt]);
                MMA16816(acc[nt], ql[ks], bh2[nt]);
            }
        }
#pragma unroll
        for (int nt = 0; nt < 2; nt++)
#pragma unroll
            for (int cc = 0; cc < 2; cc++) {
                fm[cc] = fmaxf(fm[cc], fmaxf(acc[nt][cc * 2], acc[nt][cc * 2 + 1]));
                int r = warpM * 16 + (lane >> 2) + cc * 8;
                int col = kt * 64 + warpN * 16 + nt * 8 + (lane & 3) * 2;
                float2* p = (float2*)(sc + r * SLAB_W + col);
                *p = make_float2(acc[nt][cc * 2] * ATT_SCALE,
                                 acc[nt][cc * 2 + 1] * ATT_SCALE);
            }
    }
    // reduce fragment max over lane quad, publish per-warpN partials
#pragma unroll
    for (int cc = 0; cc < 2; cc++) {
        fm[cc] = fmaxf(fm[cc], __shfl_xor_sync(0xffffffffu, fm[cc], 1));
        fm[cc] = fmaxf(fm[cc], __shfl_xor_sync(0xffffffffu, fm[cc], 2));
        if ((lane & 3) == 0) {
            int r = warpM * 16 + (lane >> 2) + cc * 8;
            maxp[warpN * 32 + r] = fm[cc];
        }
    }
    __syncthreads();   // slab + maxp complete

    // preload V tile 0 (hi only) into stage0 — overlaps softmax
    load_v_async(smb + ST0_B, g_vh4, ktok0, t);

    // ================= softmax: single pass (max precomputed) ==========
    {
        for (int rr = 0; rr < 4; rr++) {
            int r = wid * 4 + rr;
            float m = fmaxf(fmaxf(maxp[r], maxp[32 + r]),
                            fmaxf(maxp[64 + r], maxp[96 + r])) * ATT_SCALE;
            float* row = sc + r * SLAB_W;
            float s = 0.f;
            for (int c = lane; c < SEQ; c += 32) {
                float e = __expf(row[c] - m);
                row[c] = e;
                s += e;
            }
#pragma unroll
            for (int off = 16; off > 0; off >>= 1)
                s += __shfl_xor_sync(0xffffffffu, s, off);
            if (lane == 0) inv_s[r] = 1.f / s;
        }
    }

    // ================= P @ V (V hi only) =================
    float acc2[2][4];
#pragma unroll
    for (int i = 0; i < 2; i++)
#pragma unroll
        for (int j = 0; j < 4; j++) acc2[i][j] = 0.f;

#pragma unroll 1
    for (int kt = 0; kt < 9; kt++) {
        CP_WAIT0();
        __syncthreads();
        if (kt < 9 - 1) {
            u32 nb = smb + (((kt + 1) & 1) ? ST1_B : ST0_B);
            load_v_async(nb, g_vh4, ktok0 + (kt + 1) * 64, t);
        }
#pragma unroll
        for (int i = 0; i < 4; i++) {
            int r = wid * 4 + i;
            float inv = inv_s[r];
            float2 e = *(const float2*)(sc + r * SLAB_W + kt * 64 + lane * 2);
            float p0 = e.x * inv, p1 = e.y * inv;
            size_t arow = ((size_t)bh * SEQ + (size_t)(qt * 32 + r)) * SEQ;
            *(float2*)(attn_out + arow + kt * 64 + lane * 2) = make_float2(p0, p1);
            u32 off = (u32)(r * 128 + (((lane >> 2) ^ (r & 7)) << 4) + (lane & 3) * 4);
            *(u32*)(smc + PH_B + off) = pack_hi(p0, p1);
        }
        __syncthreads();

        const u32 vb2 = smb + ((kt & 1) ? ST1_B : ST0_B);

#pragma unroll
        for (int ks = 0; ks < 4; ks++) {
            u32 ph[4];
            {
                int row = warpM * 16 + (lane & 15);
                int c = ks * 2 + ((lane >> 4) & 1);
                u32 sw = (u32)(row * 128 + ((c ^ (row & 7)) << 4));
                LDSM4(ph[0], ph[1], ph[2], ph[3], smb + PH_B + sw);
            }
            u32 vh[2][2];
            {
                int m = lane >> 3;
                int row_s = ks * 16 + ((m & 1) << 3) + (lane & 7);
                int chunk = warpN * 2 + (m >> 1);
                u32 sw = (u32)(row_s * 128 + ((chunk ^ (row_s & 7)) << 4));
                u32 r0, r1, r2, r3;
                LDSM4T(r0, r1, r2, r3, vb2 + sw);
                vh[0][0] = r0; vh[0][1] = r1;
                vh[1][0] = r2; vh[1][1] = r3;
            }
#pragma unroll
            for (int nt = 0; nt < 2; nt++) {
                MMA16816(acc2[nt], ph, vh[nt]);
            }
        }
    }

    // ================= ctx epilogue (fp16 hi only) =================
    const int bb = bh / NH, h = bh % NH;
    u32* ch = (u32*)g_chi4;
#pragma unroll
    for (int nt = 0; nt < 2; nt++)
#pragma unroll
        for (int cc = 0; cc < 2; cc++) {
            int r = warpM * 16 + (lane >> 2) + cc * 8;
            int d = warpN * 16 + nt * 8 + (lane & 3) * 2;
            size_t n = (size_t)bb * SEQ + (size_t)(qt * 32 + r);
            size_t idx = n * EMBD + h * 64 + d;
            ch[idx >> 1] = pack_hi(acc2[nt][cc * 2], acc2[nt][cc * 2 + 1]);
        }
}

// =====================================================================
// launch
// =====================================================================
extern "C" void kernel_launch(void* const* d_in, const int* in_sizes, int n_in,
                              void* d_out, int out_size)
{
    const float* hs = (const float*)d_in[0];
    const float* qw = (const float*)d_in[1];
    const float* qb = (const float*)d_in[2];
    const float* kw = (const float*)d_in[3];
    const float* kb = (const float*)d_in[4];
    const float* vw = (const float*)d_in[5];
    const float* vb = (const float*)d_in[6];
    const float* ow = (const float*)d_in[7];
    const float* ob = (const float*)d_in[8];

    float* out  = (float*)d_out;
    float* attn = out + OUT_ELEMS;

    cudaFuncSetAttribute(mm_hmma_kernel, cudaFuncAttributeMaxDynamicSharedMemorySize,
                         MM_SMEM);
    cudaFuncSetAttribute(attn_kernel, cudaFuncAttributeMaxDynamicSharedMemorySize,
                         ATTN_SMEM);

    conv_x_kernel<<<(NT * EMBD / 8 + 255) / 256, 256>>>(hs);
    conv_w_kernel<<<dim3((EMBD * EMBD / 8 + 255) / 256, 4), 256>>>(qw, kw, vw, ow);

    mm_hmma_kernel<<<dim3(EMBD / 64, NT / 128, 3), 256, MM_SMEM>>>(
        qb, kb, vb, ob, out, 0);

    attn_kernel<<<dim3(18, BATCH * NH), 256, ATTN_SMEM>>>(attn);

    mm_hmma_kernel<<<dim3(EMBD / 64, NT / 128, 1), 256, MM_SMEM>>>(
        qb, kb, vb, ob, out, 3);
}

// round 10
// speedup vs baseline: 2.9169x; 1.0554x over previous
#include <cuda_runtime.h>
#include <cuda_fp16.h>

// ---------------- problem constants ----------------
#define BATCH 32
#define SEQ   576
#define EMBD  768
#define NH    12
#define HD    64
#define NT    (BATCH * SEQ)
#define OUT_ELEMS ((size_t)NT * EMBD)
#define ATT_SCALE 0.125f
#define KCHUNKS 24

typedef unsigned int u32;
typedef unsigned short u16;

// ---------------- device scratch ----------------
__device__ uint4 g_xhi4[NT * EMBD / 8];
__device__ uint4 g_xlo4[NT * EMBD / 8];
__device__ uint4 g_whi4[4 * EMBD * EMBD / 8];
__device__ uint4 g_wlo4[4 * EMBD * EMBD / 8];
__device__ uint4 g_chi4[NT * EMBD / 8];          // ctx hi only ([N, EMB], fp16)
__device__ uint4 g_qh4[NT * EMBD / 8];           // [B,H,S,D] fp16 hi/lo
__device__ uint4 g_ql4[NT * EMBD / 8];
__device__ uint4 g_kh4[NT * EMBD / 8];
__device__ uint4 g_kl4[NT * EMBD / 8];
__device__ uint4 g_vh4[NT * EMBD / 8];           // V hi only

// ---------------- helpers ----------------
__device__ __forceinline__ u32 smem_u32(const void* p) {
    u32 a;
    asm("{ .reg .u64 t; cvta.to.shared.u64 t, %1; cvt.u32.u64 %0, t; }"
        : "=r"(a) : "l"(p));
    return a;
}

#define CP_ASYNC16(dst, src) \
    asm volatile("cp.async.cg.shared.global [%0], [%1], 16;" \
                 :: "r"(dst), "l"(src) : "memory")
#define CP_COMMIT() asm volatile("cp.async.commit_group;" ::: "memory")
#define CP_WAIT1()  asm volatile("cp.async.wait_group 1;" ::: "memory")
#define CP_WAIT0()  asm volatile("cp.async.wait_group 0;" ::: "memory")

#define LDSM4(r0, r1, r2, r3, addr) \
    asm volatile("ldmatrix.sync.aligned.m8n8.x4.shared.b16 {%0,%1,%2,%3}, [%4];" \
                 : "=r"(r0), "=r"(r1), "=r"(r2), "=r"(r3) : "r"(addr))
#define LDSM4T(r0, r1, r2, r3, addr) \
    asm volatile("ldmatrix.sync.aligned.m8n8.x4.trans.shared.b16 {%0,%1,%2,%3}, [%4];" \
                 : "=r"(r0), "=r"(r1), "=r"(r2), "=r"(r3) : "r"(addr))

#define MMA16816(d, a, b) \
    asm volatile("mma.sync.aligned.m16n8k16.row.col.f32.f16.f16.f32 " \
                 "{%0,%1,%2,%3}, {%4,%5,%6,%7}, {%8,%9}, {%0,%1,%2,%3};" \
                 : "+f"((d)[0]), "+f"((d)[1]), "+f"((d)[2]), "+f"((d)[3]) \
                 : "r"((a)[0]), "r"((a)[1]), "r"((a)[2]), "r"((a)[3]), \
                   "r"((b)[0]), "r"((b)[1]))

#define STS128(addr, a, b, c, d) \
    asm volatile("st.shared.v4.b32 [%0], {%1, %2, %3, %4};" \
                 :: "r"(addr), "r"(a), "r"(b), "r"(c), "r"(d) : "memory")

__device__ __forceinline__ void pack_hilo(float v0, float v1, u32& hp, u32& lp) {
    __half h0 = __float2half_rn(v0);
    __half h1 = __float2half_rn(v1);
    __half l0 = __float2half_rn(v0 - __half2float(h0));
    __half l1 = __float2half_rn(v1 - __half2float(h1));
    hp = (u32)*(u16*)&h0 | ((u32)*(u16*)&h1 << 16);
    lp = (u32)*(u16*)&l0 | ((u32)*(u16*)&l1 << 16);
}
__device__ __forceinline__ u32 pack_hi(float v0, float v1) {
    __half h0 = __float2half_rn(v0);
    __half h1 = __float2half_rn(v1);
    return (u32)*(u16*)&h0 | ((u32)*(u16*)&h1 << 16);
}

// =====================================================================
// hi/lo split conversion (fp16)
// =====================================================================
__device__ __forceinline__ void conv8(const float4* src2, uint4* hi, uint4* lo) {
    float4 a = src2[0], b = src2[1];
    float f[8] = {a.x, a.y, a.z, a.w, b.x, b.y, b.z, b.w};
    union { uint4 v; __half h[8]; } H, L;
#pragma unroll
    for (int j = 0; j < 8; j++) {
        __half hh = __float2half_rn(f[j]);
        H.h[j] = hh;
        L.h[j] = __float2half_rn(f[j] - __half2float(hh));
    }
    *hi = H.v; *lo = L.v;
}

__global__ __launch_bounds__(256) void conv_x_kernel(const float* __restrict__ src) {
    int i = blockIdx.x * blockDim.x + threadIdx.x;
    if (i >= NT * EMBD / 8) return;
    conv8((const float4*)src + 2 * (size_t)i, &g_xhi4[i], &g_xlo4[i]);
}

__global__ __launch_bounds__(256) void conv_w_kernel(
    const float* __restrict__ qw, const float* __restrict__ kw,
    const float* __restrict__ vw, const float* __restrict__ ow) {
    int z = blockIdx.y;
    const float* src = z == 0 ? qw : z == 1 ? kw : z == 2 ? vw : ow;
    int i = blockIdx.x * blockDim.x + threadIdx.x;
    if (i >= EMBD * EMBD / 8) return;
    int di = z * (EMBD * EMBD / 8) + i;
    conv8((const float4*)src + 2 * (size_t)i, &g_whi4[di], &g_wlo4[di]);
}

// =====================================================================
// Fused Q+K projection: one CTA computes BOTH 128x64 output tiles,
// sharing the A (X hi/lo) tile and fragments. 3-term each.
// Stage: A 16K | Wq 8K | Wk 8K = 32KB. 3 stages.
// =====================================================================
#define QK_STAGE 32768
#define QK_SMEM (3 * QK_STAGE + 1024)

__global__ __launch_bounds__(256, 2) void qk_fused_kernel(
    const float* __restrict__ qb, const float* __restrict__ kb)
{
    extern __shared__ char smraw[];
    const u32 smbase = smem_u32(smraw);
    float* bias_s = (float*)(smraw + 3 * QK_STAGE);   // [2][64]

    const int t = threadIdx.x, lane = t & 31, wid = t >> 5;
    const int warpM = wid & 3;          // 32 rows
    const int warpN = wid >> 2;         // 32 cols
    const int o0 = blockIdx.x * 64;
    const int n0 = blockIdx.y * 128;

    if (t < 64) bias_s[t] = qb[o0 + t];
    else if (t < 128) bias_s[t] = kb[o0 + t - 64];

    // ---- A loader: 1024 uint4 per chunk, 4 per thread ----
    const int lr   = t >> 1;
    const int half = t & 1;
    const uint4* srcA = (half ? g_xlo4 : g_xhi4) + (size_t)(n0 + lr) * 96;
    const u32 arow_sw[4] = {
        (u32)(lr * 128 + (((half * 4 + 0) ^ (lr & 7)) << 4)),
        (u32)(lr * 128 + (((half * 4 + 1) ^ (lr & 7)) << 4)),
        (u32)(lr * 128 + (((half * 4 + 2) ^ (lr & 7)) << 4)),
        (u32)(lr * 128 + (((half * 4 + 3) ^ (lr & 7)) << 4))
    };
    // ---- W loader: 2 modes x 512 uint4 = 1024 per chunk, 4 per thread ----
    u32 wdst[4];
    const uint4* srcW[4];
#pragma unroll
    for (int j = 0; j < 4; j++) {
        int idx = t + j * 256;
        int mw = idx >> 9;              // 0 = Q weights, 1 = K weights
        int within = idx & 511;
        int row = within >> 3, rem = within & 7;
        int wh = rem >> 2, g = rem & 3;
        wdst[j] = (u32)(16384 + mw * 8192 + row * 128 + (((wh * 4 + g) ^ (row & 7)) << 4));
        srcW[j] = (wh ? g_wlo4 : g_whi4) + (size_t)mw * (EMBD * EMBD / 8)
                  + (size_t)(o0 + row) * 96 + g;
    }

    float accQ[2][4][4], accK[2][4][4];
#pragma unroll
    for (int i = 0; i < 2; i++)
#pragma unroll
        for (int j = 0; j < 4; j++)
#pragma unroll
            for (int c = 0; c < 4; c++) { accQ[i][j][c] = 0.f; accK[i][j][c] = 0.f; }

    // prefetch chunks 0 and 1
#pragma unroll
    for (int pc = 0; pc < 2; pc++) {
        const u32 st = smbase + pc * QK_STAGE;
        const int ko = pc * 4;
#pragma unroll
        for (int g = 0; g < 4; g++) CP_ASYNC16(st + arow_sw[g], srcA + ko + g);
#pragma unroll
        for (int j = 0; j < 4; j++) CP_ASYNC16(st + wdst[j], srcW[j] + ko);
        CP_COMMIT();
    }

#pragma unroll 1
    for (int kc = 0; kc < KCHUNKS; kc++) {
        if (kc == KCHUNKS - 1) { CP_WAIT0(); } else { CP_WAIT1(); }
        __syncthreads();
        if (kc + 2 < KCHUNKS) {
            int nc = kc + 2;
            const u32 st = smbase + (nc % 3) * QK_STAGE;
            const int ko = nc * 4;
#pragma unroll
            for (int g = 0; g < 4; g++) CP_ASYNC16(st + arow_sw[g], srcA + ko + g);
#pragma unroll
            for (int j = 0; j < 4; j++) CP_ASYNC16(st + wdst[j], srcW[j] + ko);
            CP_COMMIT();
        }

        const u32 Ab  = smbase + (kc % 3) * QK_STAGE;
        const u32 WqB = Ab + 16384;
        const u32 WkB = Ab + 16384 + 8192;

#pragma unroll
        for (int ks = 0; ks < 2; ks++) {
            u32 ah[2][4], al[2][4];
#pragma unroll
            for (int mt = 0; mt < 2; mt++) {
                int row = warpM * 32 + mt * 16 + (lane & 15);
                int c = ks * 2 + ((lane >> 4) & 1);
                u32 base = Ab + row * 128;
                LDSM4(ah[mt][0], ah[mt][1], ah[mt][2], ah[mt][3],
                      base + (((c) ^ (row & 7)) << 4));
                LDSM4(al[mt][0], al[mt][1], al[mt][2], al[mt][3],
                      base + (((c + 4) ^ (row & 7)) << 4));
            }
            // ---- Q mode ----
            {
                u32 bh[4][2], bl[4][2];
#pragma unroll
                for (int bt = 0; bt < 2; bt++) {
                    int row = warpN * 32 + bt * 16 + (lane & 7) + ((lane >> 4) & 1) * 8;
                    int c = ks * 2 + ((lane >> 3) & 1);
                    u32 base = WqB + row * 128;
                    u32 r0, r1, r2, r3;
                    LDSM4(r0, r1, r2, r3, base + (((c) ^ (row & 7)) << 4));
                    bh[bt * 2][0] = r0; bh[bt * 2][1] = r1;
                    bh[bt * 2 + 1][0] = r2; bh[bt * 2 + 1][1] = r3;
                    LDSM4(r0, r1, r2, r3, base + (((c + 4) ^ (row & 7)) << 4));
                    bl[bt * 2][0] = r0; bl[bt * 2][1] = r1;
                    bl[bt * 2 + 1][0] = r2; bl[bt * 2 + 1][1] = r3;
                }
#pragma unroll
                for (int mt = 0; mt < 2; mt++)
#pragma unroll
                    for (int nt = 0; nt < 4; nt++) {
                        MMA16816(accQ[mt][nt], ah[mt], bh[nt]);
                        MMA16816(accQ[mt][nt], ah[mt], bl[nt]);
                        MMA16816(accQ[mt][nt], al[mt], bh[nt]);
                    }
            }
            // ---- K mode ----
            {
                u32 bh[4][2], bl[4][2];
#pragma unroll
                for (int bt = 0; bt < 2; bt++) {
                    int row = warpN * 32 + bt * 16 + (lane & 7) + ((lane >> 4) & 1) * 8;
                    int c = ks * 2 + ((lane >> 3) & 1);
                    u32 base = WkB + row * 128;
                    u32 r0, r1, r2, r3;
                    LDSM4(r0, r1, r2, r3, base + (((c) ^ (row & 7)) << 4));
                    bh[bt * 2][0] = r0; bh[bt * 2][1] = r1;
                    bh[bt * 2 + 1][0] = r2; bh[bt * 2 + 1][1] = r3;
                    LDSM4(r0, r1, r2, r3, base + (((c + 4) ^ (row & 7)) << 4));
                    bl[bt * 2][0] = r0; bl[bt * 2][1] = r1;
                    bl[bt * 2 + 1][0] = r2; bl[bt * 2 + 1][1] = r3;
                }
#pragma unroll
                for (int mt = 0; mt < 2; mt++)
#pragma unroll
                    for (int nt = 0; nt < 4; nt++) {
                        MMA16816(accK[mt][nt], ah[mt], bh[nt]);
                        MMA16816(accK[mt][nt], ah[mt], bl[nt]);
                        MMA16816(accK[mt][nt], al[mt], bh[nt]);
                    }
            }
        }
    }

    // ---- epilogue: scatter Q and K (64 cols = one head) ----
    const int h = blockIdx.x;
    u32* qh_d = (u32*)g_qh4; u32* ql_d = (u32*)g_ql4;
    u32* kh_d = (u32*)g_kh4; u32* kl_d = (u32*)g_kl4;
#pragma unroll
    for (int mt = 0; mt < 2; mt++)
#pragma unroll
        for (int nt = 0; nt < 4; nt++)
#pragma unroll
            for (int cc = 0; cc < 2; cc++) {
                int rl = warpM * 32 + mt * 16 + (lane >> 2) + cc * 8;
                int cl = warpN * 32 + nt * 8 + (lane & 3) * 2;
                int n = n0 + rl;
                int bb = n / SEQ, ss = n - bb * SEQ;
                size_t idx = ((((size_t)bb * NH + h) * SEQ + ss) * HD + cl);
                {
                    float v0 = accQ[mt][nt][cc * 2 + 0] + bias_s[cl];
                    float v1 = accQ[mt][nt][cc * 2 + 1] + bias_s[cl + 1];
                    u32 hp, lp; pack_hilo(v0, v1, hp, lp);
                    qh_d[idx >> 1] = hp; ql_d[idx >> 1] = lp;
                }
                {
                    float v0 = accK[mt][nt][cc * 2 + 0] + bias_s[64 + cl];
                    float v1 = accK[mt][nt][cc * 2 + 1] + bias_s[64 + cl + 1];
                    u32 hp, lp; pack_hilo(v0, v1, hp, lp);
                    kh_d[idx >> 1] = hp; kl_d[idx >> 1] = lp;
                }
            }
}

// =====================================================================
// HMMA split-fp16 GEMM (V and O modes), CTA tile 128x64, 3-stage.
// mode 2 (V): 2-term, hi only. mode 3 (O): 2-term, fp32 out.
// =====================================================================
#define STAGE_BYTES 24576            // A 16K + W 8K
#define MM_SMEM (3 * STAGE_BYTES + 512)

__global__ __launch_bounds__(256, 2) void mm_hmma_kernel(
    const float* __restrict__ qb, const float* __restrict__ kb,
    const float* __restrict__ vb, const float* __restrict__ ob,
    float* __restrict__ outp, int mode_base)
{
    extern __shared__ char smraw[];
    const u32 smbase = smem_u32(smraw);
    float* bias_s = (float*)(smraw + 3 * STAGE_BYTES);

    const int t = threadIdx.x, lane = t & 31, wid = t >> 5;
    const int warpM = wid & 3;
    const int warpN = wid >> 2;
    const int mode = mode_base + blockIdx.z;
    const bool need3 = (mode < 2);
    const int o0 = blockIdx.x * 64;
    const int n0 = blockIdx.y * 128;

    const float* bias = mode == 0 ? qb : mode == 1 ? kb : mode == 2 ? vb : ob;
    const uint4* AhiG = (mode < 3) ? g_xhi4 : g_chi4;
    const uint4* AloG = g_xlo4;
    const size_t woff = (size_t)(mode < 3 ? mode : 3) * (EMBD * EMBD / 8);

    if (t < 64) bias_s[t] = bias[o0 + t];

    const int lr   = t >> 1;
    const int half = t & 1;
    const bool loadA = need3 || (half == 0);
    const uint4* srcA = (half ? AloG : AhiG) + (size_t)(n0 + lr) * 96;
    const u32 arow_sw[4] = {
        (u32)(lr * 128 + (((half * 4 + 0) ^ (lr & 7)) << 4)),
        (u32)(lr * 128 + (((half * 4 + 1) ^ (lr & 7)) << 4)),
        (u32)(lr * 128 + (((half * 4 + 2) ^ (lr & 7)) << 4)),
        (u32)(lr * 128 + (((half * 4 + 3) ^ (lr & 7)) << 4))
    };
    u32 wdst[2];
    const uint4* srcW[2];
#pragma unroll
    for (int j = 0; j < 2; j++) {
        int idx = t + j * 256;
        int row = idx >> 3, rem = idx & 7;
        int wh = rem >> 2, g = rem & 3;
        wdst[j] = (u32)(row * 128 + (((wh * 4 + g) ^ (row & 7)) << 4));
        srcW[j] = (wh ? g_wlo4 : g_whi4) + woff + (size_t)(o0 + row) * 96 + g;
    }

    float acc[2][4][4];
#pragma unroll
    for (int i = 0; i < 2; i++)
#pragma unroll
        for (int j = 0; j < 4; j++)
#pragma unroll
            for (int c = 0; c < 4; c++) acc[i][j][c] = 0.f;

#pragma unroll
    for (int pc = 0; pc < 2; pc++) {
        const u32 st = smbase + pc * STAGE_BYTES;
        const int ko = pc * 4;
#pragma unroll
        for (int g = 0; g < 4; g++)
            if (loadA) CP_ASYNC16(st + arow_sw[g], srcA + ko + g);
#pragma unroll
        for (int j = 0; j < 2; j++)
            CP_ASYNC16(st + 16384 + wdst[j], srcW[j] + ko);
        CP_COMMIT();
    }

#pragma unroll 1
    for (int kc = 0; kc < KCHUNKS; kc++) {
        if (kc == KCHUNKS - 1) { CP_WAIT0(); } else { CP_WAIT1(); }
        __syncthreads();
        if (kc + 2 < KCHUNKS) {
            int nc = kc + 2;
            const u32 st = smbase + (nc % 3) * STAGE_BYTES;
            const int ko = nc * 4;
#pragma unroll
            for (int g = 0; g < 4; g++)
                if (loadA) CP_ASYNC16(st + arow_sw[g], srcA + ko + g);
#pragma unroll
            for (int j = 0; j < 2; j++)
                CP_ASYNC16(st + 16384 + wdst[j], srcW[j] + ko);
            CP_COMMIT();
        }

        const u32 Ab = smbase + (kc % 3) * STAGE_BYTES;
        const u32 Wb = Ab + 16384;

#pragma unroll
        for (int ks = 0; ks < 2; ks++) {
            u32 ah[2][4], al[2][4];
#pragma unroll
            for (int mt = 0; mt < 2; mt++) {
                int row = warpM * 32 + mt * 16 + (lane & 15);
                int c = ks * 2 + ((lane >> 4) & 1);
                u32 base = Ab + row * 128;
                LDSM4(ah[mt][0], ah[mt][1], ah[mt][2], ah[mt][3],
                      base + (((c) ^ (row & 7)) << 4));
                if (need3)
                    LDSM4(al[mt][0], al[mt][1], al[mt][2], al[mt][3],
                          base + (((c + 4) ^ (row & 7)) << 4));
            }
            u32 bh[4][2], bl[4][2];
#pragma unroll
            for (int bt = 0; bt < 2; bt++) {
                int row = warpN * 32 + bt * 16 + (lane & 7) + ((lane >> 4) & 1) * 8;
                int c = ks * 2 + ((lane >> 3) & 1);
                u32 base = Wb + row * 128;
                u32 r0, r1, r2, r3;
                LDSM4(r0, r1, r2, r3, base + (((c) ^ (row & 7)) << 4));
                bh[bt * 2][0] = r0; bh[bt * 2][1] = r1;
                bh[bt * 2 + 1][0] = r2; bh[bt * 2 + 1][1] = r3;
                LDSM4(r0, r1, r2, r3, base + (((c + 4) ^ (row & 7)) << 4));
                bl[bt * 2][0] = r0; bl[bt * 2][1] = r1;
                bl[bt * 2 + 1][0] = r2; bl[bt * 2 + 1][1] = r3;
            }
#pragma unroll
            for (int mt = 0; mt < 2; mt++)
#pragma unroll
                for (int nt = 0; nt < 4; nt++) {
                    MMA16816(acc[mt][nt], ah[mt], bh[nt]);
                    MMA16816(acc[mt][nt], ah[mt], bl[nt]);
                    if (need3) MMA16816(acc[mt][nt], al[mt], bh[nt]);
                }
        }
    }

    u32* dsth = (u32*)(mode == 0 ? g_qh4 : mode == 1 ? g_kh4 : g_vh4);
    u32* dstl = (u32*)(mode == 0 ? g_ql4 : g_kl4);
    const int h = blockIdx.x;
#pragma unroll
    for (int mt = 0; mt < 2; mt++)
#pragma unroll
        for (int nt = 0; nt < 4; nt++)
#pragma unroll
            for (int cc = 0; cc < 2; cc++) {
                int rl = warpM * 32 + mt * 16 + (lane >> 2) + cc * 8;
                int cl = warpN * 32 + nt * 8 + (lane & 3) * 2;
                float v0 = acc[mt][nt][cc * 2 + 0] + bias_s[cl];
                float v1 = acc[mt][nt][cc * 2 + 1] + bias_s[cl + 1];
                int n = n0 + rl;
                if (mode < 3) {
                    int bb = n / SEQ, ss = n - bb * SEQ;
                    size_t idx = ((((size_t)bb * NH + h) * SEQ + ss) * HD + cl);
                    u32 hp, lp; pack_hilo(v0, v1, hp, lp);
                    dsth[idx >> 1] = hp;
                    if (mode != 2) dstl[idx >> 1] = lp;
                } else {
                    float2* p = (float2*)(outp + (size_t)n * EMBD + o0 + cl);
                    *p = make_float2(v0, v1);
                }
            }
}

// =====================================================================
// HMMA attention (unchanged from R9 passing kernel)
// =====================================================================
#define SLAB_W 578
#define SC_B   0
#define ST0_B  (32 * SLAB_W * 4)
#define ST1_B  (ST0_B + 16384)
#define PH_B   (ST1_B + 16384)
#define INV_B  (PH_B + 4096)
#define MAXP_B (INV_B + 128)
#define ATTN_SMEM (MAXP_B + 512)

__device__ __forceinline__ void load_tile64_async(
    u32 dsth, u32 dstl,
    const uint4* __restrict__ srch, const uint4* __restrict__ srcl,
    int tokbase, int t)
{
#pragma unroll
    for (int it = 0; it < 2; it++) {
        int idx = t + it * 256;
        int r = idx >> 3, c = idx & 7;
        u32 off = (u32)(r * 128 + ((c ^ (r & 7)) << 4));
        CP_ASYNC16(dsth + off, srch + (size_t)(tokbase + r) * 8 + c);
        CP_ASYNC16(dstl + off, srcl + (size_t)(tokbase + r) * 8 + c);
    }
    CP_COMMIT();
}

__device__ __forceinline__ void load_v_async(
    u32 dsth, const uint4* __restrict__ srch, int tokbase, int t)
{
#pragma unroll
    for (int it = 0; it < 2; it++) {
        int idx = t + it * 256;
        int r = idx >> 3, c = idx & 7;
        u32 off = (u32)(r * 128 + ((c ^ (r & 7)) << 4));
        CP_ASYNC16(dsth + off, srch + (size_t)(tokbase + r) * 8 + c);
    }
    CP_COMMIT();
}

__global__ __launch_bounds__(256, 2) void attn_kernel(float* __restrict__ attn_out)
{
    extern __shared__ char smc[];
    const u32 smb = smem_u32(smc);
    float* sc = (float*)smc;
    float* inv_s = (float*)(smc + INV_B);
    float* maxp  = (float*)(smc + MAXP_B);

    const int t = threadIdx.x, lane = t & 31, wid = t >> 5;
    const int warpM = wid & 1;
    const int warpN = wid >> 1;
    const int qt = blockIdx.x;
    const int bh = blockIdx.y;
    const int qtok = bh * SEQ + qt * 32;
    const int ktok0 = bh * SEQ;

    {
        int r = t >> 3, c = t & 7;
        uint4 a = g_qh4[(size_t)(qtok + r) * 8 + c];
        uint4 b = g_ql4[(size_t)(qtok + r) * 8 + c];
        u32 off = (u32)(r * 128 + ((c ^ (r & 7)) << 4));
        STS128(smb + ST0_B + off, a.x, a.y, a.z, a.w);
        STS128(smb + ST0_B + 4096 + off, b.x, b.y, b.z, b.w);
    }
    __syncthreads();

    u32 qh[4][4], ql[4][4];
#pragma unroll
    for (int ks = 0; ks < 4; ks++) {
        int row = warpM * 16 + (lane & 15);
        int c = ks * 2 + ((lane >> 4) & 1);
        u32 sw = (u32)(row * 128 + ((c ^ (row & 7)) << 4));
        LDSM4(qh[ks][0], qh[ks][1], qh[ks][2], qh[ks][3], smb + ST0_B + sw);
        LDSM4(ql[ks][0], ql[ks][1], ql[ks][2], ql[ks][3], smb + ST0_B + 4096 + sw);
    }

    load_tile64_async(smb + ST1_B, smb + ST1_B + 8192, g_kh4, g_kl4, ktok0, t);

    float fm[2] = {-1e30f, -1e30f};

#pragma unroll 1
    for (int kt = 0; kt < 9; kt++) {
        CP_WAIT0();
        __syncthreads();
        if (kt < 9 - 1) {
            u32 nb = smb + (((kt + 1 + 1) & 1) ? ST1_B : ST0_B);
            load_tile64_async(nb, nb + 8192, g_kh4, g_kl4, ktok0 + (kt + 1) * 64, t);
        }
        const u32 kb = smb + (((kt + 1) & 1) ? ST1_B : ST0_B);
        const u32 klb = kb + 8192;

        float acc[2][4];
#pragma unroll
        for (int i = 0; i < 2; i++)
#pragma unroll
            for (int j = 0; j < 4; j++) acc[i][j] = 0.f;

#pragma unroll
        for (int ks = 0; ks < 4; ks++) {
            u32 bh2[2][2], bl2[2][2];
            {
                int row = warpN * 16 + (lane & 7) + ((lane >> 4) & 1) * 8;
                int c = ks * 2 + ((lane >> 3) & 1);
                u32 sw = (u32)(row * 128 + ((c ^ (row & 7)) << 4));
                u32 r0, r1, r2, r3;
                LDSM4(r0, r1, r2, r3, kb + sw);
                bh2[0][0] = r0; bh2[0][1] = r1;
                bh2[1][0] = r2; bh2[1][1] = r3;
                LDSM4(r0, r1, r2, r3, klb + sw);
                bl2[0][0] = r0; bl2[0][1] = r1;
                bl2[1][0] = r2; bl2[1][1] = r3;
            }
#pragma unroll
            for (int nt = 0; nt < 2; nt++) {
                MMA16816(acc[nt], qh[ks], bh2[nt]);
                MMA16816(acc[nt], qh[ks], bl2[nt]);
                MMA16816(acc[nt], ql[ks], bh2[nt]);
            }
        }
#pragma unroll
        for (int nt = 0; nt < 2; nt++)
#pragma unroll
            for (int cc = 0; cc < 2; cc++) {
                fm[cc] = fmaxf(fm[cc], fmaxf(acc[nt][cc * 2], acc[nt][cc * 2 + 1]));
                int r = warpM * 16 + (lane >> 2) + cc * 8;
                int col = kt * 64 + warpN * 16 + nt * 8 + (lane & 3) * 2;
                float2* p = (float2*)(sc + r * SLAB_W + col);
                *p = make_float2(acc[nt][cc * 2] * ATT_SCALE,
                                 acc[nt][cc * 2 + 1] * ATT_SCALE);
            }
    }
#pragma unroll
    for (int cc = 0; cc < 2; cc++) {
        fm[cc] = fmaxf(fm[cc], __shfl_xor_sync(0xffffffffu, fm[cc], 1));
        fm[cc] = fmaxf(fm[cc], __shfl_xor_sync(0xffffffffu, fm[cc], 2));
        if ((lane & 3) == 0) {
            int r = warpM * 16 + (lane >> 2) + cc * 8;
            maxp[warpN * 32 + r] = fm[cc];
        }
    }
    __syncthreads();

    load_v_async(smb + ST0_B, g_vh4, ktok0, t);

    {
        for (int rr = 0; rr < 4; rr++) {
            int r = wid * 4 + rr;
            float m = fmaxf(fmaxf(maxp[r], maxp[32 + r]),
                            fmaxf(maxp[64 + r], maxp[96 + r])) * ATT_SCALE;
            float* row = sc + r * SLAB_W;
            float s = 0.f;
            for (int c = lane; c < SEQ; c += 32) {
                float e = __expf(row[c] - m);
                row[c] = e;
                s += e;
            }
#pragma unroll
            for (int off = 16; off > 0; off >>= 1)
                s += __shfl_xor_sync(0xffffffffu, s, off);
            if (lane == 0) inv_s[r] = 1.f / s;
        }
    }

    float acc2[2][4];
#pragma unroll
    for (int i = 0; i < 2; i++)
#pragma unroll
        for (int j = 0; j < 4; j++) acc2[i][j] = 0.f;

#pragma unroll 1
    for (int kt = 0; kt < 9; kt++) {
        CP_WAIT0();
        __syncthreads();
        if (kt < 9 - 1) {
            u32 nb = smb + (((kt + 1) & 1) ? ST1_B : ST0_B);
            load_v_async(nb, g_vh4, ktok0 + (kt + 1) * 64, t);
        }
#pragma unroll
        for (int i = 0; i < 4; i++) {
            int r = wid * 4 + i;
            float inv = inv_s[r];
            float2 e = *(const float2*)(sc + r * SLAB_W + kt * 64 + lane * 2);
            float p0 = e.x * inv, p1 = e.y * inv;
            size_t arow = ((size_t)bh * SEQ + (size_t)(qt * 32 + r)) * SEQ;
            *(float2*)(attn_out + arow + kt * 64 + lane * 2) = make_float2(p0, p1);
            u32 off = (u32)(r * 128 + (((lane >> 2) ^ (r & 7)) << 4) + (lane & 3) * 4);
            *(u32*)(smc + PH_B + off) = pack_hi(p0, p1);
        }
        __syncthreads();

        const u32 vb2 = smb + ((kt & 1) ? ST1_B : ST0_B);

#pragma unroll
        for (int ks = 0; ks < 4; ks++) {
            u32 ph[4];
            {
                int row = warpM * 16 + (lane & 15);
                int c = ks * 2 + ((lane >> 4) & 1);
                u32 sw = (u32)(row * 128 + ((c ^ (row & 7)) << 4));
                LDSM4(ph[0], ph[1], ph[2], ph[3], smb + PH_B + sw);
            }
            u32 vh[2][2];
            {
                int m = lane >> 3;
                int row_s = ks * 16 + ((m & 1) << 3) + (lane & 7);
                int chunk = warpN * 2 + (m >> 1);
                u32 sw = (u32)(row_s * 128 + ((chunk ^ (row_s & 7)) << 4));
                u32 r0, r1, r2, r3;
                LDSM4T(r0, r1, r2, r3, vb2 + sw);
                vh[0][0] = r0; vh[0][1] = r1;
                vh[1][0] = r2; vh[1][1] = r3;
            }
#pragma unroll
            for (int nt = 0; nt < 2; nt++) {
                MMA16816(acc2[nt], ph, vh[nt]);
            }
        }
    }

    const int bb = bh / NH, h = bh % NH;
    u32* ch = (u32*)g_chi4;
#pragma unroll
    for (int nt = 0; nt < 2; nt++)
#pragma unroll
        for (int cc = 0; cc < 2; cc++) {
            int r = warpM * 16 + (lane >> 2) + cc * 8;
            int d = warpN * 16 + nt * 8 + (lane & 3) * 2;
            size_t n = (size_t)bb * SEQ + (size_t)(qt * 32 + r);
            size_t idx = n * EMBD + h * 64 + d;
            ch[idx >> 1] = pack_hi(acc2[nt][cc * 2], acc2[nt][cc * 2 + 1]);
        }
}

// =====================================================================
// launch
// =====================================================================
extern "C" void kernel_launch(void* const* d_in, const int* in_sizes, int n_in,
                              void* d_out, int out_size)
{
    const float* hs = (const float*)d_in[0];
    const float* qw = (const float*)d_in[1];
    const float* qb = (const float*)d_in[2];
    const float* kw = (const float*)d_in[3];
    const float* kb = (const float*)d_in[4];
    const float* vw = (const float*)d_in[5];
    const float* vb = (const float*)d_in[6];
    const float* ow = (const float*)d_in[7];
    const float* ob = (const float*)d_in[8];

    float* out  = (float*)d_out;
    float* attn = out + OUT_ELEMS;

    cudaFuncSetAttribute(qk_fused_kernel, cudaFuncAttributeMaxDynamicSharedMemorySize,
                         QK_SMEM);
    cudaFuncSetAttribute(mm_hmma_kernel, cudaFuncAttributeMaxDynamicSharedMemorySize,
                         MM_SMEM);
    cudaFuncSetAttribute(attn_kernel, cudaFuncAttributeMaxDynamicSharedMemorySize,
                         ATTN_SMEM);

    conv_x_kernel<<<(NT * EMBD / 8 + 255) / 256, 256>>>(hs);
    conv_w_kernel<<<dim3((EMBD * EMBD / 8 + 255) / 256, 4), 256>>>(qw, kw, vw, ow);

    // fused Q+K projection, then V
    qk_fused_kernel<<<dim3(EMBD / 64, NT / 128), 256, QK_SMEM>>>(qb, kb);
    mm_hmma_kernel<<<dim3(EMBD / 64, NT / 128, 1), 256, MM_SMEM>>>(
        qb, kb, vb, ob, out, 2);

    attn_kernel<<<dim3(18, BATCH * NH), 256, ATTN_SMEM>>>(attn);

    mm_hmma_kernel<<<dim3(EMBD / 64, NT / 128, 1), 256, MM_SMEM>>>(
        qb, kb, vb, ob, out, 3);
}

// round 12
// speedup vs baseline: 2.9449x; 1.0096x over previous
#include <cuda_runtime.h>
#include <cuda_fp16.h>

// ---------------- problem constants ----------------
#define BATCH 32
#define SEQ   576
#define EMBD  768
#define NH    12
#define HD    64
#define NT    (BATCH * SEQ)
#define OUT_ELEMS ((size_t)NT * EMBD)
#define ATT_SCALE 0.125f
#define KCHUNKS 24

typedef unsigned int u32;
typedef unsigned short u16;

// ---------------- device scratch ----------------
__device__ uint4 g_xhi4[NT * EMBD / 8];
__device__ uint4 g_xlo4[NT * EMBD / 8];
__device__ uint4 g_whi4[4 * EMBD * EMBD / 8];
__device__ uint4 g_wlo4[4 * EMBD * EMBD / 8];
__device__ uint4 g_chi4[NT * EMBD / 8];          // ctx hi only ([N, EMB], fp16)
__device__ uint4 g_qh4[NT * EMBD / 8];           // [B,H,S,D] fp16 hi/lo
__device__ uint4 g_ql4[NT * EMBD / 8];
__device__ uint4 g_kh4[NT * EMBD / 8];
__device__ uint4 g_kl4[NT * EMBD / 8];
__device__ uint4 g_vh4[NT * EMBD / 8];           // V hi only

// ---------------- helpers ----------------
__device__ __forceinline__ u32 smem_u32(const void* p) {
    u32 a;
    asm("{ .reg .u64 t; cvta.to.shared.u64 t, %1; cvt.u32.u64 %0, t; }"
        : "=r"(a) : "l"(p));
    return a;
}

#define CP_ASYNC16(dst, src) \
    asm volatile("cp.async.cg.shared.global [%0], [%1], 16;" \
                 :: "r"(dst), "l"(src) : "memory")
#define CP_COMMIT() asm volatile("cp.async.commit_group;" ::: "memory")
#define CP_WAIT2()  asm volatile("cp.async.wait_group 2;" ::: "memory")
#define CP_WAIT1()  asm volatile("cp.async.wait_group 1;" ::: "memory")
#define CP_WAIT0()  asm volatile("cp.async.wait_group 0;" ::: "memory")

#define LDSM4(r0, r1, r2, r3, addr) \
    asm volatile("ldmatrix.sync.aligned.m8n8.x4.shared.b16 {%0,%1,%2,%3}, [%4];" \
                 : "=r"(r0), "=r"(r1), "=r"(r2), "=r"(r3) : "r"(addr))
#define LDSM4T(r0, r1, r2, r3, addr) \
    asm volatile("ldmatrix.sync.aligned.m8n8.x4.trans.shared.b16 {%0,%1,%2,%3}, [%4];" \
                 : "=r"(r0), "=r"(r1), "=r"(r2), "=r"(r3) : "r"(addr))

#define MMA16816(d, a, b) \
    asm volatile("mma.sync.aligned.m16n8k16.row.col.f32.f16.f16.f32 " \
                 "{%0,%1,%2,%3}, {%4,%5,%6,%7}, {%8,%9}, {%0,%1,%2,%3};" \
                 : "+f"((d)[0]), "+f"((d)[1]), "+f"((d)[2]), "+f"((d)[3]) \
                 : "r"((a)[0]), "r"((a)[1]), "r"((a)[2]), "r"((a)[3]), \
                   "r"((b)[0]), "r"((b)[1]))

#define STS128(addr, a, b, c, d) \
    asm volatile("st.shared.v4.b32 [%0], {%1, %2, %3, %4};" \
                 :: "r"(addr), "r"(a), "r"(b), "r"(c), "r"(d) : "memory")

__device__ __forceinline__ void pack_hilo(float v0, float v1, u32& hp, u32& lp) {
    __half h0 = __float2half_rn(v0);
    __half h1 = __float2half_rn(v1);
    __half l0 = __float2half_rn(v0 - __half2float(h0));
    __half l1 = __float2half_rn(v1 - __half2float(h1));
    hp = (u32)*(u16*)&h0 | ((u32)*(u16*)&h1 << 16);
    lp = (u32)*(u16*)&l0 | ((u32)*(u16*)&l1 << 16);
}
__device__ __forceinline__ u32 pack_hi(float v0, float v1) {
    __half h0 = __float2half_rn(v0);
    __half h1 = __float2half_rn(v1);
    return (u32)*(u16*)&h0 | ((u32)*(u16*)&h1 << 16);
}

// =====================================================================
// hi/lo split conversion (fp16)
// =====================================================================
__device__ __forceinline__ void conv8(const float4* src2, uint4* hi, uint4* lo) {
    float4 a = src2[0], b = src2[1];
    float f[8] = {a.x, a.y, a.z, a.w, b.x, b.y, b.z, b.w};
    union { uint4 v; __half h[8]; } H, L;
#pragma unroll
    for (int j = 0; j < 8; j++) {
        __half hh = __float2half_rn(f[j]);
        H.h[j] = hh;
        L.h[j] = __float2half_rn(f[j] - __half2float(hh));
    }
    *hi = H.v; *lo = L.v;
}

__global__ __launch_bounds__(256) void conv_x_kernel(const float* __restrict__ src) {
    int i = blockIdx.x * blockDim.x + threadIdx.x;
    if (i >= NT * EMBD / 8) return;
    conv8((const float4*)src + 2 * (size_t)i, &g_xhi4[i], &g_xlo4[i]);
}

__global__ __launch_bounds__(256) void conv_w_kernel(
    const float* __restrict__ qw, const float* __restrict__ kw,
    const float* __restrict__ vw, const float* __restrict__ ow) {
    int z = blockIdx.y;
    const float* src = z == 0 ? qw : z == 1 ? kw : z == 2 ? vw : ow;
    int i = blockIdx.x * blockDim.x + threadIdx.x;
    if (i >= EMBD * EMBD / 8) return;
    int di = z * (EMBD * EMBD / 8) + i;
    conv8((const float4*)src + 2 * (size_t)i, &g_whi4[di], &g_wlo4[di]);
}

// =====================================================================
// Fused Q+K projection (3-term each), 3-stage pipeline.
// =====================================================================
#define QK_STAGE 32768
#define QK_SMEM (3 * QK_STAGE + 1024)

__global__ __launch_bounds__(256, 2) void qk_fused_kernel(
    const float* __restrict__ qb, const float* __restrict__ kb)
{
    extern __shared__ char smraw[];
    const u32 smbase = smem_u32(smraw);
    float* bias_s = (float*)(smraw + 3 * QK_STAGE);   // [2][64]

    const int t = threadIdx.x, lane = t & 31, wid = t >> 5;
    const int warpM = wid & 3;
    const int warpN = wid >> 2;
    const int o0 = blockIdx.x * 64;
    const int n0 = blockIdx.y * 128;

    if (t < 64) bias_s[t] = qb[o0 + t];
    else if (t < 128) bias_s[t] = kb[o0 + t - 64];

    const int lr   = t >> 1;
    const int half = t & 1;
    const uint4* srcA = (half ? g_xlo4 : g_xhi4) + (size_t)(n0 + lr) * 96;
    const u32 arow_sw[4] = {
        (u32)(lr * 128 + (((half * 4 + 0) ^ (lr & 7)) << 4)),
        (u32)(lr * 128 + (((half * 4 + 1) ^ (lr & 7)) << 4)),
        (u32)(lr * 128 + (((half * 4 + 2) ^ (lr & 7)) << 4)),
        (u32)(lr * 128 + (((half * 4 + 3) ^ (lr & 7)) << 4))
    };
    u32 wdst[4];
    const uint4* srcW[4];
#pragma unroll
    for (int j = 0; j < 4; j++) {
        int idx = t + j * 256;
        int mw = idx >> 9;
        int within = idx & 511;
        int row = within >> 3, rem = within & 7;
        int wh = rem >> 2, g = rem & 3;
        wdst[j] = (u32)(16384 + mw * 8192 + row * 128 + (((wh * 4 + g) ^ (row & 7)) << 4));
        srcW[j] = (wh ? g_wlo4 : g_whi4) + (size_t)mw * (EMBD * EMBD / 8)
                  + (size_t)(o0 + row) * 96 + g;
    }

    float accQ[2][4][4], accK[2][4][4];
#pragma unroll
    for (int i = 0; i < 2; i++)
#pragma unroll
        for (int j = 0; j < 4; j++)
#pragma unroll
            for (int c = 0; c < 4; c++) { accQ[i][j][c] = 0.f; accK[i][j][c] = 0.f; }

#pragma unroll
    for (int pc = 0; pc < 2; pc++) {
        const u32 st = smbase + pc * QK_STAGE;
        const int ko = pc * 4;
#pragma unroll
        for (int g = 0; g < 4; g++) CP_ASYNC16(st + arow_sw[g], srcA + ko + g);
#pragma unroll
        for (int j = 0; j < 4; j++) CP_ASYNC16(st + wdst[j], srcW[j] + ko);
        CP_COMMIT();
    }

#pragma unroll 1
    for (int kc = 0; kc < KCHUNKS; kc++) {
        if (kc == KCHUNKS - 1) { CP_WAIT0(); } else { CP_WAIT1(); }
        __syncthreads();
        if (kc + 2 < KCHUNKS) {
            int nc = kc + 2;
            const u32 st = smbase + (nc % 3) * QK_STAGE;
            const int ko = nc * 4;
#pragma unroll
            for (int g = 0; g < 4; g++) CP_ASYNC16(st + arow_sw[g], srcA + ko + g);
#pragma unroll
            for (int j = 0; j < 4; j++) CP_ASYNC16(st + wdst[j], srcW[j] + ko);
            CP_COMMIT();
        }

        const u32 Ab  = smbase + (kc % 3) * QK_STAGE;
        const u32 WqB = Ab + 16384;
        const u32 WkB = Ab + 16384 + 8192;

#pragma unroll
        for (int ks = 0; ks < 2; ks++) {
            u32 ah[2][4], al[2][4];
#pragma unroll
            for (int mt = 0; mt < 2; mt++) {
                int row = warpM * 32 + mt * 16 + (lane & 15);
                int c = ks * 2 + ((lane >> 4) & 1);
                u32 base = Ab + row * 128;
                LDSM4(ah[mt][0], ah[mt][1], ah[mt][2], ah[mt][3],
                      base + (((c) ^ (row & 7)) << 4));
                LDSM4(al[mt][0], al[mt][1], al[mt][2], al[mt][3],
                      base + (((c + 4) ^ (row & 7)) << 4));
            }
            {
                u32 bh[4][2], bl[4][2];
#pragma unroll
                for (int bt = 0; bt < 2; bt++) {
                    int row = warpN * 32 + bt * 16 + (lane & 7) + ((lane >> 4) & 1) * 8;
                    int c = ks * 2 + ((lane >> 3) & 1);
                    u32 base = WqB + row * 128;
                    u32 r0, r1, r2, r3;
                    LDSM4(r0, r1, r2, r3, base + (((c) ^ (row & 7)) << 4));
                    bh[bt * 2][0] = r0; bh[bt * 2][1] = r1;
                    bh[bt * 2 + 1][0] = r2; bh[bt * 2 + 1][1] = r3;
                    LDSM4(r0, r1, r2, r3, base + (((c + 4) ^ (row & 7)) << 4));
                    bl[bt * 2][0] = r0; bl[bt * 2][1] = r1;
                    bl[bt * 2 + 1][0] = r2; bl[bt * 2 + 1][1] = r3;
                }
#pragma unroll
                for (int mt = 0; mt < 2; mt++)
#pragma unroll
                    for (int nt = 0; nt < 4; nt++) {
                        MMA16816(accQ[mt][nt], ah[mt], bh[nt]);
                        MMA16816(accQ[mt][nt], ah[mt], bl[nt]);
                        MMA16816(accQ[mt][nt], al[mt], bh[nt]);
                    }
            }
            {
                u32 bh[4][2], bl[4][2];
#pragma unroll
                for (int bt = 0; bt < 2; bt++) {
                    int row = warpN * 32 + bt * 16 + (lane & 7) + ((lane >> 4) & 1) * 8;
                    int c = ks * 2 + ((lane >> 3) & 1);
                    u32 base = WkB + row * 128;
                    u32 r0, r1, r2, r3;
                    LDSM4(r0, r1, r2, r3, base + (((c) ^ (row & 7)) << 4));
                    bh[bt * 2][0] = r0; bh[bt * 2][1] = r1;
                    bh[bt * 2 + 1][0] = r2; bh[bt * 2 + 1][1] = r3;
                    LDSM4(r0, r1, r2, r3, base + (((c + 4) ^ (row & 7)) << 4));
                    bl[bt * 2][0] = r0; bl[bt * 2][1] = r1;
                    bl[bt * 2 + 1][0] = r2; bl[bt * 2 + 1][1] = r3;
                }
#pragma unroll
                for (int mt = 0; mt < 2; mt++)
#pragma unroll
                    for (int nt = 0; nt < 4; nt++) {
                        MMA16816(accK[mt][nt], ah[mt], bh[nt]);
                        MMA16816(accK[mt][nt], ah[mt], bl[nt]);
                        MMA16816(accK[mt][nt], al[mt], bh[nt]);
                    }
            }
        }
    }

    const int h = blockIdx.x;
    u32* qh_d = (u32*)g_qh4; u32* ql_d = (u32*)g_ql4;
    u32* kh_d = (u32*)g_kh4; u32* kl_d = (u32*)g_kl4;
#pragma unroll
    for (int mt = 0; mt < 2; mt++)
#pragma unroll
        for (int nt = 0; nt < 4; nt++)
#pragma unroll
            for (int cc = 0; cc < 2; cc++) {
                int rl = warpM * 32 + mt * 16 + (lane >> 2) + cc * 8;
                int cl = warpN * 32 + nt * 8 + (lane & 3) * 2;
                int n = n0 + rl;
                int bb = n / SEQ, ss = n - bb * SEQ;
                size_t idx = ((((size_t)bb * NH + h) * SEQ + ss) * HD + cl);
                {
                    float v0 = accQ[mt][nt][cc * 2 + 0] + bias_s[cl];
                    float v1 = accQ[mt][nt][cc * 2 + 1] + bias_s[cl + 1];
                    u32 hp, lp; pack_hilo(v0, v1, hp, lp);
                    qh_d[idx >> 1] = hp; ql_d[idx >> 1] = lp;
                }
                {
                    float v0 = accK[mt][nt][cc * 2 + 0] + bias_s[64 + cl];
                    float v1 = accK[mt][nt][cc * 2 + 1] + bias_s[64 + cl + 1];
                    u32 hp, lp; pack_hilo(v0, v1, hp, lp);
                    kh_d[idx >> 1] = hp; kl_d[idx >> 1] = lp;
                }
            }
}

// =====================================================================
// HMMA split-fp16 GEMM (V and O modes), CTA tile 128x64, 4-stage.
// =====================================================================
#define STAGE_BYTES 24576            // A 16K + W 8K
#define MM_SMEM (4 * STAGE_BYTES + 512)

__global__ __launch_bounds__(256, 2) void mm_hmma_kernel(
    const float* __restrict__ qb, const float* __restrict__ kb,
    const float* __restrict__ vb, const float* __restrict__ ob,
    float* __restrict__ outp, int mode_base)
{
    extern __shared__ char smraw[];
    const u32 smbase = smem_u32(smraw);
    float* bias_s = (float*)(smraw + 4 * STAGE_BYTES);

    const int t = threadIdx.x, lane = t & 31, wid = t >> 5;
    const int warpM = wid & 3;
    const int warpN = wid >> 2;
    const int mode = mode_base + blockIdx.z;
    const bool need3 = (mode < 2);
    const int o0 = blockIdx.x * 64;
    const int n0 = blockIdx.y * 128;

    const float* bias = mode == 0 ? qb : mode == 1 ? kb : mode == 2 ? vb : ob;
    const uint4* AhiG = (mode < 3) ? g_xhi4 : g_chi4;
    const uint4* AloG = g_xlo4;
    const size_t woff = (size_t)(mode < 3 ? mode : 3) * (EMBD * EMBD / 8);

    if (t < 64) bias_s[t] = bias[o0 + t];

    const int lr   = t >> 1;
    const int half = t & 1;
    const bool loadA = need3 || (half == 0);
    const uint4* srcA = (half ? AloG : AhiG) + (size_t)(n0 + lr) * 96;
    const u32 arow_sw[4] = {
        (u32)(lr * 128 + (((half * 4 + 0) ^ (lr & 7)) << 4)),
        (u32)(lr * 128 + (((half * 4 + 1) ^ (lr & 7)) << 4)),
        (u32)(lr * 128 + (((half * 4 + 2) ^ (lr & 7)) << 4)),
        (u32)(lr * 128 + (((half * 4 + 3) ^ (lr & 7)) << 4))
    };
    u32 wdst[2];
    const uint4* srcW[2];
#pragma unroll
    for (int j = 0; j < 2; j++) {
        int idx = t + j * 256;
        int row = idx >> 3, rem = idx & 7;
        int wh = rem >> 2, g = rem & 3;
        wdst[j] = (u32)(row * 128 + (((wh * 4 + g) ^ (row & 7)) << 4));
        srcW[j] = (wh ? g_wlo4 : g_whi4) + woff + (size_t)(o0 + row) * 96 + g;
    }

    float acc[2][4][4];
#pragma unroll
    for (int i = 0; i < 2; i++)
#pragma unroll
        for (int j = 0; j < 4; j++)
#pragma unroll
            for (int c = 0; c < 4; c++) acc[i][j][c] = 0.f;

    // prefetch chunks 0..2
#pragma unroll
    for (int pc = 0; pc < 3; pc++) {
        const u32 st = smbase + pc * STAGE_BYTES;
        const int ko = pc * 4;
#pragma unroll
        for (int g = 0; g < 4; g++)
            if (loadA) CP_ASYNC16(st + arow_sw[g], srcA + ko + g);
#pragma unroll
        for (int j = 0; j < 2; j++)
            CP_ASYNC16(st + 16384 + wdst[j], srcW[j] + ko);
        CP_COMMIT();
    }

#pragma unroll 1
    for (int kc = 0; kc < KCHUNKS; kc++) {
        int rem = KCHUNKS - 1 - kc;
        if (rem >= 2)      { CP_WAIT2(); }
        else if (rem == 1) { CP_WAIT1(); }
        else               { CP_WAIT0(); }
        __syncthreads();
        if (kc + 3 < KCHUNKS) {
            int nc = kc + 3;
            const u32 st = smbase + (nc & 3) * STAGE_BYTES;
            const int ko = nc * 4;
#pragma unroll
            for (int g = 0; g < 4; g++)
                if (loadA) CP_ASYNC16(st + arow_sw[g], srcA + ko + g);
#pragma unroll
            for (int j = 0; j < 2; j++)
                CP_ASYNC16(st + 16384 + wdst[j], srcW[j] + ko);
            CP_COMMIT();
        }

        const u32 Ab = smbase + (kc & 3) * STAGE_BYTES;
        const u32 Wb = Ab + 16384;

#pragma unroll
        for (int ks = 0; ks < 2; ks++) {
            u32 ah[2][4], al[2][4];
#pragma unroll
            for (int mt = 0; mt < 2; mt++) {
                int row = warpM * 32 + mt * 16 + (lane & 15);
                int c = ks * 2 + ((lane >> 4) & 1);
                u32 base = Ab + row * 128;
                LDSM4(ah[mt][0], ah[mt][1], ah[mt][2], ah[mt][3],
                      base + (((c) ^ (row & 7)) << 4));
                if (need3)
                    LDSM4(al[mt][0], al[mt][1], al[mt][2], al[mt][3],
                          base + (((c + 4) ^ (row & 7)) << 4));
            }
            u32 bh[4][2], bl[4][2];
#pragma unroll
            for (int bt = 0; bt < 2; bt++) {
                int row = warpN * 32 + bt * 16 + (lane & 7) + ((lane >> 4) & 1) * 8;
                int c = ks * 2 + ((lane >> 3) & 1);
                u32 base = Wb + row * 128;
                u32 r0, r1, r2, r3;
                LDSM4(r0, r1, r2, r3, base + (((c) ^ (row & 7)) << 4));
                bh[bt * 2][0] = r0; bh[bt * 2][1] = r1;
                bh[bt * 2 + 1][0] = r2; bh[bt * 2 + 1][1] = r3;
                LDSM4(r0, r1, r2, r3, base + (((c + 4) ^ (row & 7)) << 4));
                bl[bt * 2][0] = r0; bl[bt * 2][1] = r1;
                bl[bt * 2 + 1][0] = r2; bl[bt * 2 + 1][1] = r3;
            }
#pragma unroll
            for (int mt = 0; mt < 2; mt++)
#pragma unroll
                for (int nt = 0; nt < 4; nt++) {
                    MMA16816(acc[mt][nt], ah[mt], bh[nt]);
                    MMA16816(acc[mt][nt], ah[mt], bl[nt]);
                    if (need3) MMA16816(acc[mt][nt], al[mt], bh[nt]);
                }
        }
    }

    u32* dsth = (u32*)(mode == 0 ? g_qh4 : mode == 1 ? g_kh4 : g_vh4);
    u32* dstl = (u32*)(mode == 0 ? g_ql4 : g_kl4);
    const int h = blockIdx.x;
#pragma unroll
    for (int mt = 0; mt < 2; mt++)
#pragma unroll
        for (int nt = 0; nt < 4; nt++)
#pragma unroll
            for (int cc = 0; cc < 2; cc++) {
                int rl = warpM * 32 + mt * 16 + (lane >> 2) + cc * 8;
                int cl = warpN * 32 + nt * 8 + (lane & 3) * 2;
                float v0 = acc[mt][nt][cc * 2 + 0] + bias_s[cl];
                float v1 = acc[mt][nt][cc * 2 + 1] + bias_s[cl + 1];
                int n = n0 + rl;
                if (mode < 3) {
                    int bb = n / SEQ, ss = n - bb * SEQ;
                    size_t idx = ((((size_t)bb * NH + h) * SEQ + ss) * HD + cl);
                    u32 hp, lp; pack_hilo(v0, v1, hp, lp);
                    dsth[idx >> 1] = hp;
                    if (mode != 2) dstl[idx >> 1] = lp;
                } else {
                    float2* p = (float2*)(outp + (size_t)n * EMBD + o0 + cl);
                    *p = make_float2(v0, v1);
                }
            }
}

// =====================================================================
// HMMA attention, 32-row q tiles, 2 CTAs/SM.
// PV phase software-pipelined with double-buffered PH tiles (1 sync/iter).
// SLAB_W = 578 (even, keeps float2 slab accesses 8B-aligned).
// =====================================================================
#define SLAB_W 578
#define SC_B   0
#define ST0_B  (32 * SLAB_W * 4)           // 73,984
#define ST1_B  (ST0_B + 16384)             // 90,368
#define PH_B   (ST1_B + 16384)             // 106,752 (2 x 4096)
#define INV_B  (PH_B + 8192)               // 114,944
#define MAXP_B (INV_B + 128)               // 115,072
#define ATTN_SMEM (MAXP_B + 512)           // 115,584

__device__ __forceinline__ void load_tile64_async(
    u32 dsth, u32 dstl,
    const uint4* __restrict__ srch, const uint4* __restrict__ srcl,
    int tokbase, int t)
{
#pragma unroll
    for (int it = 0; it < 2; it++) {
        int idx = t + it * 256;
        int r = idx >> 3, c = idx & 7;
        u32 off = (u32)(r * 128 + ((c ^ (r & 7)) << 4));
        CP_ASYNC16(dsth + off, srch + (size_t)(tokbase + r) * 8 + c);
        CP_ASYNC16(dstl + off, srcl + (size_t)(tokbase + r) * 8 + c);
    }
    CP_COMMIT();
}

__device__ __forceinline__ void load_v_async(
    u32 dsth, const uint4* __restrict__ srch, int tokbase, int t)
{
#pragma unroll
    for (int it = 0; it < 2; it++) {
        int idx = t + it * 256;
        int r = idx >> 3, c = idx & 7;
        u32 off = (u32)(r * 128 + ((c ^ (r & 7)) << 4));
        CP_ASYNC16(dsth + off, srch + (size_t)(tokbase + r) * 8 + c);
    }
    CP_COMMIT();
}

__global__ __launch_bounds__(256, 2) void attn_kernel(float* __restrict__ attn_out)
{
    extern __shared__ char smc[];
    const u32 smb = smem_u32(smc);
    float* sc = (float*)smc;
    float* inv_s = (float*)(smc + INV_B);
    float* maxp  = (float*)(smc + MAXP_B);

    const int t = threadIdx.x, lane = t & 31, wid = t >> 5;
    const int warpM = wid & 1;
    const int warpN = wid >> 1;
    const int qt = blockIdx.x;
    const int bh = blockIdx.y;
    const int qtok = bh * SEQ + qt * 32;
    const int ktok0 = bh * SEQ;

    {
        int r = t >> 3, c = t & 7;
        uint4 a = g_qh4[(size_t)(qtok + r) * 8 + c];
        uint4 b = g_ql4[(size_t)(qtok + r) * 8 + c];
        u32 off = (u32)(r * 128 + ((c ^ (r & 7)) << 4));
        STS128(smb + ST0_B + off, a.x, a.y, a.z, a.w);
        STS128(smb + ST0_B + 4096 + off, b.x, b.y, b.z, b.w);
    }
    __syncthreads();

    u32 qh[4][4], ql[4][4];
#pragma unroll
    for (int ks = 0; ks < 4; ks++) {
        int row = warpM * 16 + (lane & 15);
        int c = ks * 2 + ((lane >> 4) & 1);
        u32 sw = (u32)(row * 128 + ((c ^ (row & 7)) << 4));
        LDSM4(qh[ks][0], qh[ks][1], qh[ks][2], qh[ks][3], smb + ST0_B + sw);
        LDSM4(ql[ks][0], ql[ks][1], ql[ks][2], ql[ks][3], smb + ST0_B + 4096 + sw);
    }

    load_tile64_async(smb + ST1_B, smb + ST1_B + 8192, g_kh4, g_kl4, ktok0, t);

    float fm[2] = {-1e30f, -1e30f};

    // ================= scores =================
#pragma unroll 1
    for (int kt = 0; kt < 9; kt++) {
        CP_WAIT0();
        __syncthreads();
        if (kt < 9 - 1) {
            u32 nb = smb + (((kt + 1 + 1) & 1) ? ST1_B : ST0_B);
            load_tile64_async(nb, nb + 8192, g_kh4, g_kl4, ktok0 + (kt + 1) * 64, t);
        }
        const u32 kb = smb + (((kt + 1) & 1) ? ST1_B : ST0_B);
        const u32 klb = kb + 8192;

        float acc[2][4];
#pragma unroll
        for (int i = 0; i < 2; i++)
#pragma unroll
            for (int j = 0; j < 4; j++) acc[i][j] = 0.f;

#pragma unroll
        for (int ks = 0; ks < 4; ks++) {
            u32 bh2[2][2], bl2[2][2];
            {
                int row = warpN * 16 + (lane & 7) + ((lane >> 4) & 1) * 8;
                int c = ks * 2 + ((lane >> 3) & 1);
                u32 sw = (u32)(row * 128 + ((c ^ (row & 7)) << 4));
                u32 r0, r1, r2, r3;
                LDSM4(r0, r1, r2, r3, kb + sw);
                bh2[0][0] = r0; bh2[0][1] = r1;
                bh2[1][0] = r2; bh2[1][1] = r3;
                LDSM4(r0, r1, r2, r3, klb + sw);
                bl2[0][0] = r0; bl2[0][1] = r1;
                bl2[1][0] = r2; bl2[1][1] = r3;
            }
#pragma unroll
            for (int nt = 0; nt < 2; nt++) {
                MMA16816(acc[nt], qh[ks], bh2[nt]);
                MMA16816(acc[nt], qh[ks], bl2[nt]);
                MMA16816(acc[nt], ql[ks], bh2[nt]);
            }
        }
#pragma unroll
        for (int nt = 0; nt < 2; nt++)
#pragma unroll
            for (int cc = 0; cc < 2; cc++) {
                fm[cc] = fmaxf(fm[cc], fmaxf(acc[nt][cc * 2], acc[nt][cc * 2 + 1]));
                int r = warpM * 16 + (lane >> 2) + cc * 8;
                int col = kt * 64 + warpN * 16 + nt * 8 + (lane & 3) * 2;
                float2* p = (float2*)(sc + r * SLAB_W + col);
                *p = make_float2(acc[nt][cc * 2] * ATT_SCALE,
                                 acc[nt][cc * 2 + 1] * ATT_SCALE);
            }
    }
#pragma unroll
    for (int cc = 0; cc < 2; cc++) {
        fm[cc] = fmaxf(fm[cc], __shfl_xor_sync(0xffffffffu, fm[cc], 1));
        fm[cc] = fmaxf(fm[cc], __shfl_xor_sync(0xffffffffu, fm[cc], 2));
        if ((lane & 3) == 0) {
            int r = warpM * 16 + (lane >> 2) + cc * 8;
            maxp[warpN * 32 + r] = fm[cc];
        }
    }
    __syncthreads();

    // preload V tile 0 (hi only) into stage0 — overlaps softmax
    load_v_async(smb + ST0_B, g_vh4, ktok0, t);

    // ================= softmax: single pass =================
    {
        for (int rr = 0; rr < 4; rr++) {
            int r = wid * 4 + rr;
            float m = fmaxf(fmaxf(maxp[r], maxp[32 + r]),
                            fmaxf(maxp[64 + r], maxp[96 + r])) * ATT_SCALE;
            float* row = sc + r * SLAB_W;
            float s = 0.f;
            for (int c = lane; c < SEQ; c += 32) {
                float e = __expf(row[c] - m);
                row[c] = e;
                s += e;
            }
#pragma unroll
            for (int off = 16; off > 0; off >>= 1)
                s += __shfl_xor_sync(0xffffffffu, s, off);
            if (lane == 0) inv_s[r] = 1.f / s;
        }
    }

    // pre-pack P chunk 0 into PH buffer 0 (inv_s is warp-local per row)
#pragma unroll
    for (int i = 0; i < 4; i++) {
        int r = wid * 4 + i;
        float inv = inv_s[r];
        float2 e = *(const float2*)(sc + r * SLAB_W + lane * 2);
        float p0 = e.x * inv, p1 = e.y * inv;
        size_t arow = ((size_t)bh * SEQ + (size_t)(qt * 32 + r)) * SEQ;
        *(float2*)(attn_out + arow + lane * 2) = make_float2(p0, p1);
        u32 off = (u32)(r * 128 + (((lane >> 2) ^ (r & 7)) << 4) + (lane & 3) * 4);
        *(u32*)(smc + PH_B + off) = pack_hi(p0, p1);
    }

    // ================= P @ V (pipelined: pack(kt+1) overlaps MMA(kt)) ====
    float acc2[2][4];
#pragma unroll
    for (int i = 0; i < 2; i++)
#pragma unroll
        for (int j = 0; j < 4; j++) acc2[i][j] = 0.f;

#pragma unroll 1
    for (int kt = 0; kt < 9; kt++) {
        CP_WAIT0();
        __syncthreads();   // V(kt) visible; PH(kt) packed by all warps;
                           // V stage (kt+1)&1 and PH (kt+1)&1 free
        if (kt < 9 - 1) {
            u32 nb = smb + (((kt + 1) & 1) ? ST1_B : ST0_B);
            load_v_async(nb, g_vh4, ktok0 + (kt + 1) * 64, t);
            // pack P(kt+1) into the spare PH buffer (overlaps MMA below)
#pragma unroll
            for (int i = 0; i < 4; i++) {
                int r = wid * 4 + i;
                float inv = inv_s[r];
                float2 e = *(const float2*)(sc + r * SLAB_W + (kt + 1) * 64 + lane * 2);
                float p0 = e.x * inv, p1 = e.y * inv;
                size_t arow = ((size_t)bh * SEQ + (size_t)(qt * 32 + r)) * SEQ;
                *(float2*)(attn_out + arow + (kt + 1) * 64 + lane * 2) =
                    make_float2(p0, p1);
                u32 off = (u32)(r * 128 + (((lane >> 2) ^ (r & 7)) << 4) + (lane & 3) * 4);
                *(u32*)(smc + PH_B + ((kt + 1) & 1) * 4096 + off) = pack_hi(p0, p1);
            }
        }

        const u32 phb = smb + PH_B + (kt & 1) * 4096;
        const u32 vb2 = smb + ((kt & 1) ? ST1_B : ST0_B);

#pragma unroll
        for (int ks = 0; ks < 4; ks++) {
            u32 ph[4];
            {
                int row = warpM * 16 + (lane & 15);
                int c = ks * 2 + ((lane >> 4) & 1);
                u32 sw = (u32)(row * 128 + ((c ^ (row & 7)) << 4));
                LDSM4(ph[0], ph[1], ph[2], ph[3], phb + sw);
            }
            u32 vh[2][2];
            {
                int m = lane >> 3;
                int row_s = ks * 16 + ((m & 1) << 3) + (lane & 7);
                int chunk = warpN * 2 + (m >> 1);
                u32 sw = (u32)(row_s * 128 + ((chunk ^ (row_s & 7)) << 4));
                u32 r0, r1, r2, r3;
                LDSM4T(r0, r1, r2, r3, vb2 + sw);
                vh[0][0] = r0; vh[0][1] = r1;
                vh[1][0] = r2; vh[1][1] = r3;
            }
#pragma unroll
            for (int nt = 0; nt < 2; nt++) {
                MMA16816(acc2[nt], ph, vh[nt]);
            }
        }
    }

    // ================= ctx epilogue (fp16 hi only) =================
    const int bb = bh / NH, h = bh % NH;
    u32* ch = (u32*)g_chi4;
#pragma unroll
    for (int nt = 0; nt < 2; nt++)
#pragma unroll
        for (int cc = 0; cc < 2; cc++) {
            int r = warpM * 16 + (lane >> 2) + cc * 8;
            int d = warpN * 16 + nt * 8 + (lane & 3) * 2;
            size_t n = (size_t)bb * SEQ + (size_t)(qt * 32 + r);
            size_t idx = n * EMBD + h * 64 + d;
            ch[idx >> 1] = pack_hi(acc2[nt][cc * 2], acc2[nt][cc * 2 + 1]);
        }
}

// =====================================================================
// launch
// =====================================================================
extern "C" void kernel_launch(void* const* d_in, const int* in_sizes, int n_in,
                              void* d_out, int out_size)
{
    const float* hs = (const float*)d_in[0];
    const float* qw = (const float*)d_in[1];
    const float* qb = (const float*)d_in[2];
    const float* kw = (const float*)d_in[3];
    const float* kb = (const float*)d_in[4];
    const float* vw = (const float*)d_in[5];
    const float* vb = (const float*)d_in[6];
    const float* ow = (const float*)d_in[7];
    const float* ob = (const float*)d_in[8];

    float* out  = (float*)d_out;
    float* attn = out + OUT_ELEMS;

    cudaFuncSetAttribute(qk_fused_kernel, cudaFuncAttributeMaxDynamicSharedMemorySize,
                         QK_SMEM);
    cudaFuncSetAttribute(mm_hmma_kernel, cudaFuncAttributeMaxDynamicSharedMemorySize,
                         MM_SMEM);
    cudaFuncSetAttribute(attn_kernel, cudaFuncAttributeMaxDynamicSharedMemorySize,
                         ATTN_SMEM);

    conv_x_kernel<<<(NT * EMBD / 8 + 255) / 256, 256>>>(hs);
    conv_w_kernel<<<dim3((EMBD * EMBD / 8 + 255) / 256, 4), 256>>>(qw, kw, vw, ow);

    qk_fused_kernel<<<dim3(EMBD / 64, NT / 128), 256, QK_SMEM>>>(qb, kb);
    mm_hmma_kernel<<<dim3(EMBD / 64, NT / 128, 1), 256, MM_SMEM>>>(
        qb, kb, vb, ob, out, 2);

    attn_kernel<<<dim3(18, BATCH * NH), 256, ATTN_SMEM>>>(attn);

    mm_hmma_kernel<<<dim3(EMBD / 64, NT / 128, 1), 256, MM_SMEM>>>(
        qb, kb, vb, ob, out, 3);
}

// round 13
// speedup vs baseline: 2.9466x; 1.0006x over previous
#include <cuda_runtime.h>
#include <cuda_fp16.h>

// ---------------- problem constants ----------------
#define BATCH 32
#define SEQ   576
#define EMBD  768
#define NH    12
#define HD    64
#define NT    (BATCH * SEQ)
#define OUT_ELEMS ((size_t)NT * EMBD)
#define ATT_SCALE 0.125f
#define KCHUNKS 24

typedef unsigned int u32;
typedef unsigned short u16;

// ---------------- device scratch ----------------
__device__ uint4 g_xhi4[NT * EMBD / 8];
__device__ uint4 g_xlo4[NT * EMBD / 8];
__device__ uint4 g_whi4[4 * EMBD * EMBD / 8];
__device__ uint4 g_wlo4[4 * EMBD * EMBD / 8];
__device__ uint4 g_chi4[NT * EMBD / 8];          // ctx hi only ([N, EMB], fp16)
__device__ uint4 g_qh4[NT * EMBD / 8];           // [B,H,S,D] fp16 hi/lo
__device__ uint4 g_ql4[NT * EMBD / 8];
__device__ uint4 g_kh4[NT * EMBD / 8];
__device__ uint4 g_kl4[NT * EMBD / 8];
__device__ uint4 g_vh4[NT * EMBD / 8];           // V hi only

// ---------------- helpers ----------------
__device__ __forceinline__ u32 smem_u32(const void* p) {
    u32 a;
    asm("{ .reg .u64 t; cvta.to.shared.u64 t, %1; cvt.u32.u64 %0, t; }"
        : "=r"(a) : "l"(p));
    return a;
}

#define CP_ASYNC16(dst, src) \
    asm volatile("cp.async.cg.shared.global [%0], [%1], 16;" \
                 :: "r"(dst), "l"(src) : "memory")
#define CP_COMMIT() asm volatile("cp.async.commit_group;" ::: "memory")
#define CP_WAIT2()  asm volatile("cp.async.wait_group 2;" ::: "memory")
#define CP_WAIT1()  asm volatile("cp.async.wait_group 1;" ::: "memory")
#define CP_WAIT0()  asm volatile("cp.async.wait_group 0;" ::: "memory")

#define LDSM4(r0, r1, r2, r3, addr) \
    asm volatile("ldmatrix.sync.aligned.m8n8.x4.shared.b16 {%0,%1,%2,%3}, [%4];" \
                 : "=r"(r0), "=r"(r1), "=r"(r2), "=r"(r3) : "r"(addr))
#define LDSM4T(r0, r1, r2, r3, addr) \
    asm volatile("ldmatrix.sync.aligned.m8n8.x4.trans.shared.b16 {%0,%1,%2,%3}, [%4];" \
                 : "=r"(r0), "=r"(r1), "=r"(r2), "=r"(r3) : "r"(addr))

#define MMA16816(d, a, b) \
    asm volatile("mma.sync.aligned.m16n8k16.row.col.f32.f16.f16.f32 " \
                 "{%0,%1,%2,%3}, {%4,%5,%6,%7}, {%8,%9}, {%0,%1,%2,%3};" \
                 : "+f"((d)[0]), "+f"((d)[1]), "+f"((d)[2]), "+f"((d)[3]) \
                 : "r"((a)[0]), "r"((a)[1]), "r"((a)[2]), "r"((a)[3]), \
                   "r"((b)[0]), "r"((b)[1]))

#define STS128(addr, a, b, c, d) \
    asm volatile("st.shared.v4.b32 [%0], {%1, %2, %3, %4};" \
                 :: "r"(addr), "r"(a), "r"(b), "r"(c), "r"(d) : "memory")

__device__ __forceinline__ void pack_hilo(float v0, float v1, u32& hp, u32& lp) {
    __half h0 = __float2half_rn(v0);
    __half h1 = __float2half_rn(v1);
    __half l0 = __float2half_rn(v0 - __half2float(h0));
    __half l1 = __float2half_rn(v1 - __half2float(h1));
    hp = (u32)*(u16*)&h0 | ((u32)*(u16*)&h1 << 16);
    lp = (u32)*(u16*)&l0 | ((u32)*(u16*)&l1 << 16);
}
__device__ __forceinline__ u32 pack_hi(float v0, float v1) {
    __half h0 = __float2half_rn(v0);
    __half h1 = __float2half_rn(v1);
    return (u32)*(u16*)&h0 | ((u32)*(u16*)&h1 << 16);
}

// =====================================================================
// hi/lo split conversion (fp16)
// =====================================================================
__device__ __forceinline__ void conv8(const float4* src2, uint4* hi, uint4* lo) {
    float4 a = src2[0], b = src2[1];
    float f[8] = {a.x, a.y, a.z, a.w, b.x, b.y, b.z, b.w};
    union { uint4 v; __half h[8]; } H, L;
#pragma unroll
    for (int j = 0; j < 8; j++) {
        __half hh = __float2half_rn(f[j]);
        H.h[j] = hh;
        L.h[j] = __float2half_rn(f[j] - __half2float(hh));
    }
    *hi = H.v; *lo = L.v;
}

__global__ __launch_bounds__(256) void conv_x_kernel(const float* __restrict__ src) {
    int i = blockIdx.x * blockDim.x + threadIdx.x;
    if (i >= NT * EMBD / 8) return;
    conv8((const float4*)src + 2 * (size_t)i, &g_xhi4[i], &g_xlo4[i]);
}

__global__ __launch_bounds__(256) void conv_w_kernel(
    const float* __restrict__ qw, const float* __restrict__ kw,
    const float* __restrict__ vw, const float* __restrict__ ow) {
    int z = blockIdx.y;
    const float* src = z == 0 ? qw : z == 1 ? kw : z == 2 ? vw : ow;
    int i = blockIdx.x * blockDim.x + threadIdx.x;
    if (i >= EMBD * EMBD / 8) return;
    int di = z * (EMBD * EMBD / 8) + i;
    conv8((const float4*)src + 2 * (size_t)i, &g_whi4[di], &g_wlo4[di]);
}

// =====================================================================
// Fused Q+K projection (3-term each), 3-stage pipeline.
// =====================================================================
#define QK_STAGE 32768
#define QK_SMEM (3 * QK_STAGE + 1024)

__global__ __launch_bounds__(256, 2) void qk_fused_kernel(
    const float* __restrict__ qb, const float* __restrict__ kb)
{
    extern __shared__ char smraw[];
    const u32 smbase = smem_u32(smraw);
    float* bias_s = (float*)(smraw + 3 * QK_STAGE);   // [2][64]

    const int t = threadIdx.x, lane = t & 31, wid = t >> 5;
    const int warpM = wid & 3;
    const int warpN = wid >> 2;
    const int o0 = blockIdx.x * 64;
    const int n0 = blockIdx.y * 128;

    if (t < 64) bias_s[t] = qb[o0 + t];
    else if (t < 128) bias_s[t] = kb[o0 + t - 64];

    const int lr   = t >> 1;
    const int half = t & 1;
    const uint4* srcA = (half ? g_xlo4 : g_xhi4) + (size_t)(n0 + lr) * 96;
    const u32 arow_sw[4] = {
        (u32)(lr * 128 + (((half * 4 + 0) ^ (lr & 7)) << 4)),
        (u32)(lr * 128 + (((half * 4 + 1) ^ (lr & 7)) << 4)),
        (u32)(lr * 128 + (((half * 4 + 2) ^ (lr & 7)) << 4)),
        (u32)(lr * 128 + (((half * 4 + 3) ^ (lr & 7)) << 4))
    };
    u32 wdst[4];
    const uint4* srcW[4];
#pragma unroll
    for (int j = 0; j < 4; j++) {
        int idx = t + j * 256;
        int mw = idx >> 9;
        int within = idx & 511;
        int row = within >> 3, rem = within & 7;
        int wh = rem >> 2, g = rem & 3;
        wdst[j] = (u32)(16384 + mw * 8192 + row * 128 + (((wh * 4 + g) ^ (row & 7)) << 4));
        srcW[j] = (wh ? g_wlo4 : g_whi4) + (size_t)mw * (EMBD * EMBD / 8)
                  + (size_t)(o0 + row) * 96 + g;
    }

    float accQ[2][4][4], accK[2][4][4];
#pragma unroll
    for (int i = 0; i < 2; i++)
#pragma unroll
        for (int j = 0; j < 4; j++)
#pragma unroll
            for (int c = 0; c < 4; c++) { accQ[i][j][c] = 0.f; accK[i][j][c] = 0.f; }

#pragma unroll
    for (int pc = 0; pc < 2; pc++) {
        const u32 st = smbase + pc * QK_STAGE;
        const int ko = pc * 4;
#pragma unroll
        for (int g = 0; g < 4; g++) CP_ASYNC16(st + arow_sw[g], srcA + ko + g);
#pragma unroll
        for (int j = 0; j < 4; j++) CP_ASYNC16(st + wdst[j], srcW[j] + ko);
        CP_COMMIT();
    }

#pragma unroll 1
    for (int kc = 0; kc < KCHUNKS; kc++) {
        if (kc == KCHUNKS - 1) { CP_WAIT0(); } else { CP_WAIT1(); }
        __syncthreads();
        if (kc + 2 < KCHUNKS) {
            int nc = kc + 2;
            const u32 st = smbase + (nc % 3) * QK_STAGE;
            const int ko = nc * 4;
#pragma unroll
            for (int g = 0; g < 4; g++) CP_ASYNC16(st + arow_sw[g], srcA + ko + g);
#pragma unroll
            for (int j = 0; j < 4; j++) CP_ASYNC16(st + wdst[j], srcW[j] + ko);
            CP_COMMIT();
        }

        const u32 Ab  = smbase + (kc % 3) * QK_STAGE;
        const u32 WqB = Ab + 16384;
        const u32 WkB = Ab + 16384 + 8192;

#pragma unroll
        for (int ks = 0; ks < 2; ks++) {
            u32 ah[2][4], al[2][4];
#pragma unroll
            for (int mt = 0; mt < 2; mt++) {
                int row = warpM * 32 + mt * 16 + (lane & 15);
                int c = ks * 2 + ((lane >> 4) & 1);
                u32 base = Ab + row * 128;
                LDSM4(ah[mt][0], ah[mt][1], ah[mt][2], ah[mt][3],
                      base + (((c) ^ (row & 7)) << 4));
                LDSM4(al[mt][0], al[mt][1], al[mt][2], al[mt][3],
                      base + (((c + 4) ^ (row & 7)) << 4));
            }
            {
                u32 bh[4][2], bl[4][2];
#pragma unroll
                for (int bt = 0; bt < 2; bt++) {
                    int row = warpN * 32 + bt * 16 + (lane & 7) + ((lane >> 4) & 1) * 8;
                    int c = ks * 2 + ((lane >> 3) & 1);
                    u32 base = WqB + row * 128;
                    u32 r0, r1, r2, r3;
                    LDSM4(r0, r1, r2, r3, base + (((c) ^ (row & 7)) << 4));
                    bh[bt * 2][0] = r0; bh[bt * 2][1] = r1;
                    bh[bt * 2 + 1][0] = r2; bh[bt * 2 + 1][1] = r3;
                    LDSM4(r0, r1, r2, r3, base + (((c + 4) ^ (row & 7)) << 4));
                    bl[bt * 2][0] = r0; bl[bt * 2][1] = r1;
                    bl[bt * 2 + 1][0] = r2; bl[bt * 2 + 1][1] = r3;
                }
#pragma unroll
                for (int mt = 0; mt < 2; mt++)
#pragma unroll
                    for (int nt = 0; nt < 4; nt++) {
                        MMA16816(accQ[mt][nt], ah[mt], bh[nt]);
                        MMA16816(accQ[mt][nt], ah[mt], bl[nt]);
                        MMA16816(accQ[mt][nt], al[mt], bh[nt]);
                    }
            }
            {
                u32 bh[4][2], bl[4][2];
#pragma unroll
                for (int bt = 0; bt < 2; bt++) {
                    int row = warpN * 32 + bt * 16 + (lane & 7) + ((lane >> 4) & 1) * 8;
                    int c = ks * 2 + ((lane >> 3) & 1);
                    u32 base = WkB + row * 128;
                    u32 r0, r1, r2, r3;
                    LDSM4(r0, r1, r2, r3, base + (((c) ^ (row & 7)) << 4));
                    bh[bt * 2][0] = r0; bh[bt * 2][1] = r1;
                    bh[bt * 2 + 1][0] = r2; bh[bt * 2 + 1][1] = r3;
                    LDSM4(r0, r1, r2, r3, base + (((c + 4) ^ (row & 7)) << 4));
                    bl[bt * 2][0] = r0; bl[bt * 2][1] = r1;
                    bl[bt * 2 + 1][0] = r2; bl[bt * 2 + 1][1] = r3;
                }
#pragma unroll
                for (int mt = 0; mt < 2; mt++)
#pragma unroll
                    for (int nt = 0; nt < 4; nt++) {
                        MMA16816(accK[mt][nt], ah[mt], bh[nt]);
                        MMA16816(accK[mt][nt], ah[mt], bl[nt]);
                        MMA16816(accK[mt][nt], al[mt], bh[nt]);
                    }
            }
        }
    }

    const int h = blockIdx.x;
    u32* qh_d = (u32*)g_qh4; u32* ql_d = (u32*)g_ql4;
    u32* kh_d = (u32*)g_kh4; u32* kl_d = (u32*)g_kl4;
#pragma unroll
    for (int mt = 0; mt < 2; mt++)
#pragma unroll
        for (int nt = 0; nt < 4; nt++)
#pragma unroll
            for (int cc = 0; cc < 2; cc++) {
                int rl = warpM * 32 + mt * 16 + (lane >> 2) + cc * 8;
                int cl = warpN * 32 + nt * 8 + (lane & 3) * 2;
                int n = n0 + rl;
                int bb = n / SEQ, ss = n - bb * SEQ;
                size_t idx = ((((size_t)bb * NH + h) * SEQ + ss) * HD + cl);
                {
                    float v0 = accQ[mt][nt][cc * 2 + 0] + bias_s[cl];
                    float v1 = accQ[mt][nt][cc * 2 + 1] + bias_s[cl + 1];
                    u32 hp, lp; pack_hilo(v0, v1, hp, lp);
                    qh_d[idx >> 1] = hp; ql_d[idx >> 1] = lp;
                }
                {
                    float v0 = accK[mt][nt][cc * 2 + 0] + bias_s[64 + cl];
                    float v1 = accK[mt][nt][cc * 2 + 1] + bias_s[64 + cl + 1];
                    u32 hp, lp; pack_hilo(v0, v1, hp, lp);
                    kh_d[idx >> 1] = hp; kl_d[idx >> 1] = lp;
                }
            }
}

// =====================================================================
// HMMA split-fp16 GEMM (V and O modes), CTA tile 128x64, 4-stage.
// =====================================================================
#define STAGE_BYTES 24576            // A 16K + W 8K
#define MM_SMEM (4 * STAGE_BYTES + 512)

__global__ __launch_bounds__(256, 2) void mm_hmma_kernel(
    const float* __restrict__ qb, const float* __restrict__ kb,
    const float* __restrict__ vb, const float* __restrict__ ob,
    float* __restrict__ outp, int mode_base)
{
    extern __shared__ char smraw[];
    const u32 smbase = smem_u32(smraw);
    float* bias_s = (float*)(smraw + 4 * STAGE_BYTES);

    const int t = threadIdx.x, lane = t & 31, wid = t >> 5;
    const int warpM = wid & 3;
    const int warpN = wid >> 2;
    const int mode = mode_base + blockIdx.z;
    const bool need3 = (mode < 2);
    const int o0 = blockIdx.x * 64;
    const int n0 = blockIdx.y * 128;

    const float* bias = mode == 0 ? qb : mode == 1 ? kb : mode == 2 ? vb : ob;
    const uint4* AhiG = (mode < 3) ? g_xhi4 : g_chi4;
    const uint4* AloG = g_xlo4;
    const size_t woff = (size_t)(mode < 3 ? mode : 3) * (EMBD * EMBD / 8);

    if (t < 64) bias_s[t] = bias[o0 + t];

    const int lr   = t >> 1;
    const int half = t & 1;
    const bool loadA = need3 || (half == 0);
    const uint4* srcA = (half ? AloG : AhiG) + (size_t)(n0 + lr) * 96;
    const u32 arow_sw[4] = {
        (u32)(lr * 128 + (((half * 4 + 0) ^ (lr & 7)) << 4)),
        (u32)(lr * 128 + (((half * 4 + 1) ^ (lr & 7)) << 4)),
        (u32)(lr * 128 + (((half * 4 + 2) ^ (lr & 7)) << 4)),
        (u32)(lr * 128 + (((half * 4 + 3) ^ (lr & 7)) << 4))
    };
    u32 wdst[2];
    const uint4* srcW[2];
#pragma unroll
    for (int j = 0; j < 2; j++) {
        int idx = t + j * 256;
        int row = idx >> 3, rem = idx & 7;
        int wh = rem >> 2, g = rem & 3;
        wdst[j] = (u32)(row * 128 + (((wh * 4 + g) ^ (row & 7)) << 4));
        srcW[j] = (wh ? g_wlo4 : g_whi4) + woff + (size_t)(o0 + row) * 96 + g;
    }

    float acc[2][4][4];
#pragma unroll
    for (int i = 0; i < 2; i++)
#pragma unroll
        for (int j = 0; j < 4; j++)
#pragma unroll
            for (int c = 0; c < 4; c++) acc[i][j][c] = 0.f;

    // prefetch chunks 0..2
#pragma unroll
    for (int pc = 0; pc < 3; pc++) {
        const u32 st = smbase + pc * STAGE_BYTES;
        const int ko = pc * 4;
#pragma unroll
        for (int g = 0; g < 4; g++)
            if (loadA) CP_ASYNC16(st + arow_sw[g], srcA + ko + g);
#pragma unroll
        for (int j = 0; j < 2; j++)
            CP_ASYNC16(st + 16384 + wdst[j], srcW[j] + ko);
        CP_COMMIT();
    }

#pragma unroll 1
    for (int kc = 0; kc < KCHUNKS; kc++) {
        int rem = KCHUNKS - 1 - kc;
        if (rem >= 2)      { CP_WAIT2(); }
        else if (rem == 1) { CP_WAIT1(); }
        else               { CP_WAIT0(); }
        __syncthreads();
        if (kc + 3 < KCHUNKS) {
            int nc = kc + 3;
            const u32 st = smbase + (nc & 3) * STAGE_BYTES;
            const int ko = nc * 4;
#pragma unroll
            for (int g = 0; g < 4; g++)
                if (loadA) CP_ASYNC16(st + arow_sw[g], srcA + ko + g);
#pragma unroll
            for (int j = 0; j < 2; j++)
                CP_ASYNC16(st + 16384 + wdst[j], srcW[j] + ko);
            CP_COMMIT();
        }

        const u32 Ab = smbase + (kc & 3) * STAGE_BYTES;
        const u32 Wb = Ab + 16384;

#pragma unroll
        for (int ks = 0; ks < 2; ks++) {
            u32 ah[2][4], al[2][4];
#pragma unroll
            for (int mt = 0; mt < 2; mt++) {
                int row = warpM * 32 + mt * 16 + (lane & 15);
                int c = ks * 2 + ((lane >> 4) & 1);
                u32 base = Ab + row * 128;
                LDSM4(ah[mt][0], ah[mt][1], ah[mt][2], ah[mt][3],
                      base + (((c) ^ (row & 7)) << 4));
                if (need3)
                    LDSM4(al[mt][0], al[mt][1], al[mt][2], al[mt][3],
                          base + (((c + 4) ^ (row & 7)) << 4));
            }
            u32 bh[4][2], bl[4][2];
#pragma unroll
            for (int bt = 0; bt < 2; bt++) {
                int row = warpN * 32 + bt * 16 + (lane & 7) + ((lane >> 4) & 1) * 8;
                int c = ks * 2 + ((lane >> 3) & 1);
                u32 base = Wb + row * 128;
                u32 r0, r1, r2, r3;
                LDSM4(r0, r1, r2, r3, base + (((c) ^ (row & 7)) << 4));
                bh[bt * 2][0] = r0; bh[bt * 2][1] = r1;
                bh[bt * 2 + 1][0] = r2; bh[bt * 2 + 1][1] = r3;
                LDSM4(r0, r1, r2, r3, base + (((c + 4) ^ (row & 7)) << 4));
                bl[bt * 2][0] = r0; bl[bt * 2][1] = r1;
                bl[bt * 2 + 1][0] = r2; bl[bt * 2 + 1][1] = r3;
            }
#pragma unroll
            for (int mt = 0; mt < 2; mt++)
#pragma unroll
                for (int nt = 0; nt < 4; nt++) {
                    MMA16816(acc[mt][nt], ah[mt], bh[nt]);
                    MMA16816(acc[mt][nt], ah[mt], bl[nt]);
                    if (need3) MMA16816(acc[mt][nt], al[mt], bh[nt]);
                }
        }
    }

    u32* dsth = (u32*)(mode == 0 ? g_qh4 : mode == 1 ? g_kh4 : g_vh4);
    u32* dstl = (u32*)(mode == 0 ? g_ql4 : g_kl4);
    const int h = blockIdx.x;
#pragma unroll
    for (int mt = 0; mt < 2; mt++)
#pragma unroll
        for (int nt = 0; nt < 4; nt++)
#pragma unroll
            for (int cc = 0; cc < 2; cc++) {
                int rl = warpM * 32 + mt * 16 + (lane >> 2) + cc * 8;
                int cl = warpN * 32 + nt * 8 + (lane & 3) * 2;
                float v0 = acc[mt][nt][cc * 2 + 0] + bias_s[cl];
                float v1 = acc[mt][nt][cc * 2 + 1] + bias_s[cl + 1];
                int n = n0 + rl;
                if (mode < 3) {
                    int bb = n / SEQ, ss = n - bb * SEQ;
                    size_t idx = ((((size_t)bb * NH + h) * SEQ + ss) * HD + cl);
                    u32 hp, lp; pack_hilo(v0, v1, hp, lp);
                    dsth[idx >> 1] = hp;
                    if (mode != 2) dstl[idx >> 1] = lp;
                } else {
                    float2* p = (float2*)(outp + (size_t)n * EMBD + o0 + cl);
                    *p = make_float2(v0, v1);
                }
            }
}

// =====================================================================
// HMMA attention, 32-row q tiles, 2 CTAs/SM.
// PV phase software-pipelined with double-buffered PH tiles (1 sync/iter).
// SLAB_W = 578 (even, keeps float2 slab accesses 8B-aligned).
// =====================================================================
#define SLAB_W 578
#define SC_B   0
#define ST0_B  (32 * SLAB_W * 4)           // 73,984
#define ST1_B  (ST0_B + 16384)             // 90,368
#define PH_B   (ST1_B + 16384)             // 106,752 (2 x 4096)
#define INV_B  (PH_B + 8192)               // 114,944
#define MAXP_B (INV_B + 128)               // 115,072
#define ATTN_SMEM (MAXP_B + 512)           // 115,584

__device__ __forceinline__ void load_tile64_async(
    u32 dsth, u32 dstl,
    const uint4* __restrict__ srch, const uint4* __restrict__ srcl,
    int tokbase, int t)
{
#pragma unroll
    for (int it = 0; it < 2; it++) {
        int idx = t + it * 256;
        int r = idx >> 3, c = idx & 7;
        u32 off = (u32)(r * 128 + ((c ^ (r & 7)) << 4));
        CP_ASYNC16(dsth + off, srch + (size_t)(tokbase + r) * 8 + c);
        CP_ASYNC16(dstl + off, srcl + (size_t)(tokbase + r) * 8 + c);
    }
    CP_COMMIT();
}

__device__ __forceinline__ void load_v_async(
    u32 dsth, const uint4* __restrict__ srch, int tokbase, int t)
{
#pragma unroll
    for (int it = 0; it < 2; it++) {
        int idx = t + it * 256;
        int r = idx >> 3, c = idx & 7;
        u32 off = (u32)(r * 128 + ((c ^ (r & 7)) << 4));
        CP_ASYNC16(dsth + off, srch + (size_t)(tokbase + r) * 8 + c);
    }
    CP_COMMIT();
}

__global__ __launch_bounds__(256, 2) void attn_kernel(float* __restrict__ attn_out)
{
    extern __shared__ char smc[];
    const u32 smb = smem_u32(smc);
    float* sc = (float*)smc;
    float* inv_s = (float*)(smc + INV_B);
    float* maxp  = (float*)(smc + MAXP_B);

    const int t = threadIdx.x, lane = t & 31, wid = t >> 5;
    const int warpM = wid & 1;
    const int warpN = wid >> 1;
    const int qt = blockIdx.x;
    const int bh = blockIdx.y;
    const int qtok = bh * SEQ + qt * 32;
    const int ktok0 = bh * SEQ;

    {
        int r = t >> 3, c = t & 7;
        uint4 a = g_qh4[(size_t)(qtok + r) * 8 + c];
        uint4 b = g_ql4[(size_t)(qtok + r) * 8 + c];
        u32 off = (u32)(r * 128 + ((c ^ (r & 7)) << 4));
        STS128(smb + ST0_B + off, a.x, a.y, a.z, a.w);
        STS128(smb + ST0_B + 4096 + off, b.x, b.y, b.z, b.w);
    }
    __syncthreads();

    u32 qh[4][4], ql[4][4];
#pragma unroll
    for (int ks = 0; ks < 4; ks++) {
        int row = warpM * 16 + (lane & 15);
        int c = ks * 2 + ((lane >> 4) & 1);
        u32 sw = (u32)(row * 128 + ((c ^ (row & 7)) << 4));
        LDSM4(qh[ks][0], qh[ks][1], qh[ks][2], qh[ks][3], smb + ST0_B + sw);
        LDSM4(ql[ks][0], ql[ks][1], ql[ks][2], ql[ks][3], smb + ST0_B + 4096 + sw);
    }

    load_tile64_async(smb + ST1_B, smb + ST1_B + 8192, g_kh4, g_kl4, ktok0, t);

    float fm[2] = {-1e30f, -1e30f};

    // ================= scores =================
#pragma unroll 1
    for (int kt = 0; kt < 9; kt++) {
        CP_WAIT0();
        __syncthreads();
        if (kt < 9 - 1) {
            u32 nb = smb + (((kt + 1 + 1) & 1) ? ST1_B : ST0_B);
            load_tile64_async(nb, nb + 8192, g_kh4, g_kl4, ktok0 + (kt + 1) * 64, t);
        }
        const u32 kb = smb + (((kt + 1) & 1) ? ST1_B : ST0_B);
        const u32 klb = kb + 8192;

        float acc[2][4];
#pragma unroll
        for (int i = 0; i < 2; i++)
#pragma unroll
            for (int j = 0; j < 4; j++) acc[i][j] = 0.f;

#pragma unroll
        for (int ks = 0; ks < 4; ks++) {
            u32 bh2[2][2], bl2[2][2];
            {
                int row = warpN * 16 + (lane & 7) + ((lane >> 4) & 1) * 8;
                int c = ks * 2 + ((lane >> 3) & 1);
                u32 sw = (u32)(row * 128 + ((c ^ (row & 7)) << 4));
                u32 r0, r1, r2, r3;
                LDSM4(r0, r1, r2, r3, kb + sw);
                bh2[0][0] = r0; bh2[0][1] = r1;
                bh2[1][0] = r2; bh2[1][1] = r3;
                LDSM4(r0, r1, r2, r3, klb + sw);
                bl2[0][0] = r0; bl2[0][1] = r1;
                bl2[1][0] = r2; bl2[1][1] = r3;
            }
#pragma unroll
            for (int nt = 0; nt < 2; nt++) {
                MMA16816(acc[nt], qh[ks], bh2[nt]);
                MMA16816(acc[nt], qh[ks], bl2[nt]);
                MMA16816(acc[nt], ql[ks], bh2[nt]);
            }
        }
#pragma unroll
        for (int nt = 0; nt < 2; nt++)
#pragma unroll
            for (int cc = 0; cc < 2; cc++) {
                fm[cc] = fmaxf(fm[cc], fmaxf(acc[nt][cc * 2], acc[nt][cc * 2 + 1]));
                int r = warpM * 16 + (lane >> 2) + cc * 8;
                int col = kt * 64 + warpN * 16 + nt * 8 + (lane & 3) * 2;
                float2* p = (float2*)(sc + r * SLAB_W + col);
                *p = make_float2(acc[nt][cc * 2] * ATT_SCALE,
                                 acc[nt][cc * 2 + 1] * ATT_SCALE);
            }
    }
#pragma unroll
    for (int cc = 0; cc < 2; cc++) {
        fm[cc] = fmaxf(fm[cc], __shfl_xor_sync(0xffffffffu, fm[cc], 1));
        fm[cc] = fmaxf(fm[cc], __shfl_xor_sync(0xffffffffu, fm[cc], 2));
        if ((lane & 3) == 0) {
            int r = warpM * 16 + (lane >> 2) + cc * 8;
            maxp[warpN * 32 + r] = fm[cc];
        }
    }
    __syncthreads();

    // preload V tile 0 (hi only) into stage0 — overlaps softmax
    load_v_async(smb + ST0_B, g_vh4, ktok0, t);

    // ================= softmax: single pass =================
    {
        for (int rr = 0; rr < 4; rr++) {
            int r = wid * 4 + rr;
            float m = fmaxf(fmaxf(maxp[r], maxp[32 + r]),
                            fmaxf(maxp[64 + r], maxp[96 + r])) * ATT_SCALE;
            float* row = sc + r * SLAB_W;
            float s = 0.f;
            for (int c = lane; c < SEQ; c += 32) {
                float e = __expf(row[c] - m);
                row[c] = e;
                s += e;
            }
#pragma unroll
            for (int off = 16; off > 0; off >>= 1)
                s += __shfl_xor_sync(0xffffffffu, s, off);
            if (lane == 0) inv_s[r] = 1.f / s;
        }
    }

    // pre-pack P chunk 0 into PH buffer 0 (inv_s is warp-local per row)
#pragma unroll
    for (int i = 0; i < 4; i++) {
        int r = wid * 4 + i;
        float inv = inv_s[r];
        float2 e = *(const float2*)(sc + r * SLAB_W + lane * 2);
        float p0 = e.x * inv, p1 = e.y * inv;
        size_t arow = ((size_t)bh * SEQ + (size_t)(qt * 32 + r)) * SEQ;
        *(float2*)(attn_out + arow + lane * 2) = make_float2(p0, p1);
        u32 off = (u32)(r * 128 + (((lane >> 2) ^ (r & 7)) << 4) + (lane & 3) * 4);
        *(u32*)(smc + PH_B + off) = pack_hi(p0, p1);
    }

    // ================= P @ V (pipelined: pack(kt+1) overlaps MMA(kt)) ====
    float acc2[2][4];
#pragma unroll
    for (int i = 0; i < 2; i++)
#pragma unroll
        for (int j = 0; j < 4; j++) acc2[i][j] = 0.f;

#pragma unroll 1
    for (int kt = 0; kt < 9; kt++) {
        CP_WAIT0();
        __syncthreads();   // V(kt) visible; PH(kt) packed by all warps;
                           // V stage (kt+1)&1 and PH (kt+1)&1 free
        if (kt < 9 - 1) {
            u32 nb = smb + (((kt + 1) & 1) ? ST1_B : ST0_B);
            load_v_async(nb, g_vh4, ktok0 + (kt + 1) * 64, t);
            // pack P(kt+1) into the spare PH buffer (overlaps MMA below)
#pragma unroll
            for (int i = 0; i < 4; i++) {
                int r = wid * 4 + i;
                float inv = inv_s[r];
                float2 e = *(const float2*)(sc + r * SLAB_W + (kt + 1) * 64 + lane * 2);
                float p0 = e.x * inv, p1 = e.y * inv;
                size_t arow = ((size_t)bh * SEQ + (size_t)(qt * 32 + r)) * SEQ;
                *(float2*)(attn_out + arow + (kt + 1) * 64 + lane * 2) =
                    make_float2(p0, p1);
                u32 off = (u32)(r * 128 + (((lane >> 2) ^ (r & 7)) << 4) + (lane & 3) * 4);
                *(u32*)(smc + PH_B + ((kt + 1) & 1) * 4096 + off) = pack_hi(p0, p1);
            }
        }

        const u32 phb = smb + PH_B + (kt & 1) * 4096;
        const u32 vb2 = smb + ((kt & 1) ? ST1_B : ST0_B);

#pragma unroll
        for (int ks = 0; ks < 4; ks++) {
            u32 ph[4];
            {
                int row = warpM * 16 + (lane & 15);
                int c = ks * 2 + ((lane >> 4) & 1);
                u32 sw = (u32)(row * 128 + ((c ^ (row & 7)) << 4));
                LDSM4(ph[0], ph[1], ph[2], ph[3], phb + sw);
            }
            u32 vh[2][2];
            {
                int m = lane >> 3;
                int row_s = ks * 16 + ((m & 1) << 3) + (lane & 7);
                int chunk = warpN * 2 + (m >> 1);
                u32 sw = (u32)(row_s * 128 + ((chunk ^ (row_s & 7)) << 4));
                u32 r0, r1, r2, r3;
                LDSM4T(r0, r1, r2, r3, vb2 + sw);
                vh[0][0] = r0; vh[0][1] = r1;
                vh[1][0] = r2; vh[1][1] = r3;
            }
#pragma unroll
            for (int nt = 0; nt < 2; nt++) {
                MMA16816(acc2[nt], ph, vh[nt]);
            }
        }
    }

    // ================= ctx epilogue (fp16 hi only) =================
    const int bb = bh / NH, h = bh % NH;
    u32* ch = (u32*)g_chi4;
#pragma unroll
    for (int nt = 0; nt < 2; nt++)
#pragma unroll
        for (int cc = 0; cc < 2; cc++) {
            int r = warpM * 16 + (lane >> 2) + cc * 8;
            int d = warpN * 16 + nt * 8 + (lane & 3) * 2;
            size_t n = (size_t)bb * SEQ + (size_t)(qt * 32 + r);
            size_t idx = n * EMBD + h * 64 + d;
            ch[idx >> 1] = pack_hi(acc2[nt][cc * 2], acc2[nt][cc * 2 + 1]);
        }
}

// =====================================================================
// launch
// =====================================================================
extern "C" void kernel_launch(void* const* d_in, const int* in_sizes, int n_in,
                              void* d_out, int out_size)
{
    const float* hs = (const float*)d_in[0];
    const float* qw = (const float*)d_in[1];
    const float* qb = (const float*)d_in[2];
    const float* kw = (const float*)d_in[3];
    const float* kb = (const float*)d_in[4];
    const float* vw = (const float*)d_in[5];
    const float* vb = (const float*)d_in[6];
    const float* ow = (const float*)d_in[7];
    const float* ob = (const float*)d_in[8];

    float* out  = (float*)d_out;
    float* attn = out + OUT_ELEMS;

    cudaFuncSetAttribute(qk_fused_kernel, cudaFuncAttributeMaxDynamicSharedMemorySize,
                         QK_SMEM);
    cudaFuncSetAttribute(mm_hmma_kernel, cudaFuncAttributeMaxDynamicSharedMemorySize,
                         MM_SMEM);
    cudaFuncSetAttribute(attn_kernel, cudaFuncAttributeMaxDynamicSharedMemorySize,
                         ATTN_SMEM);

    conv_x_kernel<<<(NT * EMBD / 8 + 255) / 256, 256>>>(hs);
    conv_w_kernel<<<dim3((EMBD * EMBD / 8 + 255) / 256, 4), 256>>>(qw, kw, vw, ow);

    qk_fused_kernel<<<dim3(EMBD / 64, NT / 128), 256, QK_SMEM>>>(qb, kb);
    mm_hmma_kernel<<<dim3(EMBD / 64, NT / 128, 1), 256, MM_SMEM>>>(
        qb, kb, vb, ob, out, 2);

    attn_kernel<<<dim3(18, BATCH * NH), 256, ATTN_SMEM>>>(attn);

    mm_hmma_kernel<<<dim3(EMBD / 64, NT / 128, 1), 256, MM_SMEM>>>(
        qb, kb, vb, ob, out, 3);
}

// round 14
// speedup vs baseline: 2.9819x; 1.0120x over previous
#include <cuda_runtime.h>
#include <cuda_fp16.h>

// ---------------- problem constants ----------------
#define BATCH 32
#define SEQ   576
#define EMBD  768
#define NH    12
#define HD    64
#define NT    (BATCH * SEQ)
#define OUT_ELEMS ((size_t)NT * EMBD)
#define ATT_SCALE 0.125f
#define KCHUNKS 24

typedef unsigned int u32;
typedef unsigned short u16;

// ---------------- device scratch ----------------
__device__ uint4 g_xhi4[NT * EMBD / 8];
__device__ uint4 g_xlo4[NT * EMBD / 8];
__device__ uint4 g_whi4[4 * EMBD * EMBD / 8];
__device__ uint4 g_wlo4[4 * EMBD * EMBD / 8];
__device__ uint4 g_chi4[NT * EMBD / 8];          // ctx hi only ([N, EMB], fp16)
__device__ uint4 g_qh4[NT * EMBD / 8];           // Q hi only [B,H,S,D]
__device__ uint4 g_kh4[NT * EMBD / 8];           // K hi/lo
__device__ uint4 g_kl4[NT * EMBD / 8];
__device__ uint4 g_vh4[NT * EMBD / 8];           // V hi only

// ---------------- helpers ----------------
__device__ __forceinline__ u32 smem_u32(const void* p) {
    u32 a;
    asm("{ .reg .u64 t; cvta.to.shared.u64 t, %1; cvt.u32.u64 %0, t; }"
        : "=r"(a) : "l"(p));
    return a;
}

#define CP_ASYNC16(dst, src) \
    asm volatile("cp.async.cg.shared.global [%0], [%1], 16;" \
                 :: "r"(dst), "l"(src) : "memory")
#define CP_COMMIT() asm volatile("cp.async.commit_group;" ::: "memory")
#define CP_WAIT2()  asm volatile("cp.async.wait_group 2;" ::: "memory")
#define CP_WAIT1()  asm volatile("cp.async.wait_group 1;" ::: "memory")
#define CP_WAIT0()  asm volatile("cp.async.wait_group 0;" ::: "memory")

#define LDSM4(r0, r1, r2, r3, addr) \
    asm volatile("ldmatrix.sync.aligned.m8n8.x4.shared.b16 {%0,%1,%2,%3}, [%4];" \
                 : "=r"(r0), "=r"(r1), "=r"(r2), "=r"(r3) : "r"(addr))
#define LDSM4T(r0, r1, r2, r3, addr) \
    asm volatile("ldmatrix.sync.aligned.m8n8.x4.trans.shared.b16 {%0,%1,%2,%3}, [%4];" \
                 : "=r"(r0), "=r"(r1), "=r"(r2), "=r"(r3) : "r"(addr))

#define MMA16816(d, a, b) \
    asm volatile("mma.sync.aligned.m16n8k16.row.col.f32.f16.f16.f32 " \
                 "{%0,%1,%2,%3}, {%4,%5,%6,%7}, {%8,%9}, {%0,%1,%2,%3};" \
                 : "+f"((d)[0]), "+f"((d)[1]), "+f"((d)[2]), "+f"((d)[3]) \
                 : "r"((a)[0]), "r"((a)[1]), "r"((a)[2]), "r"((a)[3]), \
                   "r"((b)[0]), "r"((b)[1]))

#define STS128(addr, a, b, c, d) \
    asm volatile("st.shared.v4.b32 [%0], {%1, %2, %3, %4};" \
                 :: "r"(addr), "r"(a), "r"(b), "r"(c), "r"(d) : "memory")

__device__ __forceinline__ void pack_hilo(float v0, float v1, u32& hp, u32& lp) {
    __half h0 = __float2half_rn(v0);
    __half h1 = __float2half_rn(v1);
    __half l0 = __float2half_rn(v0 - __half2float(h0));
    __half l1 = __float2half_rn(v1 - __half2float(h1));
    hp = (u32)*(u16*)&h0 | ((u32)*(u16*)&h1 << 16);
    lp = (u32)*(u16*)&l0 | ((u32)*(u16*)&l1 << 16);
}
__device__ __forceinline__ u32 pack_hi(float v0, float v1) {
    __half h0 = __float2half_rn(v0);
    __half h1 = __float2half_rn(v1);
    return (u32)*(u16*)&h0 | ((u32)*(u16*)&h1 << 16);
}

// =====================================================================
// hi/lo split conversion (fp16)
// =====================================================================
__device__ __forceinline__ void conv8(const float4* src2, uint4* hi, uint4* lo) {
    float4 a = src2[0], b = src2[1];
    float f[8] = {a.x, a.y, a.z, a.w, b.x, b.y, b.z, b.w};
    union { uint4 v; __half h[8]; } H, L;
#pragma unroll
    for (int j = 0; j < 8; j++) {
        __half hh = __float2half_rn(f[j]);
        H.h[j] = hh;
        L.h[j] = __float2half_rn(f[j] - __half2float(hh));
    }
    *hi = H.v; *lo = L.v;
}

__global__ __launch_bounds__(256) void conv_x_kernel(const float* __restrict__ src) {
    int i = blockIdx.x * blockDim.x + threadIdx.x;
    if (i >= NT * EMBD / 8) return;
    conv8((const float4*)src + 2 * (size_t)i, &g_xhi4[i], &g_xlo4[i]);
}

__global__ __launch_bounds__(256) void conv_w_kernel(
    const float* __restrict__ qw, const float* __restrict__ kw,
    const float* __restrict__ vw, const float* __restrict__ ow) {
    int z = blockIdx.y;
    const float* src = z == 0 ? qw : z == 1 ? kw : z == 2 ? vw : ow;
    int i = blockIdx.x * blockDim.x + threadIdx.x;
    if (i >= EMBD * EMBD / 8) return;
    int di = z * (EMBD * EMBD / 8) + i;
    conv8((const float4*)src + 2 * (size_t)i, &g_whi4[di], &g_wlo4[di]);
}

// =====================================================================
// Fused Q+K projection (3-term each), 3-stage pipeline.
// Q epilogue stores hi ONLY; K stores hi/lo.
// =====================================================================
#define QK_STAGE 32768
#define QK_SMEM (3 * QK_STAGE + 1024)

__global__ __launch_bounds__(256, 2) void qk_fused_kernel(
    const float* __restrict__ qb, const float* __restrict__ kb)
{
    extern __shared__ char smraw[];
    const u32 smbase = smem_u32(smraw);
    float* bias_s = (float*)(smraw + 3 * QK_STAGE);   // [2][64]

    const int t = threadIdx.x, lane = t & 31, wid = t >> 5;
    const int warpM = wid & 3;
    const int warpN = wid >> 2;
    const int o0 = blockIdx.x * 64;
    const int n0 = blockIdx.y * 128;

    if (t < 64) bias_s[t] = qb[o0 + t];
    else if (t < 128) bias_s[t] = kb[o0 + t - 64];

    const int lr   = t >> 1;
    const int half = t & 1;
    const uint4* srcA = (half ? g_xlo4 : g_xhi4) + (size_t)(n0 + lr) * 96;
    const u32 arow_sw[4] = {
        (u32)(lr * 128 + (((half * 4 + 0) ^ (lr & 7)) << 4)),
        (u32)(lr * 128 + (((half * 4 + 1) ^ (lr & 7)) << 4)),
        (u32)(lr * 128 + (((half * 4 + 2) ^ (lr & 7)) << 4)),
        (u32)(lr * 128 + (((half * 4 + 3) ^ (lr & 7)) << 4))
    };
    u32 wdst[4];
    const uint4* srcW[4];
#pragma unroll
    for (int j = 0; j < 4; j++) {
        int idx = t + j * 256;
        int mw = idx >> 9;
        int within = idx & 511;
        int row = within >> 3, rem = within & 7;
        int wh = rem >> 2, g = rem & 3;
        wdst[j] = (u32)(16384 + mw * 8192 + row * 128 + (((wh * 4 + g) ^ (row & 7)) << 4));
        srcW[j] = (wh ? g_wlo4 : g_whi4) + (size_t)mw * (EMBD * EMBD / 8)
                  + (size_t)(o0 + row) * 96 + g;
    }

    float accQ[2][4][4], accK[2][4][4];
#pragma unroll
    for (int i = 0; i < 2; i++)
#pragma unroll
        for (int j = 0; j < 4; j++)
#pragma unroll
            for (int c = 0; c < 4; c++) { accQ[i][j][c] = 0.f; accK[i][j][c] = 0.f; }

#pragma unroll
    for (int pc = 0; pc < 2; pc++) {
        const u32 st = smbase + pc * QK_STAGE;
        const int ko = pc * 4;
#pragma unroll
        for (int g = 0; g < 4; g++) CP_ASYNC16(st + arow_sw[g], srcA + ko + g);
#pragma unroll
        for (int j = 0; j < 4; j++) CP_ASYNC16(st + wdst[j], srcW[j] + ko);
        CP_COMMIT();
    }

#pragma unroll 1
    for (int kc = 0; kc < KCHUNKS; kc++) {
        if (kc == KCHUNKS - 1) { CP_WAIT0(); } else { CP_WAIT1(); }
        __syncthreads();
        if (kc + 2 < KCHUNKS) {
            int nc = kc + 2;
            const u32 st = smbase + (nc % 3) * QK_STAGE;
            const int ko = nc * 4;
#pragma unroll
            for (int g = 0; g < 4; g++) CP_ASYNC16(st + arow_sw[g], srcA + ko + g);
#pragma unroll
            for (int j = 0; j < 4; j++) CP_ASYNC16(st + wdst[j], srcW[j] + ko);
            CP_COMMIT();
        }

        const u32 Ab  = smbase + (kc % 3) * QK_STAGE;
        const u32 WqB = Ab + 16384;
        const u32 WkB = Ab + 16384 + 8192;

#pragma unroll
        for (int ks = 0; ks < 2; ks++) {
            u32 ah[2][4], al[2][4];
#pragma unroll
            for (int mt = 0; mt < 2; mt++) {
                int row = warpM * 32 + mt * 16 + (lane & 15);
                int c = ks * 2 + ((lane >> 4) & 1);
                u32 base = Ab + row * 128;
                LDSM4(ah[mt][0], ah[mt][1], ah[mt][2], ah[mt][3],
                      base + (((c) ^ (row & 7)) << 4));
                LDSM4(al[mt][0], al[mt][1], al[mt][2], al[mt][3],
                      base + (((c + 4) ^ (row & 7)) << 4));
            }
            {
                u32 bh[4][2], bl[4][2];
#pragma unroll
                for (int bt = 0; bt < 2; bt++) {
                    int row = warpN * 32 + bt * 16 + (lane & 7) + ((lane >> 4) & 1) * 8;
                    int c = ks * 2 + ((lane >> 3) & 1);
                    u32 base = WqB + row * 128;
                    u32 r0, r1, r2, r3;
                    LDSM4(r0, r1, r2, r3, base + (((c) ^ (row & 7)) << 4));
                    bh[bt * 2][0] = r0; bh[bt * 2][1] = r1;
                    bh[bt * 2 + 1][0] = r2; bh[bt * 2 + 1][1] = r3;
                    LDSM4(r0, r1, r2, r3, base + (((c + 4) ^ (row & 7)) << 4));
                    bl[bt * 2][0] = r0; bl[bt * 2][1] = r1;
                    bl[bt * 2 + 1][0] = r2; bl[bt * 2 + 1][1] = r3;
                }
#pragma unroll
                for (int mt = 0; mt < 2; mt++)
#pragma unroll
                    for (int nt = 0; nt < 4; nt++) {
                        MMA16816(accQ[mt][nt], ah[mt], bh[nt]);
                        MMA16816(accQ[mt][nt], ah[mt], bl[nt]);
                        MMA16816(accQ[mt][nt], al[mt], bh[nt]);
                    }
            }
            {
                u32 bh[4][2], bl[4][2];
#pragma unroll
                for (int bt = 0; bt < 2; bt++) {
                    int row = warpN * 32 + bt * 16 + (lane & 7) + ((lane >> 4) & 1) * 8;
                    int c = ks * 2 + ((lane >> 3) & 1);
                    u32 base = WkB + row * 128;
                    u32 r0, r1, r2, r3;
                    LDSM4(r0, r1, r2, r3, base + (((c) ^ (row & 7)) << 4));
                    bh[bt * 2][0] = r0; bh[bt * 2][1] = r1;
                    bh[bt * 2 + 1][0] = r2; bh[bt * 2 + 1][1] = r3;
                    LDSM4(r0, r1, r2, r3, base + (((c + 4) ^ (row & 7)) << 4));
                    bl[bt * 2][0] = r0; bl[bt * 2][1] = r1;
                    bl[bt * 2 + 1][0] = r2; bl[bt * 2 + 1][1] = r3;
                }
#pragma unroll
                for (int mt = 0; mt < 2; mt++)
#pragma unroll
                    for (int nt = 0; nt < 4; nt++) {
                        MMA16816(accK[mt][nt], ah[mt], bh[nt]);
                        MMA16816(accK[mt][nt], ah[mt], bl[nt]);
                        MMA16816(accK[mt][nt], al[mt], bh[nt]);
                    }
            }
        }
    }

    const int h = blockIdx.x;
    u32* qh_d = (u32*)g_qh4;
    u32* kh_d = (u32*)g_kh4; u32* kl_d = (u32*)g_kl4;
#pragma unroll
    for (int mt = 0; mt < 2; mt++)
#pragma unroll
        for (int nt = 0; nt < 4; nt++)
#pragma unroll
            for (int cc = 0; cc < 2; cc++) {
                int rl = warpM * 32 + mt * 16 + (lane >> 2) + cc * 8;
                int cl = warpN * 32 + nt * 8 + (lane & 3) * 2;
                int n = n0 + rl;
                int bb = n / SEQ, ss = n - bb * SEQ;
                size_t idx = ((((size_t)bb * NH + h) * SEQ + ss) * HD + cl);
                {
                    float v0 = accQ[mt][nt][cc * 2 + 0] + bias_s[cl];
                    float v1 = accQ[mt][nt][cc * 2 + 1] + bias_s[cl + 1];
                    qh_d[idx >> 1] = pack_hi(v0, v1);   // Q hi only
                }
                {
                    float v0 = accK[mt][nt][cc * 2 + 0] + bias_s[64 + cl];
                    float v1 = accK[mt][nt][cc * 2 + 1] + bias_s[64 + cl + 1];
                    u32 hp, lp; pack_hilo(v0, v1, hp, lp);
                    kh_d[idx >> 1] = hp; kl_d[idx >> 1] = lp;
                }
            }
}

// =====================================================================
// HMMA split-fp16 GEMM (V and O modes), CTA tile 128x64, 4-stage.
// =====================================================================
#define STAGE_BYTES 24576            // A 16K + W 8K
#define MM_SMEM (4 * STAGE_BYTES + 512)

__global__ __launch_bounds__(256, 2) void mm_hmma_kernel(
    const float* __restrict__ qb, const float* __restrict__ kb,
    const float* __restrict__ vb, const float* __restrict__ ob,
    float* __restrict__ outp, int mode_base)
{
    extern __shared__ char smraw[];
    const u32 smbase = smem_u32(smraw);
    float* bias_s = (float*)(smraw + 4 * STAGE_BYTES);

    const int t = threadIdx.x, lane = t & 31, wid = t >> 5;
    const int warpM = wid & 3;
    const int warpN = wid >> 2;
    const int mode = mode_base + blockIdx.z;
    const bool need3 = (mode < 2);
    const int o0 = blockIdx.x * 64;
    const int n0 = blockIdx.y * 128;

    const float* bias = mode == 0 ? qb : mode == 1 ? kb : mode == 2 ? vb : ob;
    const uint4* AhiG = (mode < 3) ? g_xhi4 : g_chi4;
    const uint4* AloG = g_xlo4;
    const size_t woff = (size_t)(mode < 3 ? mode : 3) * (EMBD * EMBD / 8);

    if (t < 64) bias_s[t] = bias[o0 + t];

    const int lr   = t >> 1;
    const int half = t & 1;
    const bool loadA = need3 || (half == 0);
    const uint4* srcA = (half ? AloG : AhiG) + (size_t)(n0 + lr) * 96;
    const u32 arow_sw[4] = {
        (u32)(lr * 128 + (((half * 4 + 0) ^ (lr & 7)) << 4)),
        (u32)(lr * 128 + (((half * 4 + 1) ^ (lr & 7)) << 4)),
        (u32)(lr * 128 + (((half * 4 + 2) ^ (lr & 7)) << 4)),
        (u32)(lr * 128 + (((half * 4 + 3) ^ (lr & 7)) << 4))
    };
    u32 wdst[2];
    const uint4* srcW[2];
#pragma unroll
    for (int j = 0; j < 2; j++) {
        int idx = t + j * 256;
        int row = idx >> 3, rem = idx & 7;
        int wh = rem >> 2, g = rem & 3;
        wdst[j] = (u32)(row * 128 + (((wh * 4 + g) ^ (row & 7)) << 4));
        srcW[j] = (wh ? g_wlo4 : g_whi4) + woff + (size_t)(o0 + row) * 96 + g;
    }

    float acc[2][4][4];
#pragma unroll
    for (int i = 0; i < 2; i++)
#pragma unroll
        for (int j = 0; j < 4; j++)
#pragma unroll
            for (int c = 0; c < 4; c++) acc[i][j][c] = 0.f;

    // prefetch chunks 0..2
#pragma unroll
    for (int pc = 0; pc < 3; pc++) {
        const u32 st = smbase + pc * STAGE_BYTES;
        const int ko = pc * 4;
#pragma unroll
        for (int g = 0; g < 4; g++)
            if (loadA) CP_ASYNC16(st + arow_sw[g], srcA + ko + g);
#pragma unroll
        for (int j = 0; j < 2; j++)
            CP_ASYNC16(st + 16384 + wdst[j], srcW[j] + ko);
        CP_COMMIT();
    }

#pragma unroll 1
    for (int kc = 0; kc < KCHUNKS; kc++) {
        int rem = KCHUNKS - 1 - kc;
        if (rem >= 2)      { CP_WAIT2(); }
        else if (rem == 1) { CP_WAIT1(); }
        else               { CP_WAIT0(); }
        __syncthreads();
        if (kc + 3 < KCHUNKS) {
            int nc = kc + 3;
            const u32 st = smbase + (nc & 3) * STAGE_BYTES;
            const int ko = nc * 4;
#pragma unroll
            for (int g = 0; g < 4; g++)
                if (loadA) CP_ASYNC16(st + arow_sw[g], srcA + ko + g);
#pragma unroll
            for (int j = 0; j < 2; j++)
                CP_ASYNC16(st + 16384 + wdst[j], srcW[j] + ko);
            CP_COMMIT();
        }

        const u32 Ab = smbase + (kc & 3) * STAGE_BYTES;
        const u32 Wb = Ab + 16384;

#pragma unroll
        for (int ks = 0; ks < 2; ks++) {
            u32 ah[2][4], al[2][4];
#pragma unroll
            for (int mt = 0; mt < 2; mt++) {
                int row = warpM * 32 + mt * 16 + (lane & 15);
                int c = ks * 2 + ((lane >> 4) & 1);
                u32 base = Ab + row * 128;
                LDSM4(ah[mt][0], ah[mt][1], ah[mt][2], ah[mt][3],
                      base + (((c) ^ (row & 7)) << 4));
                if (need3)
                    LDSM4(al[mt][0], al[mt][1], al[mt][2], al[mt][3],
                          base + (((c + 4) ^ (row & 7)) << 4));
            }
            u32 bh[4][2], bl[4][2];
#pragma unroll
            for (int bt = 0; bt < 2; bt++) {
                int row = warpN * 32 + bt * 16 + (lane & 7) + ((lane >> 4) & 1) * 8;
                int c = ks * 2 + ((lane >> 3) & 1);
                u32 base = Wb + row * 128;
                u32 r0, r1, r2, r3;
                LDSM4(r0, r1, r2, r3, base + (((c) ^ (row & 7)) << 4));
                bh[bt * 2][0] = r0; bh[bt * 2][1] = r1;
                bh[bt * 2 + 1][0] = r2; bh[bt * 2 + 1][1] = r3;
                LDSM4(r0, r1, r2, r3, base + (((c + 4) ^ (row & 7)) << 4));
                bl[bt * 2][0] = r0; bl[bt * 2][1] = r1;
                bl[bt * 2 + 1][0] = r2; bl[bt * 2 + 1][1] = r3;
            }
#pragma unroll
            for (int mt = 0; mt < 2; mt++)
#pragma unroll
                for (int nt = 0; nt < 4; nt++) {
                    MMA16816(acc[mt][nt], ah[mt], bh[nt]);
                    MMA16816(acc[mt][nt], ah[mt], bl[nt]);
                    if (need3) MMA16816(acc[mt][nt], al[mt], bh[nt]);
                }
        }
    }

    u32* dsth = (u32*)g_vh4;                // only mode 2 scatters here
    const int h = blockIdx.x;
#pragma unroll
    for (int mt = 0; mt < 2; mt++)
#pragma unroll
        for (int nt = 0; nt < 4; nt++)
#pragma unroll
            for (int cc = 0; cc < 2; cc++) {
                int rl = warpM * 32 + mt * 16 + (lane >> 2) + cc * 8;
                int cl = warpN * 32 + nt * 8 + (lane & 3) * 2;
                float v0 = acc[mt][nt][cc * 2 + 0] + bias_s[cl];
                float v1 = acc[mt][nt][cc * 2 + 1] + bias_s[cl + 1];
                int n = n0 + rl;
                if (mode < 3) {
                    int bb = n / SEQ, ss = n - bb * SEQ;
                    size_t idx = ((((size_t)bb * NH + h) * SEQ + ss) * HD + cl);
                    dsth[idx >> 1] = pack_hi(v0, v1);
                } else {
                    float2* p = (float2*)(outp + (size_t)n * EMBD + o0 + cl);
                    *p = make_float2(v0, v1);
                }
            }
}

// =====================================================================
// HMMA attention, 32-row q tiles, 2 CTAs/SM.
// Q hi-only (2-term scores: Qh·Kh + Qh·Kl). PV pipelined, PH double-buffered.
// =====================================================================
#define SLAB_W 578
#define SC_B   0
#define ST0_B  (32 * SLAB_W * 4)           // 73,984
#define ST1_B  (ST0_B + 16384)             // 90,368
#define PH_B   (ST1_B + 16384)             // 106,752 (2 x 4096)
#define INV_B  (PH_B + 8192)               // 114,944
#define MAXP_B (INV_B + 128)               // 115,072
#define ATTN_SMEM (MAXP_B + 512)           // 115,584

__device__ __forceinline__ void load_tile64_async(
    u32 dsth, u32 dstl,
    const uint4* __restrict__ srch, const uint4* __restrict__ srcl,
    int tokbase, int t)
{
#pragma unroll
    for (int it = 0; it < 2; it++) {
        int idx = t + it * 256;
        int r = idx >> 3, c = idx & 7;
        u32 off = (u32)(r * 128 + ((c ^ (r & 7)) << 4));
        CP_ASYNC16(dsth + off, srch + (size_t)(tokbase + r) * 8 + c);
        CP_ASYNC16(dstl + off, srcl + (size_t)(tokbase + r) * 8 + c);
    }
    CP_COMMIT();
}

__device__ __forceinline__ void load_v_async(
    u32 dsth, const uint4* __restrict__ srch, int tokbase, int t)
{
#pragma unroll
    for (int it = 0; it < 2; it++) {
        int idx = t + it * 256;
        int r = idx >> 3, c = idx & 7;
        u32 off = (u32)(r * 128 + ((c ^ (r & 7)) << 4));
        CP_ASYNC16(dsth + off, srch + (size_t)(tokbase + r) * 8 + c);
    }
    CP_COMMIT();
}

__global__ __launch_bounds__(256, 2) void attn_kernel(float* __restrict__ attn_out)
{
    extern __shared__ char smc[];
    const u32 smb = smem_u32(smc);
    float* sc = (float*)smc;
    float* inv_s = (float*)(smc + INV_B);
    float* maxp  = (float*)(smc + MAXP_B);

    const int t = threadIdx.x, lane = t & 31, wid = t >> 5;
    const int warpM = wid & 1;
    const int warpN = wid >> 1;
    const int qt = blockIdx.x;
    const int bh = blockIdx.y;
    const int qtok = bh * SEQ + qt * 32;
    const int ktok0 = bh * SEQ;

    // load Q tile (hi only, 32 x 64) into stage0 area
    if (t < 256) {
        int r = t >> 3, c = t & 7;
        if (r < 32) {
            uint4 a = g_qh4[(size_t)(qtok + r) * 8 + c];
            u32 off = (u32)(r * 128 + ((c ^ (r & 7)) << 4));
            STS128(smb + ST0_B + off, a.x, a.y, a.z, a.w);
        }
    }
    __syncthreads();

    u32 qh[4][4];
#pragma unroll
    for (int ks = 0; ks < 4; ks++) {
        int row = warpM * 16 + (lane & 15);
        int c = ks * 2 + ((lane >> 4) & 1);
        u32 sw = (u32)(row * 128 + ((c ^ (row & 7)) << 4));
        LDSM4(qh[ks][0], qh[ks][1], qh[ks][2], qh[ks][3], smb + ST0_B + sw);
    }

    load_tile64_async(smb + ST1_B, smb + ST1_B + 8192, g_kh4, g_kl4, ktok0, t);

    float fm[2] = {-1e30f, -1e30f};

    // ================= scores (2-term: Qh·Kh + Qh·Kl) =================
#pragma unroll 1
    for (int kt = 0; kt < 9; kt++) {
        CP_WAIT0();
        __syncthreads();
        if (kt < 9 - 1) {
            u32 nb = smb + (((kt + 1 + 1) & 1) ? ST1_B : ST0_B);
            load_tile64_async(nb, nb + 8192, g_kh4, g_kl4, ktok0 + (kt + 1) * 64, t);
        }
        const u32 kb = smb + (((kt + 1) & 1) ? ST1_B : ST0_B);
        const u32 klb = kb + 8192;

        float acc[2][4];
#pragma unroll
        for (int i = 0; i < 2; i++)
#pragma unroll
            for (int j = 0; j < 4; j++) acc[i][j] = 0.f;

#pragma unroll
        for (int ks = 0; ks < 4; ks++) {
            u32 bh2[2][2], bl2[2][2];
            {
                int row = warpN * 16 + (lane & 7) + ((lane >> 4) & 1) * 8;
                int c = ks * 2 + ((lane >> 3) & 1);
                u32 sw = (u32)(row * 128 + ((c ^ (row & 7)) << 4));
                u32 r0, r1, r2, r3;
                LDSM4(r0, r1, r2, r3, kb + sw);
                bh2[0][0] = r0; bh2[0][1] = r1;
                bh2[1][0] = r2; bh2[1][1] = r3;
                LDSM4(r0, r1, r2, r3, klb + sw);
                bl2[0][0] = r0; bl2[0][1] = r1;
                bl2[1][0] = r2; bl2[1][1] = r3;
            }
#pragma unroll
            for (int nt = 0; nt < 2; nt++) {
                MMA16816(acc[nt], qh[ks], bh2[nt]);
                MMA16816(acc[nt], qh[ks], bl2[nt]);
            }
        }
#pragma unroll
        for (int nt = 0; nt < 2; nt++)
#pragma unroll
            for (int cc = 0; cc < 2; cc++) {
                fm[cc] = fmaxf(fm[cc], fmaxf(acc[nt][cc * 2], acc[nt][cc * 2 + 1]));
                int r = warpM * 16 + (lane >> 2) + cc * 8;
                int col = kt * 64 + warpN * 16 + nt * 8 + (lane & 3) * 2;
                float2* p = (float2*)(sc + r * SLAB_W + col);
                *p = make_float2(acc[nt][cc * 2] * ATT_SCALE,
                                 acc[nt][cc * 2 + 1] * ATT_SCALE);
            }
    }
#pragma unroll
    for (int cc = 0; cc < 2; cc++) {
        fm[cc] = fmaxf(fm[cc], __shfl_xor_sync(0xffffffffu, fm[cc], 1));
        fm[cc] = fmaxf(fm[cc], __shfl_xor_sync(0xffffffffu, fm[cc], 2));
        if ((lane & 3) == 0) {
            int r = warpM * 16 + (lane >> 2) + cc * 8;
            maxp[warpN * 32 + r] = fm[cc];
        }
    }
    __syncthreads();

    // preload V tile 0 (hi only) into stage0 — overlaps softmax
    load_v_async(smb + ST0_B, g_vh4, ktok0, t);

    // ================= softmax: single pass =================
    {
        for (int rr = 0; rr < 4; rr++) {
            int r = wid * 4 + rr;
            float m = fmaxf(fmaxf(maxp[r], maxp[32 + r]),
                            fmaxf(maxp[64 + r], maxp[96 + r])) * ATT_SCALE;
            float* row = sc + r * SLAB_W;
            float s = 0.f;
            for (int c = lane; c < SEQ; c += 32) {
                float e = __expf(row[c] - m);
                row[c] = e;
                s += e;
            }
#pragma unroll
            for (int off = 16; off > 0; off >>= 1)
                s += __shfl_xor_sync(0xffffffffu, s, off);
            if (lane == 0) inv_s[r] = 1.f / s;
        }
    }

    // pre-pack P chunk 0 into PH buffer 0
#pragma unroll
    for (int i = 0; i < 4; i++) {
        int r = wid * 4 + i;
        float inv = inv_s[r];
        float2 e = *(const float2*)(sc + r * SLAB_W + lane * 2);
        float p0 = e.x * inv, p1 = e.y * inv;
        size_t arow = ((size_t)bh * SEQ + (size_t)(qt * 32 + r)) * SEQ;
        *(float2*)(attn_out + arow + lane * 2) = make_float2(p0, p1);
        u32 off = (u32)(r * 128 + (((lane >> 2) ^ (r & 7)) << 4) + (lane & 3) * 4);
        *(u32*)(smc + PH_B + off) = pack_hi(p0, p1);
    }

    // ================= P @ V (pipelined) ====
    float acc2[2][4];
#pragma unroll
    for (int i = 0; i < 2; i++)
#pragma unroll
        for (int j = 0; j < 4; j++) acc2[i][j] = 0.f;

#pragma unroll 1
    for (int kt = 0; kt < 9; kt++) {
        CP_WAIT0();
        __syncthreads();
        if (kt < 9 - 1) {
            u32 nb = smb + (((kt + 1) & 1) ? ST1_B : ST0_B);
            load_v_async(nb, g_vh4, ktok0 + (kt + 1) * 64, t);
#pragma unroll
            for (int i = 0; i < 4; i++) {
                int r = wid * 4 + i;
                float inv = inv_s[r];
                float2 e = *(const float2*)(sc + r * SLAB_W + (kt + 1) * 64 + lane * 2);
                float p0 = e.x * inv, p1 = e.y * inv;
                size_t arow = ((size_t)bh * SEQ + (size_t)(qt * 32 + r)) * SEQ;
                *(float2*)(attn_out + arow + (kt + 1) * 64 + lane * 2) =
                    make_float2(p0, p1);
                u32 off = (u32)(r * 128 + (((lane >> 2) ^ (r & 7)) << 4) + (lane & 3) * 4);
                *(u32*)(smc + PH_B + ((kt + 1) & 1) * 4096 + off) = pack_hi(p0, p1);
            }
        }

        const u32 phb = smb + PH_B + (kt & 1) * 4096;
        const u32 vb2 = smb + ((kt & 1) ? ST1_B : ST0_B);

#pragma unroll
        for (int ks = 0; ks < 4; ks++) {
            u32 ph[4];
            {
                int row = warpM * 16 + (lane & 15);
                int c = ks * 2 + ((lane >> 4) & 1);
                u32 sw = (u32)(row * 128 + ((c ^ (row & 7)) << 4));
                LDSM4(ph[0], ph[1], ph[2], ph[3], phb + sw);
            }
            u32 vh[2][2];
            {
                int m = lane >> 3;
                int row_s = ks * 16 + ((m & 1) << 3) + (lane & 7);
                int chunk = warpN * 2 + (m >> 1);
                u32 sw = (u32)(row_s * 128 + ((chunk ^ (row_s & 7)) << 4));
                u32 r0, r1, r2, r3;
                LDSM4T(r0, r1, r2, r3, vb2 + sw);
                vh[0][0] = r0; vh[0][1] = r1;
                vh[1][0] = r2; vh[1][1] = r3;
            }
#pragma unroll
            for (int nt = 0; nt < 2; nt++) {
                MMA16816(acc2[nt], ph, vh[nt]);
            }
        }
    }

    // ================= ctx epilogue (fp16 hi only) =================
    const int bb = bh / NH, h = bh % NH;
    u32* ch = (u32*)g_chi4;
#pragma unroll
    for (int nt = 0; nt < 2; nt++)
#pragma unroll
        for (int cc = 0; cc < 2; cc++) {
            int r = warpM * 16 + (lane >> 2) + cc * 8;
            int d = warpN * 16 + nt * 8 + (lane & 3) * 2;
            size_t n = (size_t)bb * SEQ + (size_t)(qt * 32 + r);
            size_t idx = n * EMBD + h * 64 + d;
            ch[idx >> 1] = pack_hi(acc2[nt][cc * 2], acc2[nt][cc * 2 + 1]);
        }
}

// =====================================================================
// launch
// =====================================================================
extern "C" void kernel_launch(void* const* d_in, const int* in_sizes, int n_in,
                              void* d_out, int out_size)
{
    const float* hs = (const float*)d_in[0];
    const float* qw = (const float*)d_in[1];
    const float* qb = (const float*)d_in[2];
    const float* kw = (const float*)d_in[3];
    const float* kb = (const float*)d_in[4];
    const float* vw = (const float*)d_in[5];
    const float* vb = (const float*)d_in[6];
    const float* ow = (const float*)d_in[7];
    const float* ob = (const float*)d_in[8];

    float* out  = (float*)d_out;
    float* attn = out + OUT_ELEMS;

    cudaFuncSetAttribute(qk_fused_kernel, cudaFuncAttributeMaxDynamicSharedMemorySize,
                         QK_SMEM);
    cudaFuncSetAttribute(mm_hmma_kernel, cudaFuncAttributeMaxDynamicSharedMemorySize,
                         MM_SMEM);
    cudaFuncSetAttribute(attn_kernel, cudaFuncAttributeMaxDynamicSharedMemorySize,
                         ATTN_SMEM);

    conv_x_kernel<<<(NT * EMBD / 8 + 255) / 256, 256>>>(hs);
    conv_w_kernel<<<dim3((EMBD * EMBD / 8 + 255) / 256, 4), 256>>>(qw, kw, vw, ow);

    qk_fused_kernel<<<dim3(EMBD / 64, NT / 128), 256, QK_SMEM>>>(qb, kb);
    mm_hmma_kernel<<<dim3(EMBD / 64, NT / 128, 1), 256, MM_SMEM>>>(
        qb, kb, vb, ob, out, 2);

    attn_kernel<<<dim3(18, BATCH * NH), 256, ATTN_SMEM>>>(attn);

    mm_hmma_kernel<<<dim3(EMBD / 64, NT / 128, 1), 256, MM_SMEM>>>(
        qb, kb, vb, ob, out, 3);
}

// round 15
// speedup vs baseline: 3.7918x; 1.2716x over previous
#include <cuda_runtime.h>
#include <cuda_fp16.h>

// ---------------- problem constants ----------------
#define BATCH 32
#define SEQ   576
#define EMBD  768
#define NH    12
#define HD    64
#define NT    (BATCH * SEQ)
#define OUT_ELEMS ((size_t)NT * EMBD)
#define ATT_SCALE 0.125f
#define KCHUNKS 24

typedef unsigned int u32;
typedef unsigned short u16;

// ---------------- device scratch ----------------
__device__ uint4 g_xhi4[NT * EMBD / 8];
__device__ uint4 g_xlo4[NT * EMBD / 8];
__device__ uint4 g_whi4[4 * EMBD * EMBD / 8];
__device__ uint4 g_wlo4[2 * EMBD * EMBD / 8];    // lo only for Q,K weights
__device__ uint4 g_chi4[NT * EMBD / 8];          // ctx hi only ([N, EMB], fp16)
__device__ uint4 g_qh4[NT * EMBD / 8];           // Q hi only [B,H,S,D]
__device__ uint4 g_kh4[NT * EMBD / 8];           // K hi/lo
__device__ uint4 g_kl4[NT * EMBD / 8];
__device__ uint4 g_vh4[NT * EMBD / 8];           // V hi only

// ---------------- helpers ----------------
__device__ __forceinline__ u32 smem_u32(const void* p) {
    u32 a;
    asm("{ .reg .u64 t; cvta.to.shared.u64 t, %1; cvt.u32.u64 %0, t; }"
        : "=r"(a) : "l"(p));
    return a;
}

#define CP_ASYNC16(dst, src) \
    asm volatile("cp.async.cg.shared.global [%0], [%1], 16;" \
                 :: "r"(dst), "l"(src) : "memory")
#define CP_COMMIT() asm volatile("cp.async.commit_group;" ::: "memory")
#define CP_WAIT2()  asm volatile("cp.async.wait_group 2;" ::: "memory")
#define CP_WAIT1()  asm volatile("cp.async.wait_group 1;" ::: "memory")
#define CP_WAIT0()  asm volatile("cp.async.wait_group 0;" ::: "memory")

#define LDSM4(r0, r1, r2, r3, addr) \
    asm volatile("ldmatrix.sync.aligned.m8n8.x4.shared.b16 {%0,%1,%2,%3}, [%4];" \
                 : "=r"(r0), "=r"(r1), "=r"(r2), "=r"(r3) : "r"(addr))
#define LDSM4T(r0, r1, r2, r3, addr) \
    asm volatile("ldmatrix.sync.aligned.m8n8.x4.trans.shared.b16 {%0,%1,%2,%3}, [%4];" \
                 : "=r"(r0), "=r"(r1), "=r"(r2), "=r"(r3) : "r"(addr))

#define MMA16816(d, a, b) \
    asm volatile("mma.sync.aligned.m16n8k16.row.col.f32.f16.f16.f32 " \
                 "{%0,%1,%2,%3}, {%4,%5,%6,%7}, {%8,%9}, {%0,%1,%2,%3};" \
                 : "+f"((d)[0]), "+f"((d)[1]), "+f"((d)[2]), "+f"((d)[3]) \
                 : "r"((a)[0]), "r"((a)[1]), "r"((a)[2]), "r"((a)[3]), \
                   "r"((b)[0]), "r"((b)[1]))

#define STS128(addr, a, b, c, d) \
    asm volatile("st.shared.v4.b32 [%0], {%1, %2, %3, %4};" \
                 :: "r"(addr), "r"(a), "r"(b), "r"(c), "r"(d) : "memory")

__device__ __forceinline__ void pack_hilo(float v0, float v1, u32& hp, u32& lp) {
    __half h0 = __float2half_rn(v0);
    __half h1 = __float2half_rn(v1);
    __half l0 = __float2half_rn(v0 - __half2float(h0));
    __half l1 = __float2half_rn(v1 - __half2float(h1));
    hp = (u32)*(u16*)&h0 | ((u32)*(u16*)&h1 << 16);
    lp = (u32)*(u16*)&l0 | ((u32)*(u16*)&l1 << 16);
}
__device__ __forceinline__ u32 pack_hi(float v0, float v1) {
    __half h0 = __float2half_rn(v0);
    __half h1 = __float2half_rn(v1);
    return (u32)*(u16*)&h0 | ((u32)*(u16*)&h1 << 16);
}

// =====================================================================
// hi/lo split conversion (fp16)
// =====================================================================
__device__ __forceinline__ void conv8(const float4* src2, uint4* hi, uint4* lo) {
    float4 a = src2[0], b = src2[1];
    float f[8] = {a.x, a.y, a.z, a.w, b.x, b.y, b.z, b.w};
    union { uint4 v; __half h[8]; } H, L;
#pragma unroll
    for (int j = 0; j < 8; j++) {
        __half hh = __float2half_rn(f[j]);
        H.h[j] = hh;
        L.h[j] = __float2half_rn(f[j] - __half2float(hh));
    }
    *hi = H.v; *lo = L.v;
}
__device__ __forceinline__ void conv8_hi(const float4* src2, uint4* hi) {
    float4 a = src2[0], b = src2[1];
    float f[8] = {a.x, a.y, a.z, a.w, b.x, b.y, b.z, b.w};
    union { uint4 v; __half h[8]; } H;
#pragma unroll
    for (int j = 0; j < 8; j++) H.h[j] = __float2half_rn(f[j]);
    *hi = H.v;
}

__global__ __launch_bounds__(256) void conv_x_kernel(const float* __restrict__ src) {
    int i = blockIdx.x * blockDim.x + threadIdx.x;
    if (i >= NT * EMBD / 8) return;
    conv8((const float4*)src + 2 * (size_t)i, &g_xhi4[i], &g_xlo4[i]);
}

__global__ __launch_bounds__(256) void conv_w_kernel(
    const float* __restrict__ qw, const float* __restrict__ kw,
    const float* __restrict__ vw, const float* __restrict__ ow) {
    int z = blockIdx.y;
    const float* src = z == 0 ? qw : z == 1 ? kw : z == 2 ? vw : ow;
    int i = blockIdx.x * blockDim.x + threadIdx.x;
    if (i >= EMBD * EMBD / 8) return;
    int di = z * (EMBD * EMBD / 8) + i;
    if (z < 2)
        conv8((const float4*)src + 2 * (size_t)i, &g_whi4[di], &g_wlo4[di]);
    else
        conv8_hi((const float4*)src + 2 * (size_t)i, &g_whi4[di]);
}

// =====================================================================
// Fused Q+K projection, 3-stage pipeline.
// Q: 2-term (Xhi·Wh + Xhi·Wl)  [stored hi-only, rounding dominates]
// K: 3-term                     [stored hi/lo, must be fp32-accurate]
// =====================================================================
#define QK_STAGE 32768
#define QK_SMEM (3 * QK_STAGE + 1024)

__global__ __launch_bounds__(256, 2) void qk_fused_kernel(
    const float* __restrict__ qb, const float* __restrict__ kb)
{
    extern __shared__ char smraw[];
    const u32 smbase = smem_u32(smraw);
    float* bias_s = (float*)(smraw + 3 * QK_STAGE);   // [2][64]

    const int t = threadIdx.x, lane = t & 31, wid = t >> 5;
    const int warpM = wid & 3;
    const int warpN = wid >> 2;
    const int o0 = blockIdx.x * 64;
    const int n0 = blockIdx.y * 128;

    if (t < 64) bias_s[t] = qb[o0 + t];
    else if (t < 128) bias_s[t] = kb[o0 + t - 64];

    const int lr   = t >> 1;
    const int half = t & 1;
    const uint4* srcA = (half ? g_xlo4 : g_xhi4) + (size_t)(n0 + lr) * 96;
    const u32 arow_sw[4] = {
        (u32)(lr * 128 + (((half * 4 + 0) ^ (lr & 7)) << 4)),
        (u32)(lr * 128 + (((half * 4 + 1) ^ (lr & 7)) << 4)),
        (u32)(lr * 128 + (((half * 4 + 2) ^ (lr & 7)) << 4)),
        (u32)(lr * 128 + (((half * 4 + 3) ^ (lr & 7)) << 4))
    };
    u32 wdst[4];
    const uint4* srcW[4];
#pragma unroll
    for (int j = 0; j < 4; j++) {
        int idx = t + j * 256;
        int mw = idx >> 9;              // 0 = Q weights, 1 = K weights
        int within = idx & 511;
        int row = within >> 3, rem = within & 7;
        int wh = rem >> 2, g = rem & 3;
        wdst[j] = (u32)(16384 + mw * 8192 + row * 128 + (((wh * 4 + g) ^ (row & 7)) << 4));
        srcW[j] = (wh ? g_wlo4 : g_whi4) + (size_t)mw * (EMBD * EMBD / 8)
                  + (size_t)(o0 + row) * 96 + g;
    }

    float accQ[2][4][4], accK[2][4][4];
#pragma unroll
    for (int i = 0; i < 2; i++)
#pragma unroll
        for (int j = 0; j < 4; j++)
#pragma unroll
            for (int c = 0; c < 4; c++) { accQ[i][j][c] = 0.f; accK[i][j][c] = 0.f; }

#pragma unroll
    for (int pc = 0; pc < 2; pc++) {
        const u32 st = smbase + pc * QK_STAGE;
        const int ko = pc * 4;
#pragma unroll
        for (int g = 0; g < 4; g++) CP_ASYNC16(st + arow_sw[g], srcA + ko + g);
#pragma unroll
        for (int j = 0; j < 4; j++) CP_ASYNC16(st + wdst[j], srcW[j] + ko);
        CP_COMMIT();
    }

#pragma unroll 1
    for (int kc = 0; kc < KCHUNKS; kc++) {
        if (kc == KCHUNKS - 1) { CP_WAIT0(); } else { CP_WAIT1(); }
        __syncthreads();
        if (kc + 2 < KCHUNKS) {
            int nc = kc + 2;
            const u32 st = smbase + (nc % 3) * QK_STAGE;
            const int ko = nc * 4;
#pragma unroll
            for (int g = 0; g < 4; g++) CP_ASYNC16(st + arow_sw[g], srcA + ko + g);
#pragma unroll
            for (int j = 0; j < 4; j++) CP_ASYNC16(st + wdst[j], srcW[j] + ko);
            CP_COMMIT();
        }

        const u32 Ab  = smbase + (kc % 3) * QK_STAGE;
        const u32 WqB = Ab + 16384;
        const u32 WkB = Ab + 16384 + 8192;

#pragma unroll
        for (int ks = 0; ks < 2; ks++) {
            u32 ah[2][4], al[2][4];
#pragma unroll
            for (int mt = 0; mt < 2; mt++) {
                int row = warpM * 32 + mt * 16 + (lane & 15);
                int c = ks * 2 + ((lane >> 4) & 1);
                u32 base = Ab + row * 128;
                LDSM4(ah[mt][0], ah[mt][1], ah[mt][2], ah[mt][3],
                      base + (((c) ^ (row & 7)) << 4));
                LDSM4(al[mt][0], al[mt][1], al[mt][2], al[mt][3],
                      base + (((c + 4) ^ (row & 7)) << 4));
            }
            // ---- Q: 2-term ----
            {
                u32 bh[4][2], bl[4][2];
#pragma unroll
                for (int bt = 0; bt < 2; bt++) {
                    int row = warpN * 32 + bt * 16 + (lane & 7) + ((lane >> 4) & 1) * 8;
                    int c = ks * 2 + ((lane >> 3) & 1);
                    u32 base = WqB + row * 128;
                    u32 r0, r1, r2, r3;
                    LDSM4(r0, r1, r2, r3, base + (((c) ^ (row & 7)) << 4));
                    bh[bt * 2][0] = r0; bh[bt * 2][1] = r1;
                    bh[bt * 2 + 1][0] = r2; bh[bt * 2 + 1][1] = r3;
                    LDSM4(r0, r1, r2, r3, base + (((c + 4) ^ (row & 7)) << 4));
                    bl[bt * 2][0] = r0; bl[bt * 2][1] = r1;
                    bl[bt * 2 + 1][0] = r2; bl[bt * 2 + 1][1] = r3;
                }
#pragma unroll
                for (int mt = 0; mt < 2; mt++)
#pragma unroll
                    for (int nt = 0; nt < 4; nt++) {
                        MMA16816(accQ[mt][nt], ah[mt], bh[nt]);
                        MMA16816(accQ[mt][nt], ah[mt], bl[nt]);
                    }
            }
            // ---- K: 3-term ----
            {
                u32 bh[4][2], bl[4][2];
#pragma unroll
                for (int bt = 0; bt < 2; bt++) {
                    int row = warpN * 32 + bt * 16 + (lane & 7) + ((lane >> 4) & 1) * 8;
                    int c = ks * 2 + ((lane >> 3) & 1);
                    u32 base = WkB + row * 128;
                    u32 r0, r1, r2, r3;
                    LDSM4(r0, r1, r2, r3, base + (((c) ^ (row & 7)) << 4));
                    bh[bt * 2][0] = r0; bh[bt * 2][1] = r1;
                    bh[bt * 2 + 1][0] = r2; bh[bt * 2 + 1][1] = r3;
                    LDSM4(r0, r1, r2, r3, base + (((c + 4) ^ (row & 7)) << 4));
                    bl[bt * 2][0] = r0; bl[bt * 2][1] = r1;
                    bl[bt * 2 + 1][0] = r2; bl[bt * 2 + 1][1] = r3;
                }
#pragma unroll
                for (int mt = 0; mt < 2; mt++)
#pragma unroll
                    for (int nt = 0; nt < 4; nt++) {
                        MMA16816(accK[mt][nt], ah[mt], bh[nt]);
                        MMA16816(accK[mt][nt], ah[mt], bl[nt]);
                        MMA16816(accK[mt][nt], al[mt], bh[nt]);
                    }
            }
        }
    }

    const int h = blockIdx.x;
    u32* qh_d = (u32*)g_qh4;
    u32* kh_d = (u32*)g_kh4; u32* kl_d = (u32*)g_kl4;
#pragma unroll
    for (int mt = 0; mt < 2; mt++)
#pragma unroll
        for (int nt = 0; nt < 4; nt++)
#pragma unroll
            for (int cc = 0; cc < 2; cc++) {
                int rl = warpM * 32 + mt * 16 + (lane >> 2) + cc * 8;
                int cl = warpN * 32 + nt * 8 + (lane & 3) * 2;
                int n = n0 + rl;
                int bb = n / SEQ, ss = n - bb * SEQ;
                size_t idx = ((((size_t)bb * NH + h) * SEQ + ss) * HD + cl);
                {
                    float v0 = accQ[mt][nt][cc * 2 + 0] + bias_s[cl];
                    float v1 = accQ[mt][nt][cc * 2 + 1] + bias_s[cl + 1];
                    qh_d[idx >> 1] = pack_hi(v0, v1);   // Q hi only
                }
                {
                    float v0 = accK[mt][nt][cc * 2 + 0] + bias_s[64 + cl];
                    float v1 = accK[mt][nt][cc * 2 + 1] + bias_s[64 + cl + 1];
                    u32 hp, lp; pack_hilo(v0, v1, hp, lp);
                    kh_d[idx >> 1] = hp; kl_d[idx >> 1] = lp;
                }
            }
}

// =====================================================================
// HMMA hi-only GEMM (V and O modes), CTA tile 128x64, 4-stage, 1-term.
// mode 2 (V): A=Xhi, scatter V hi. mode 3 (O): A=ctx hi, fp32 out.
// =====================================================================
#define STAGE_BYTES 24576            // A 16K (hi half used) + W 8K (hi half used)
#define MM_SMEM (4 * STAGE_BYTES + 512)

__global__ __launch_bounds__(256, 2) void mm_hmma_kernel(
    const float* __restrict__ vb, const float* __restrict__ ob,
    float* __restrict__ outp, int mode)
{
    extern __shared__ char smraw[];
    const u32 smbase = smem_u32(smraw);
    float* bias_s = (float*)(smraw + 4 * STAGE_BYTES);

    const int t = threadIdx.x, lane = t & 31, wid = t >> 5;
    const int warpM = wid & 3;
    const int warpN = wid >> 2;
    const int o0 = blockIdx.x * 64;
    const int n0 = blockIdx.y * 128;

    const float* bias = mode == 2 ? vb : ob;
    const uint4* AhiG = (mode == 2) ? g_xhi4 : g_chi4;
    const size_t woff = (size_t)(mode == 2 ? 2 : 3) * (EMBD * EMBD / 8);

    if (t < 64) bias_s[t] = bias[o0 + t];

    // A loader: 128 rows x 4 hi chunks = 512 uint4, 2 per thread
    u32 adst[2];
    const uint4* srcA[2];
#pragma unroll
    for (int j = 0; j < 2; j++) {
        int idx = t + j * 256;
        int row = idx >> 2, g = idx & 3;
        adst[j] = (u32)(row * 128 + ((g ^ (row & 7)) << 4));
        srcA[j] = AhiG + (size_t)(n0 + row) * 96 + g;
    }
    // W loader: 64 rows x 4 hi chunks = 256 uint4, 1 per thread
    const int wrow = t >> 2, wg = t & 3;
    const u32 wdst = (u32)(wrow * 128 + ((wg ^ (wrow & 7)) << 4));
    const uint4* srcW = g_whi4 + woff + (size_t)(o0 + wrow) * 96 + wg;

    float acc[2][4][4];
#pragma unroll
    for (int i = 0; i < 2; i++)
#pragma unroll
        for (int j = 0; j < 4; j++)
#pragma unroll
            for (int c = 0; c < 4; c++) acc[i][j][c] = 0.f;

    // prefetch chunks 0..2
#pragma unroll
    for (int pc = 0; pc < 3; pc++) {
        const u32 st = smbase + pc * STAGE_BYTES;
        const int ko = pc * 4;
#pragma unroll
        for (int j = 0; j < 2; j++) CP_ASYNC16(st + adst[j], srcA[j] + ko);
        CP_ASYNC16(st + 16384 + wdst, srcW + ko);
        CP_COMMIT();
    }

#pragma unroll 1
    for (int kc = 0; kc < KCHUNKS; kc++) {
        int rem = KCHUNKS - 1 - kc;
        if (rem >= 2)      { CP_WAIT2(); }
        else if (rem == 1) { CP_WAIT1(); }
        else               { CP_WAIT0(); }
        __syncthreads();
        if (kc + 3 < KCHUNKS) {
            int nc = kc + 3;
            const u32 st = smbase + (nc & 3) * STAGE_BYTES;
            const int ko = nc * 4;
#pragma unroll
            for (int j = 0; j < 2; j++) CP_ASYNC16(st + adst[j], srcA[j] + ko);
            CP_ASYNC16(st + 16384 + wdst, srcW + ko);
            CP_COMMIT();
        }

        const u32 Ab = smbase + (kc & 3) * STAGE_BYTES;
        const u32 Wb = Ab + 16384;

#pragma unroll
        for (int ks = 0; ks < 2; ks++) {
            u32 ah[2][4];
#pragma unroll
            for (int mt = 0; mt < 2; mt++) {
                int row = warpM * 32 + mt * 16 + (lane & 15);
                int c = ks * 2 + ((lane >> 4) & 1);
                u32 base = Ab + row * 128;
                LDSM4(ah[mt][0], ah[mt][1], ah[mt][2], ah[mt][3],
                      base + (((c) ^ (row & 7)) << 4));
            }
            u32 bh[4][2];
#pragma unroll
            for (int bt = 0; bt < 2; bt++) {
                int row = warpN * 32 + bt * 16 + (lane & 7) + ((lane >> 4) & 1) * 8;
                int c = ks * 2 + ((lane >> 3) & 1);
                u32 base = Wb + row * 128;
                u32 r0, r1, r2, r3;
                LDSM4(r0, r1, r2, r3, base + (((c) ^ (row & 7)) << 4));
                bh[bt * 2][0] = r0; bh[bt * 2][1] = r1;
                bh[bt * 2 + 1][0] = r2; bh[bt * 2 + 1][1] = r3;
            }
#pragma unroll
            for (int mt = 0; mt < 2; mt++)
#pragma unroll
                for (int nt = 0; nt < 4; nt++)
                    MMA16816(acc[mt][nt], ah[mt], bh[nt]);
        }
    }

    u32* dsth = (u32*)g_vh4;
    const int h = blockIdx.x;
#pragma unroll
    for (int mt = 0; mt < 2; mt++)
#pragma unroll
        for (int nt = 0; nt < 4; nt++)
#pragma unroll
            for (int cc = 0; cc < 2; cc++) {
                int rl = warpM * 32 + mt * 16 + (lane >> 2) + cc * 8;
                int cl = warpN * 32 + nt * 8 + (lane & 3) * 2;
                float v0 = acc[mt][nt][cc * 2 + 0] + bias_s[cl];
                float v1 = acc[mt][nt][cc * 2 + 1] + bias_s[cl + 1];
                int n = n0 + rl;
                if (mode == 2) {
                    int bb = n / SEQ, ss = n - bb * SEQ;
                    size_t idx = ((((size_t)bb * NH + h) * SEQ + ss) * HD + cl);
                    dsth[idx >> 1] = pack_hi(v0, v1);
                } else {
                    float2* p = (float2*)(outp + (size_t)n * EMBD + o0 + cl);
                    *p = make_float2(v0, v1);
                }
            }
}

// =====================================================================
// HMMA attention, 32-row q tiles, 2 CTAs/SM.
// Q hi-only (2-term scores). PV pipelined, PH double-buffered.
// =====================================================================
#define SLAB_W 578
#define SC_B   0
#define ST0_B  (32 * SLAB_W * 4)           // 73,984
#define ST1_B  (ST0_B + 16384)             // 90,368
#define PH_B   (ST1_B + 16384)             // 106,752 (2 x 4096)
#define INV_B  (PH_B + 8192)               // 114,944
#define MAXP_B (INV_B + 128)               // 115,072
#define ATTN_SMEM (MAXP_B + 512)           // 115,584

__device__ __forceinline__ void load_tile64_async(
    u32 dsth, u32 dstl,
    const uint4* __restrict__ srch, const uint4* __restrict__ srcl,
    int tokbase, int t)
{
#pragma unroll
    for (int it = 0; it < 2; it++) {
        int idx = t + it * 256;
        int r = idx >> 3, c = idx & 7;
        u32 off = (u32)(r * 128 + ((c ^ (r & 7)) << 4));
        CP_ASYNC16(dsth + off, srch + (size_t)(tokbase + r) * 8 + c);
        CP_ASYNC16(dstl + off, srcl + (size_t)(tokbase + r) * 8 + c);
    }
    CP_COMMIT();
}

__device__ __forceinline__ void load_v_async(
    u32 dsth, const uint4* __restrict__ srch, int tokbase, int t)
{
#pragma unroll
    for (int it = 0; it < 2; it++) {
        int idx = t + it * 256;
        int r = idx >> 3, c = idx & 7;
        u32 off = (u32)(r * 128 + ((c ^ (r & 7)) << 4));
        CP_ASYNC16(dsth + off, srch + (size_t)(tokbase + r) * 8 + c);
    }
    CP_COMMIT();
}

__global__ __launch_bounds__(256, 2) void attn_kernel(float* __restrict__ attn_out)
{
    extern __shared__ char smc[];
    const u32 smb = smem_u32(smc);
    float* sc = (float*)smc;
    float* inv_s = (float*)(smc + INV_B);
    float* maxp  = (float*)(smc + MAXP_B);

    const int t = threadIdx.x, lane = t & 31, wid = t >> 5;
    const int warpM = wid & 1;
    const int warpN = wid >> 1;
    const int qt = blockIdx.x;
    const int bh = blockIdx.y;
    const int qtok = bh * SEQ + qt * 32;
    const int ktok0 = bh * SEQ;

    // load Q tile (hi only, 32 x 64) into stage0 area
    {
        int r = t >> 3, c = t & 7;
        if (r < 32) {
            uint4 a = g_qh4[(size_t)(qtok + r) * 8 + c];
            u32 off = (u32)(r * 128 + ((c ^ (r & 7)) << 4));
            STS128(smb + ST0_B + off, a.x, a.y, a.z, a.w);
        }
    }
    __syncthreads();

    u32 qh[4][4];
#pragma unroll
    for (int ks = 0; ks < 4; ks++) {
        int row = warpM * 16 + (lane & 15);
        int c = ks * 2 + ((lane >> 4) & 1);
        u32 sw = (u32)(row * 128 + ((c ^ (row & 7)) << 4));
        LDSM4(qh[ks][0], qh[ks][1], qh[ks][2], qh[ks][3], smb + ST0_B + sw);
    }

    load_tile64_async(smb + ST1_B, smb + ST1_B + 8192, g_kh4, g_kl4, ktok0, t);

    float fm[2] = {-1e30f, -1e30f};

    // ================= scores (2-term: Qh·Kh + Qh·Kl) =================
#pragma unroll 1
    for (int kt = 0; kt < 9; kt++) {
        CP_WAIT0();
        __syncthreads();
        if (kt < 9 - 1) {
            u32 nb = smb + (((kt + 1 + 1) & 1) ? ST1_B : ST0_B);
            load_tile64_async(nb, nb + 8192, g_kh4, g_kl4, ktok0 + (kt + 1) * 64, t);
        }
        const u32 kb = smb + (((kt + 1) & 1) ? ST1_B : ST0_B);
        const u32 klb = kb + 8192;

        float acc[2][4];
#pragma unroll
        for (int i = 0; i < 2; i++)
#pragma unroll
            for (int j = 0; j < 4; j++) acc[i][j] = 0.f;

#pragma unroll
        for (int ks = 0; ks < 4; ks++) {
            u32 bh2[2][2], bl2[2][2];
            {
                int row = warpN * 16 + (lane & 7) + ((lane >> 4) & 1) * 8;
                int c = ks * 2 + ((lane >> 3) & 1);
                u32 sw = (u32)(row * 128 + ((c ^ (row & 7)) << 4));
                u32 r0, r1, r2, r3;
                LDSM4(r0, r1, r2, r3, kb + sw);
                bh2[0][0] = r0; bh2[0][1] = r1;
                bh2[1][0] = r2; bh2[1][1] = r3;
                LDSM4(r0, r1, r2, r3, klb + sw);
                bl2[0][0] = r0; bl2[0][1] = r1;
                bl2[1][0] = r2; bl2[1][1] = r3;
            }
#pragma unroll
            for (int nt = 0; nt < 2; nt++) {
                MMA16816(acc[nt], qh[ks], bh2[nt]);
                MMA16816(acc[nt], qh[ks], bl2[nt]);
            }
        }
#pragma unroll
        for (int nt = 0; nt < 2; nt++)
#pragma unroll
            for (int cc = 0; cc < 2; cc++) {
                fm[cc] = fmaxf(fm[cc], fmaxf(acc[nt][cc * 2], acc[nt][cc * 2 + 1]));
                int r = warpM * 16 + (lane >> 2) + cc * 8;
                int col = kt * 64 + warpN * 16 + nt * 8 + (lane & 3) * 2;
                float2* p = (float2*)(sc + r * SLAB_W + col);
                *p = make_float2(acc[nt][cc * 2] * ATT_SCALE,
                                 acc[nt][cc * 2 + 1] * ATT_SCALE);
            }
    }
#pragma unroll
    for (int cc = 0; cc < 2; cc++) {
        fm[cc] = fmaxf(fm[cc], __shfl_xor_sync(0xffffffffu, fm[cc], 1));
        fm[cc] = fmaxf(fm[cc], __shfl_xor_sync(0xffffffffu, fm[cc], 2));
        if ((lane & 3) == 0) {
            int r = warpM * 16 + (lane >> 2) + cc * 8;
            maxp[warpN * 32 + r] = fm[cc];
        }
    }
    __syncthreads();

    // preload V tile 0 (hi only) into stage0 — overlaps softmax
    load_v_async(smb + ST0_B, g_vh4, ktok0, t);

    // ================= softmax: single pass =================
    {
        for (int rr = 0; rr < 4; rr++) {
            int r = wid * 4 + rr;
            float m = fmaxf(fmaxf(maxp[r], maxp[32 + r]),
                            fmaxf(maxp[64 + r], maxp[96 + r])) * ATT_SCALE;
            float* row = sc + r * SLAB_W;
            float s = 0.f;
            for (int c = lane; c < SEQ; c += 32) {
                float e = __expf(row[c] - m);
                row[c] = e;
                s += e;
            }
#pragma unroll
            for (int off = 16; off > 0; off >>= 1)
                s += __shfl_xor_sync(0xffffffffu, s, off);
            if (lane == 0) inv_s[r] = 1.f / s;
        }
    }

    // pre-pack P chunk 0 into PH buffer 0
#pragma unroll
    for (int i = 0; i < 4; i++) {
        int r = wid * 4 + i;
        float inv = inv_s[r];
        float2 e = *(const float2*)(sc + r * SLAB_W + lane * 2);
        float p0 = e.x * inv, p1 = e.y * inv;
        size_t arow = ((size_t)bh * SEQ + (size_t)(qt * 32 + r)) * SEQ;
        *(float2*)(attn_out + arow + lane * 2) = make_float2(p0, p1);
        u32 off = (u32)(r * 128 + (((lane >> 2) ^ (r & 7)) << 4) + (lane & 3) * 4);
        *(u32*)(smc + PH_B + off) = pack_hi(p0, p1);
    }

    // ================= P @ V (pipelined) ====
    float acc2[2][4];
#pragma unroll
    for (int i = 0; i < 2; i++)
#pragma unroll
        for (int j = 0; j < 4; j++) acc2[i][j] = 0.f;

#pragma unroll 1
    for (int kt = 0; kt < 9; kt++) {
        CP_WAIT0();
        __syncthreads();
        if (kt < 9 - 1) {
            u32 nb = smb + (((kt + 1) & 1) ? ST1_B : ST0_B);
            load_v_async(nb, g_vh4, ktok0 + (kt + 1) * 64, t);
#pragma unroll
            for (int i = 0; i < 4; i++) {
                int r = wid * 4 + i;
                float inv = inv_s[r];
                float2 e = *(const float2*)(sc + r * SLAB_W + (kt + 1) * 64 + lane * 2);
                float p0 = e.x * inv, p1 = e.y * inv;
                size_t arow = ((size_t)bh * SEQ + (size_t)(qt * 32 + r)) * SEQ;
                *(float2*)(attn_out + arow + (kt + 1) * 64 + lane * 2) =
                    make_float2(p0, p1);
                u32 off = (u32)(r * 128 + (((lane >> 2) ^ (r & 7)) << 4) + (lane & 3) * 4);
                *(u32*)(smc + PH_B + ((kt + 1) & 1) * 4096 + off) = pack_hi(p0, p1);
            }
        }

        const u32 phb = smb + PH_B + (kt & 1) * 4096;
        const u32 vb2 = smb + ((kt & 1) ? ST1_B : ST0_B);

#pragma unroll
        for (int ks = 0; ks < 4; ks++) {
            u32 ph[4];
            {
                int row = warpM * 16 + (lane & 15);
                int c = ks * 2 + ((lane >> 4) & 1);
                u32 sw = (u32)(row * 128 + ((c ^ (row & 7)) << 4));
                LDSM4(ph[0], ph[1], ph[2], ph[3], phb + sw);
            }
            u32 vh[2][2];
            {
                int m = lane >> 3;
                int row_s = ks * 16 + ((m & 1) << 3) + (lane & 7);
                int chunk = warpN * 2 + (m >> 1);
                u32 sw = (u32)(row_s * 128 + ((chunk ^ (row_s & 7)) << 4));
                u32 r0, r1, r2, r3;
                LDSM4T(r0, r1, r2, r3, vb2 + sw);
                vh[0][0] = r0; vh[0][1] = r1;
                vh[1][0] = r2; vh[1][1] = r3;
            }
#pragma unroll
            for (int nt = 0; nt < 2; nt++) {
                MMA16816(acc2[nt], ph, vh[nt]);
            }
        }
    }

    // ================= ctx epilogue (fp16 hi only) =================
    const int bb = bh / NH, h = bh % NH;
    u32* ch = (u32*)g_chi4;
#pragma unroll
    for (int nt = 0; nt < 2; nt++)
#pragma unroll
        for (int cc = 0; cc < 2; cc++) {
            int r = warpM * 16 + (lane >> 2) + cc * 8;
            int d = warpN * 16 + nt * 8 + (lane & 3) * 2;
            size_t n = (size_t)bb * SEQ + (size_t)(qt * 32 + r);
            size_t idx = n * EMBD + h * 64 + d;
            ch[idx >> 1] = pack_hi(acc2[nt][cc * 2], acc2[nt][cc * 2 + 1]);
        }
}

// =====================================================================
// launch
// =====================================================================
extern "C" void kernel_launch(void* const* d_in, const int* in_sizes, int n_in,
                              void* d_out, int out_size)
{
    const float* hs = (const float*)d_in[0];
    const float* qw = (const float*)d_in[1];
    const float* qb = (const float*)d_in[2];
    const float* kw = (const float*)d_in[3];
    const float* kb = (const float*)d_in[4];
    const float* vw = (const float*)d_in[5];
    const float* vb = (const float*)d_in[6];
    const float* ow = (const float*)d_in[7];
    const float* ob = (const float*)d_in[8];

    float* out  = (float*)d_out;
    float* attn = out + OUT_ELEMS;

    cudaFuncSetAttribute(qk_fused_kernel, cudaFuncAttributeMaxDynamicSharedMemorySize,
                         QK_SMEM);
    cudaFuncSetAttribute(mm_hmma_kernel, cudaFuncAttributeMaxDynamicSharedMemorySize,
                         MM_SMEM);
    cudaFuncSetAttribute(attn_kernel, cudaFuncAttributeMaxDynamicSharedMemorySize,
                         ATTN_SMEM);

    conv_x_kernel<<<(NT * EMBD / 8 + 255) / 256, 256>>>(hs);
    conv_w_kernel<<<dim3((EMBD * EMBD / 8 + 255) / 256, 4), 256>>>(qw, kw, vw, ow);

    qk_fused_kernel<<<dim3(EMBD / 64, NT / 128), 256, QK_SMEM>>>(qb, kb);
    mm_hmma_kernel<<<dim3(EMBD / 64, NT / 128), 256, MM_SMEM>>>(vb, ob, out, 2);

    attn_kernel<<<dim3(18, BATCH * NH), 256, ATTN_SMEM>>>(attn);

    mm_hmma_kernel<<<dim3(EMBD / 64, NT / 128), 256, MM_SMEM>>>(vb, ob, out, 3);
}

// round 17
// speedup vs baseline: 4.7810x; 1.2609x over previous
#include <cuda_runtime.h>
#include <cuda_fp16.h>

// ---------------- problem constants ----------------
#define BATCH 32
#define SEQ   576
#define EMBD  768
#define NH    12
#define HD    64
#define NT    (BATCH * SEQ)
#define OUT_ELEMS ((size_t)NT * EMBD)
#define ATT_SCALE 0.125f
#define KCHUNKS 24

typedef unsigned int u32;
typedef unsigned short u16;

// ---------------- device scratch ----------------
__device__ uint4 g_xhi4[NT * EMBD / 8];          // X hi only
__device__ uint4 g_whi4[4 * EMBD * EMBD / 8];
__device__ uint4 g_wlo4[2 * EMBD * EMBD / 8];    // lo only for Q,K weights
__device__ uint4 g_chi4[NT * EMBD / 8];          // ctx hi only ([N, EMB], fp16)
__device__ uint4 g_qh4[NT * EMBD / 8];           // Q hi only [B,H,S,D]
__device__ uint4 g_kh4[NT * EMBD / 8];           // K hi only
__device__ uint4 g_vh4[NT * EMBD / 8];           // V hi only

// ---------------- helpers ----------------
__device__ __forceinline__ u32 smem_u32(const void* p) {
    u32 a;
    asm("{ .reg .u64 t; cvta.to.shared.u64 t, %1; cvt.u32.u64 %0, t; }"
        : "=r"(a) : "l"(p));
    return a;
}

#define CP_ASYNC16(dst, src) \
    asm volatile("cp.async.cg.shared.global [%0], [%1], 16;" \
                 :: "r"(dst), "l"(src) : "memory")
#define CP_COMMIT() asm volatile("cp.async.commit_group;" ::: "memory")
#define CP_WAIT2()  asm volatile("cp.async.wait_group 2;" ::: "memory")
#define CP_WAIT1()  asm volatile("cp.async.wait_group 1;" ::: "memory")
#define CP_WAIT0()  asm volatile("cp.async.wait_group 0;" ::: "memory")

#define LDSM4(r0, r1, r2, r3, addr) \
    asm volatile("ldmatrix.sync.aligned.m8n8.x4.shared.b16 {%0,%1,%2,%3}, [%4];" \
                 : "=r"(r0), "=r"(r1), "=r"(r2), "=r"(r3) : "r"(addr))
#define LDSM4T(r0, r1, r2, r3, addr) \
    asm volatile("ldmatrix.sync.aligned.m8n8.x4.trans.shared.b16 {%0,%1,%2,%3}, [%4];" \
                 : "=r"(r0), "=r"(r1), "=r"(r2), "=r"(r3) : "r"(addr))

#define MMA16816(d, a, b) \
    asm volatile("mma.sync.aligned.m16n8k16.row.col.f32.f16.f16.f32 " \
                 "{%0,%1,%2,%3}, {%4,%5,%6,%7}, {%8,%9}, {%0,%1,%2,%3};" \
                 : "+f"((d)[0]), "+f"((d)[1]), "+f"((d)[2]), "+f"((d)[3]) \
                 : "r"((a)[0]), "r"((a)[1]), "r"((a)[2]), "r"((a)[3]), \
                   "r"((b)[0]), "r"((b)[1]))

#define STS128(addr, a, b, c, d) \
    asm volatile("st.shared.v4.b32 [%0], {%1, %2, %3, %4};" \
                 :: "r"(addr), "r"(a), "r"(b), "r"(c), "r"(d) : "memory")

__device__ __forceinline__ u32 pack_hi(float v0, float v1) {
    __half h0 = __float2half_rn(v0);
    __half h1 = __float2half_rn(v1);
    return (u32)*(u16*)&h0 | ((u32)*(u16*)&h1 << 16);
}

// =====================================================================
// fp16 conversion kernels
// =====================================================================
__device__ __forceinline__ void conv8(const float4* src2, uint4* hi, uint4* lo) {
    float4 a = src2[0], b = src2[1];
    float f[8] = {a.x, a.y, a.z, a.w, b.x, b.y, b.z, b.w};
    union { uint4 v; __half h[8]; } H, L;
#pragma unroll
    for (int j = 0; j < 8; j++) {
        __half hh = __float2half_rn(f[j]);
        H.h[j] = hh;
        L.h[j] = __float2half_rn(f[j] - __half2float(hh));
    }
    *hi = H.v; *lo = L.v;
}
__device__ __forceinline__ void conv8_hi(const float4* src2, uint4* hi) {
    float4 a = src2[0], b = src2[1];
    float f[8] = {a.x, a.y, a.z, a.w, b.x, b.y, b.z, b.w};
    union { uint4 v; __half h[8]; } H;
#pragma unroll
    for (int j = 0; j < 8; j++) H.h[j] = __float2half_rn(f[j]);
    *hi = H.v;
}

__global__ __launch_bounds__(256) void conv_x_kernel(const float* __restrict__ src) {
    int i = blockIdx.x * blockDim.x + threadIdx.x;
    if (i >= NT * EMBD / 8) return;
    conv8_hi((const float4*)src + 2 * (size_t)i, &g_xhi4[i]);
}

__global__ __launch_bounds__(256) void conv_w_kernel(
    const float* __restrict__ qw, const float* __restrict__ kw,
    const float* __restrict__ vw, const float* __restrict__ ow) {
    int z = blockIdx.y;
    const float* src = z == 0 ? qw : z == 1 ? kw : z == 2 ? vw : ow;
    int i = blockIdx.x * blockDim.x + threadIdx.x;
    if (i >= EMBD * EMBD / 8) return;
    int di = z * (EMBD * EMBD / 8) + i;
    if (z < 2)
        conv8((const float4*)src + 2 * (size_t)i, &g_whi4[di], &g_wlo4[di]);
    else
        conv8_hi((const float4*)src + 2 * (size_t)i, &g_whi4[di]);
}

// =====================================================================
// Fused Q+K projection, 3-stage pipeline.
// Both 2-term: Xhi·Whi + Xhi·Wlo. Both stored hi-only.
// Stage layout: A 16K (128 rows x 128B swizzle domain) | Wq 8K | Wk 8K.
// =====================================================================
#define QK_STAGE 32768
#define QK_SMEM (3 * QK_STAGE + 1024)

__global__ __launch_bounds__(256, 2) void qk_fused_kernel(
    const float* __restrict__ qb, const float* __restrict__ kb)
{
    extern __shared__ char smraw[];
    const u32 smbase = smem_u32(smraw);
    float* bias_s = (float*)(smraw + 3 * QK_STAGE);   // [2][64]

    const int t = threadIdx.x, lane = t & 31, wid = t >> 5;
    const int warpM = wid & 3;
    const int warpN = wid >> 2;
    const int o0 = blockIdx.x * 64;
    const int n0 = blockIdx.y * 128;

    if (t < 64) bias_s[t] = qb[o0 + t];
    else if (t < 128) bias_s[t] = kb[o0 + t - 64];

    // A loader: 128 rows x 4 hi chunks per k-chunk = 512 uint4, 2 per thread
    // (row stride 128B — swizzle spans the full row)
    u32 adst[2];
    const uint4* srcA[2];
#pragma unroll
    for (int j = 0; j < 2; j++) {
        int idx = t + j * 256;
        int row = idx >> 2, g = idx & 3;
        adst[j] = (u32)(row * 128 + ((g ^ (row & 7)) << 4));
        srcA[j] = g_xhi4 + (size_t)(n0 + row) * 96 + g;
    }
    // W loader: 2 matrices x 64 rows x (hi|lo) x 4 chunks = 1024 uint4, 4/thread
    u32 wdst[4];
    const uint4* srcW[4];
#pragma unroll
    for (int j = 0; j < 4; j++) {
        int idx = t + j * 256;
        int mw = idx >> 9;              // 0 = Q weights, 1 = K weights
        int within = idx & 511;
        int row = within >> 3, rem = within & 7;
        int wh = rem >> 2, g = rem & 3;
        wdst[j] = (u32)(16384 + mw * 8192 + row * 128 + (((wh * 4 + g) ^ (row & 7)) << 4));
        srcW[j] = (wh ? g_wlo4 : g_whi4) + (size_t)mw * (EMBD * EMBD / 8)
                  + (size_t)(o0 + row) * 96 + g;
    }

    float accQ[2][4][4], accK[2][4][4];
#pragma unroll
    for (int i = 0; i < 2; i++)
#pragma unroll
        for (int j = 0; j < 4; j++)
#pragma unroll
            for (int c = 0; c < 4; c++) { accQ[i][j][c] = 0.f; accK[i][j][c] = 0.f; }

    // prefetch chunks 0 and 1
#pragma unroll
    for (int pc = 0; pc < 2; pc++) {
        const u32 st = smbase + pc * QK_STAGE;
        const int ko = pc * 4;
#pragma unroll
        for (int j = 0; j < 2; j++) CP_ASYNC16(st + adst[j], srcA[j] + ko);
#pragma unroll
        for (int j = 0; j < 4; j++) CP_ASYNC16(st + wdst[j], srcW[j] + ko);
        CP_COMMIT();
    }

#pragma unroll 1
    for (int kc = 0; kc < KCHUNKS; kc++) {
        if (kc == KCHUNKS - 1) { CP_WAIT0(); } else { CP_WAIT1(); }
        __syncthreads();
        if (kc + 2 < KCHUNKS) {
            int nc = kc + 2;
            const u32 st = smbase + (nc % 3) * QK_STAGE;
            const int ko = nc * 4;
#pragma unroll
            for (int j = 0; j < 2; j++) CP_ASYNC16(st + adst[j], srcA[j] + ko);
#pragma unroll
            for (int j = 0; j < 4; j++) CP_ASYNC16(st + wdst[j], srcW[j] + ko);
            CP_COMMIT();
        }

        const u32 Ab  = smbase + (kc % 3) * QK_STAGE;
        const u32 WqB = Ab + 16384;
        const u32 WkB = Ab + 24576;

#pragma unroll
        for (int ks = 0; ks < 2; ks++) {
            u32 ah[2][4];
#pragma unroll
            for (int mt = 0; mt < 2; mt++) {
                int row = warpM * 32 + mt * 16 + (lane & 15);
                int c = ks * 2 + ((lane >> 4) & 1);
                u32 base = Ab + row * 128;
                LDSM4(ah[mt][0], ah[mt][1], ah[mt][2], ah[mt][3],
                      base + (((c) ^ (row & 7)) << 4));
            }
            // ---- Q: 2-term ----
            {
                u32 bh[4][2], bl[4][2];
#pragma unroll
                for (int bt = 0; bt < 2; bt++) {
                    int row = warpN * 32 + bt * 16 + (lane & 7) + ((lane >> 4) & 1) * 8;
                    int c = ks * 2 + ((lane >> 3) & 1);
                    u32 base = WqB + row * 128;
                    u32 r0, r1, r2, r3;
                    LDSM4(r0, r1, r2, r3, base + (((c) ^ (row & 7)) << 4));
                    bh[bt * 2][0] = r0; bh[bt * 2][1] = r1;
                    bh[bt * 2 + 1][0] = r2; bh[bt * 2 + 1][1] = r3;
                    LDSM4(r0, r1, r2, r3, base + (((c + 4) ^ (row & 7)) << 4));
                    bl[bt * 2][0] = r0; bl[bt * 2][1] = r1;
                    bl[bt * 2 + 1][0] = r2; bl[bt * 2 + 1][1] = r3;
                }
#pragma unroll
                for (int mt = 0; mt < 2; mt++)
#pragma unroll
                    for (int nt = 0; nt < 4; nt++) {
                        MMA16816(accQ[mt][nt], ah[mt], bh[nt]);
                        MMA16816(accQ[mt][nt], ah[mt], bl[nt]);
                    }
            }
            // ---- K: 2-term ----
            {
                u32 bh[4][2], bl[4][2];
#pragma unroll
                for (int bt = 0; bt < 2; bt++) {
                    int row = warpN * 32 + bt * 16 + (lane & 7) + ((lane >> 4) & 1) * 8;
                    int c = ks * 2 + ((lane >> 3) & 1);
                    u32 base = WkB + row * 128;
                    u32 r0, r1, r2, r3;
                    LDSM4(r0, r1, r2, r3, base + (((c) ^ (row & 7)) << 4));
                    bh[bt * 2][0] = r0; bh[bt * 2][1] = r1;
                    bh[bt * 2 + 1][0] = r2; bh[bt * 2 + 1][1] = r3;
                    LDSM4(r0, r1, r2, r3, base + (((c + 4) ^ (row & 7)) << 4));
                    bl[bt * 2][0] = r0; bl[bt * 2][1] = r1;
                    bl[bt * 2 + 1][0] = r2; bl[bt * 2 + 1][1] = r3;
                }
#pragma unroll
                for (int mt = 0; mt < 2; mt++)
#pragma unroll
                    for (int nt = 0; nt < 4; nt++) {
                        MMA16816(accK[mt][nt], ah[mt], bh[nt]);
                        MMA16816(accK[mt][nt], ah[mt], bl[nt]);
                    }
            }
        }
    }

    const int h = blockIdx.x;
    u32* qh_d = (u32*)g_qh4;
    u32* kh_d = (u32*)g_kh4;
#pragma unroll
    for (int mt = 0; mt < 2; mt++)
#pragma unroll
        for (int nt = 0; nt < 4; nt++)
#pragma unroll
            for (int cc = 0; cc < 2; cc++) {
                int rl = warpM * 32 + mt * 16 + (lane >> 2) + cc * 8;
                int cl = warpN * 32 + nt * 8 + (lane & 3) * 2;
                int n = n0 + rl;
                int bb = n / SEQ, ss = n - bb * SEQ;
                size_t idx = ((((size_t)bb * NH + h) * SEQ + ss) * HD + cl);
                qh_d[idx >> 1] = pack_hi(accQ[mt][nt][cc * 2] + bias_s[cl],
                                         accQ[mt][nt][cc * 2 + 1] + bias_s[cl + 1]);
                kh_d[idx >> 1] = pack_hi(accK[mt][nt][cc * 2] + bias_s[64 + cl],
                                         accK[mt][nt][cc * 2 + 1] + bias_s[64 + cl + 1]);
            }
}

// =====================================================================
// HMMA hi-only GEMM (V and O modes), CTA tile 128x64, 4-stage, 1-term.
// =====================================================================
#define STAGE_BYTES 24576
#define MM_SMEM (4 * STAGE_BYTES + 512)

__global__ __launch_bounds__(256, 2) void mm_hmma_kernel(
    const float* __restrict__ vb, const float* __restrict__ ob,
    float* __restrict__ outp, int mode)
{
    extern __shared__ char smraw[];
    const u32 smbase = smem_u32(smraw);
    float* bias_s = (float*)(smraw + 4 * STAGE_BYTES);

    const int t = threadIdx.x, lane = t & 31, wid = t >> 5;
    const int warpM = wid & 3;
    const int warpN = wid >> 2;
    const int o0 = blockIdx.x * 64;
    const int n0 = blockIdx.y * 128;

    const float* bias = mode == 2 ? vb : ob;
    const uint4* AhiG = (mode == 2) ? g_xhi4 : g_chi4;
    const size_t woff = (size_t)(mode == 2 ? 2 : 3) * (EMBD * EMBD / 8);

    if (t < 64) bias_s[t] = bias[o0 + t];

    u32 adst[2];
    const uint4* srcA[2];
#pragma unroll
    for (int j = 0; j < 2; j++) {
        int idx = t + j * 256;
        int row = idx >> 2, g = idx & 3;
        adst[j] = (u32)(row * 128 + ((g ^ (row & 7)) << 4));
        srcA[j] = AhiG + (size_t)(n0 + row) * 96 + g;
    }
    const int wrow = t >> 2, wg = t & 3;
    const u32 wdst = (u32)(wrow * 128 + ((wg ^ (wrow & 7)) << 4));
    const uint4* srcW = g_whi4 + woff + (size_t)(o0 + wrow) * 96 + wg;

    float acc[2][4][4];
#pragma unroll
    for (int i = 0; i < 2; i++)
#pragma unroll
        for (int j = 0; j < 4; j++)
#pragma unroll
            for (int c = 0; c < 4; c++) acc[i][j][c] = 0.f;

#pragma unroll
    for (int pc = 0; pc < 3; pc++) {
        const u32 st = smbase + pc * STAGE_BYTES;
        const int ko = pc * 4;
#pragma unroll
        for (int j = 0; j < 2; j++) CP_ASYNC16(st + adst[j], srcA[j] + ko);
        CP_ASYNC16(st + 16384 + wdst, srcW + ko);
        CP_COMMIT();
    }

#pragma unroll 1
    for (int kc = 0; kc < KCHUNKS; kc++) {
        int rem = KCHUNKS - 1 - kc;
        if (rem >= 2)      { CP_WAIT2(); }
        else if (rem == 1) { CP_WAIT1(); }
        else               { CP_WAIT0(); }
        __syncthreads();
        if (kc + 3 < KCHUNKS) {
            int nc = kc + 3;
            const u32 st = smbase + (nc & 3) * STAGE_BYTES;
            const int ko = nc * 4;
#pragma unroll
            for (int j = 0; j < 2; j++) CP_ASYNC16(st + adst[j], srcA[j] + ko);
            CP_ASYNC16(st + 16384 + wdst, srcW + ko);
            CP_COMMIT();
        }

        const u32 Ab = smbase + (kc & 3) * STAGE_BYTES;
        const u32 Wb = Ab + 16384;

#pragma unroll
        for (int ks = 0; ks < 2; ks++) {
            u32 ah[2][4];
#pragma unroll
            for (int mt = 0; mt < 2; mt++) {
                int row = warpM * 32 + mt * 16 + (lane & 15);
                int c = ks * 2 + ((lane >> 4) & 1);
                u32 base = Ab + row * 128;
                LDSM4(ah[mt][0], ah[mt][1], ah[mt][2], ah[mt][3],
                      base + (((c) ^ (row & 7)) << 4));
            }
            u32 bh[4][2];
#pragma unroll
            for (int bt = 0; bt < 2; bt++) {
                int row = warpN * 32 + bt * 16 + (lane & 7) + ((lane >> 4) & 1) * 8;
                int c = ks * 2 + ((lane >> 3) & 1);
                u32 base = Wb + row * 128;
                u32 r0, r1, r2, r3;
                LDSM4(r0, r1, r2, r3, base + (((c) ^ (row & 7)) << 4));
                bh[bt * 2][0] = r0; bh[bt * 2][1] = r1;
                bh[bt * 2 + 1][0] = r2; bh[bt * 2 + 1][1] = r3;
            }
#pragma unroll
            for (int mt = 0; mt < 2; mt++)
#pragma unroll
                for (int nt = 0; nt < 4; nt++)
                    MMA16816(acc[mt][nt], ah[mt], bh[nt]);
        }
    }

    u32* dsth = (u32*)g_vh4;
    const int h = blockIdx.x;
#pragma unroll
    for (int mt = 0; mt < 2; mt++)
#pragma unroll
        for (int nt = 0; nt < 4; nt++)
#pragma unroll
            for (int cc = 0; cc < 2; cc++) {
                int rl = warpM * 32 + mt * 16 + (lane >> 2) + cc * 8;
                int cl = warpN * 32 + nt * 8 + (lane & 3) * 2;
                float v0 = acc[mt][nt][cc * 2 + 0] + bias_s[cl];
                float v1 = acc[mt][nt][cc * 2 + 1] + bias_s[cl + 1];
                int n = n0 + rl;
                if (mode == 2) {
                    int bb = n / SEQ, ss = n - bb * SEQ;
                    size_t idx = ((((size_t)bb * NH + h) * SEQ + ss) * HD + cl);
                    dsth[idx >> 1] = pack_hi(v0, v1);
                } else {
                    float2* p = (float2*)(outp + (size_t)n * EMBD + o0 + cl);
                    *p = make_float2(v0, v1);
                }
            }
}

// =====================================================================
// HMMA attention, 32-row q tiles, 2 CTAs/SM.
// Q, K, V all hi-only: scores 1-term, PV 1-term. Both phases pipelined.
// =====================================================================
#define SLAB_W 578
#define SC_B   0
#define ST0_B  (32 * SLAB_W * 4)           // 73,984
#define ST1_B  (ST0_B + 16384)             // 90,368
#define PH_B   (ST1_B + 16384)             // 106,752 (2 x 4096)
#define INV_B  (PH_B + 8192)               // 114,944
#define MAXP_B (INV_B + 128)               // 115,072
#define ATTN_SMEM (MAXP_B + 512)           // 115,584

__device__ __forceinline__ void load_hi_async(
    u32 dsth, const uint4* __restrict__ srch, int tokbase, int t)
{
#pragma unroll
    for (int it = 0; it < 2; it++) {
        int idx = t + it * 256;
        int r = idx >> 3, c = idx & 7;
        u32 off = (u32)(r * 128 + ((c ^ (r & 7)) << 4));
        CP_ASYNC16(dsth + off, srch + (size_t)(tokbase + r) * 8 + c);
    }
    CP_COMMIT();
}

__global__ __launch_bounds__(256, 2) void attn_kernel(float* __restrict__ attn_out)
{
    extern __shared__ char smc[];
    const u32 smb = smem_u32(smc);
    float* sc = (float*)smc;
    float* inv_s = (float*)(smc + INV_B);
    float* maxp  = (float*)(smc + MAXP_B);

    const int t = threadIdx.x, lane = t & 31, wid = t >> 5;
    const int warpM = wid & 1;
    const int warpN = wid >> 1;
    const int qt = blockIdx.x;
    const int bh = blockIdx.y;
    const int qtok = bh * SEQ + qt * 32;
    const int ktok0 = bh * SEQ;

    // load Q tile (hi only, 32 x 64) into stage0 area
    {
        int r = t >> 3, c = t & 7;
        if (r < 32) {
            uint4 a = g_qh4[(size_t)(qtok + r) * 8 + c];
            u32 off = (u32)(r * 128 + ((c ^ (r & 7)) << 4));
            STS128(smb + ST0_B + off, a.x, a.y, a.z, a.w);
        }
    }
    __syncthreads();

    u32 qh[4][4];
#pragma unroll
    for (int ks = 0; ks < 4; ks++) {
        int row = warpM * 16 + (lane & 15);
        int c = ks * 2 + ((lane >> 4) & 1);
        u32 sw = (u32)(row * 128 + ((c ^ (row & 7)) << 4));
        LDSM4(qh[ks][0], qh[ks][1], qh[ks][2], qh[ks][3], smb + ST0_B + sw);
    }

    // preload K tile 0 into stage1 (doesn't touch Q area)
    load_hi_async(smb + ST1_B, g_kh4, ktok0, t);

    float fm[2] = {-1e30f, -1e30f};

    // ================= scores (1-term: Qh·Kh) =================
#pragma unroll 1
    for (int kt = 0; kt < 9; kt++) {
        CP_WAIT0();
        __syncthreads();
        if (kt < 9 - 1) {
            u32 nb = smb + (((kt + 1 + 1) & 1) ? ST1_B : ST0_B);
            load_hi_async(nb, g_kh4, ktok0 + (kt + 1) * 64, t);
        }
        const u32 kb = smb + (((kt + 1) & 1) ? ST1_B : ST0_B);

        float acc[2][4];
#pragma unroll
        for (int i = 0; i < 2; i++)
#pragma unroll
            for (int j = 0; j < 4; j++) acc[i][j] = 0.f;

#pragma unroll
        for (int ks = 0; ks < 4; ks++) {
            u32 bh2[2][2];
            {
                int row = warpN * 16 + (lane & 7) + ((lane >> 4) & 1) * 8;
                int c = ks * 2 + ((lane >> 3) & 1);
                u32 sw = (u32)(row * 128 + ((c ^ (row & 7)) << 4));
                u32 r0, r1, r2, r3;
                LDSM4(r0, r1, r2, r3, kb + sw);
                bh2[0][0] = r0; bh2[0][1] = r1;
                bh2[1][0] = r2; bh2[1][1] = r3;
            }
#pragma unroll
            for (int nt = 0; nt < 2; nt++)
                MMA16816(acc[nt], qh[ks], bh2[nt]);
        }
#pragma unroll
        for (int nt = 0; nt < 2; nt++)
#pragma unroll
            for (int cc = 0; cc < 2; cc++) {
                fm[cc] = fmaxf(fm[cc], fmaxf(acc[nt][cc * 2], acc[nt][cc * 2 + 1]));
                int r = warpM * 16 + (lane >> 2) + cc * 8;
                int col = kt * 64 + warpN * 16 + nt * 8 + (lane & 3) * 2;
                float2* p = (float2*)(sc + r * SLAB_W + col);
                *p = make_float2(acc[nt][cc * 2] * ATT_SCALE,
                                 acc[nt][cc * 2 + 1] * ATT_SCALE);
            }
    }
#pragma unroll
    for (int cc = 0; cc < 2; cc++) {
        fm[cc] = fmaxf(fm[cc], __shfl_xor_sync(0xffffffffu, fm[cc], 1));
        fm[cc] = fmaxf(fm[cc], __shfl_xor_sync(0xffffffffu, fm[cc], 2));
        if ((lane & 3) == 0) {
            int r = warpM * 16 + (lane >> 2) + cc * 8;
            maxp[warpN * 32 + r] = fm[cc];
        }
    }
    __syncthreads();

    // preload V tile 0 into stage0 — overlaps softmax
    load_hi_async(smb + ST0_B, g_vh4, ktok0, t);

    // ================= softmax: single pass =================
    {
        for (int rr = 0; rr < 4; rr++) {
            int r = wid * 4 + rr;
            float m = fmaxf(fmaxf(maxp[r], maxp[32 + r]),
                            fmaxf(maxp[64 + r], maxp[96 + r])) * ATT_SCALE;
            float* row = sc + r * SLAB_W;
            float s = 0.f;
            for (int c = lane; c < SEQ; c += 32) {
                float e = __expf(row[c] - m);
                row[c] = e;
                s += e;
            }
#pragma unroll
            for (int off = 16; off > 0; off >>= 1)
                s += __shfl_xor_sync(0xffffffffu, s, off);
            if (lane == 0) inv_s[r] = 1.f / s;
        }
    }

    // pre-pack P chunk 0 into PH buffer 0
#pragma unroll
    for (int i = 0; i < 4; i++) {
        int r = wid * 4 + i;
        float inv = inv_s[r];
        float2 e = *(const float2*)(sc + r * SLAB_W + lane * 2);
        float p0 = e.x * inv, p1 = e.y * inv;
        size_t arow = ((size_t)bh * SEQ + (size_t)(qt * 32 + r)) * SEQ;
        *(float2*)(attn_out + arow + lane * 2) = make_float2(p0, p1);
        u32 off = (u32)(r * 128 + (((lane >> 2) ^ (r & 7)) << 4) + (lane & 3) * 4);
        *(u32*)(smc + PH_B + off) = pack_hi(p0, p1);
    }

    // ================= P @ V (pipelined) ====
    float acc2[2][4];
#pragma unroll
    for (int i = 0; i < 2; i++)
#pragma unroll
        for (int j = 0; j < 4; j++) acc2[i][j] = 0.f;

#pragma unroll 1
    for (int kt = 0; kt < 9; kt++) {
        CP_WAIT0();
        __syncthreads();
        if (kt < 9 - 1) {
            u32 nb = smb + (((kt + 1) & 1) ? ST1_B : ST0_B);
            load_hi_async(nb, g_vh4, ktok0 + (kt + 1) * 64, t);
#pragma unroll
            for (int i = 0; i < 4; i++) {
                int r = wid * 4 + i;
                float inv = inv_s[r];
                float2 e = *(const float2*)(sc + r * SLAB_W + (kt + 1) * 64 + lane * 2);
                float p0 = e.x * inv, p1 = e.y * inv;
                size_t arow = ((size_t)bh * SEQ + (size_t)(qt * 32 + r)) * SEQ;
                *(float2*)(attn_out + arow + (kt + 1) * 64 + lane * 2) =
                    make_float2(p0, p1);
                u32 off = (u32)(r * 128 + (((lane >> 2) ^ (r & 7)) << 4) + (lane & 3) * 4);
                *(u32*)(smc + PH_B + ((kt + 1) & 1) * 4096 + off) = pack_hi(p0, p1);
            }
        }

        const u32 phb = smb + PH_B + (kt & 1) * 4096;
        const u32 vb2 = smb + ((kt & 1) ? ST1_B : ST0_B);

#pragma unroll
        for (int ks = 0; ks < 4; ks++) {
            u32 ph[4];
            {
                int row = warpM * 16 + (lane & 15);
                int c = ks * 2 + ((lane >> 4) & 1);
                u32 sw = (u32)(row * 128 + ((c ^ (row & 7)) << 4));
                LDSM4(ph[0], ph[1], ph[2], ph[3], phb + sw);
            }
            u32 vh[2][2];
            {
                int m = lane >> 3;
                int row_s = ks * 16 + ((m & 1) << 3) + (lane & 7);
                int chunk = warpN * 2 + (m >> 1);
                u32 sw = (u32)(row_s * 128 + ((chunk ^ (row_s & 7)) << 4));
                u32 r0, r1, r2, r3;
                LDSM4T(r0, r1, r2, r3, vb2 + sw);
                vh[0][0] = r0; vh[0][1] = r1;
                vh[1][0] = r2; vh[1][1] = r3;
            }
#pragma unroll
            for (int nt = 0; nt < 2; nt++)
                MMA16816(acc2[nt], ph, vh[nt]);
        }
    }

    // ================= ctx epilogue (fp16 hi only) =================
    const int bb = bh / NH, h = bh % NH;
    u32* ch = (u32*)g_chi4;
#pragma unroll
    for (int nt = 0; nt < 2; nt++)
#pragma unroll
        for (int cc = 0; cc < 2; cc++) {
            int r = warpM * 16 + (lane >> 2) + cc * 8;
            int d = warpN * 16 + nt * 8 + (lane & 3) * 2;
            size_t n = (size_t)bb * SEQ + (size_t)(qt * 32 + r);
            size_t idx = n * EMBD + h * 64 + d;
            ch[idx >> 1] = pack_hi(acc2[nt][cc * 2], acc2[nt][cc * 2 + 1]);
        }
}

// =====================================================================
// launch
// =====================================================================
extern "C" void kernel_launch(void* const* d_in, const int* in_sizes, int n_in,
                              void* d_out, int out_size)
{
    const float* hs = (const float*)d_in[0];
    const float* qw = (const float*)d_in[1];
    const float* qb = (const float*)d_in[2];
    const float* kw = (const float*)d_in[3];
    const float* kb = (const float*)d_in[4];
    const float* vw = (const float*)d_in[5];
    const float* vb = (const float*)d_in[6];
    const float* ow = (const float*)d_in[7];
    const float* ob = (const float*)d_in[8];

    float* out  = (float*)d_out;
    float* attn = out + OUT_ELEMS;

    cudaFuncSetAttribute(qk_fused_kernel, cudaFuncAttributeMaxDynamicSharedMemorySize,
                         QK_SMEM);
    cudaFuncSetAttribute(mm_hmma_kernel, cudaFuncAttributeMaxDynamicSharedMemorySize,
                         MM_SMEM);
    cudaFuncSetAttribute(attn_kernel, cudaFuncAttributeMaxDynamicSharedMemorySize,
                         ATTN_SMEM);

    conv_x_kernel<<<(NT * EMBD / 8 + 255) / 256, 256>>>(hs);
    conv_w_kernel<<<dim3((EMBD * EMBD / 8 + 255) / 256, 4), 256>>>(qw, kw, vw, ow);

    qk_fused_kernel<<<dim3(EMBD / 64, NT / 128), 256, QK_SMEM>>>(qb, kb);
    mm_hmma_kernel<<<dim3(EMBD / 64, NT / 128), 256, MM_SMEM>>>(vb, ob, out, 2);

    attn_kernel<<<dim3(18, BATCH * NH), 256, ATTN_SMEM>>>(attn);

    mm_hmma_kernel<<<dim3(EMBD / 64, NT / 128), 256, MM_SMEM>>>(vb, ob, out, 3);
}